// round 1
// baseline (speedup 1.0000x reference)
#include <cuda_runtime.h>
#include <math.h>
#include <stdint.h>

// ---------------- problem constants ----------------
#define B_    2
#define L_    1024
#define TXT_  1024
#define HID_  2048
#define INT_  6144
#define NH_   16
#define NKV_  8
#define HD_   128
#define NL_   8
#define SW_   128
#define MT_   (B_*L_)          // 2048 tokens
#define EPS_  1e-6f
#define NREP_ (NH_/NKV_)       // 2

// ---------------- scratch (static device globals; no allocation) ----------------
__device__ float g_h   [(size_t)MT_*HID_];
__device__ float g_hn  [(size_t)MT_*HID_];
__device__ float g_q   [(size_t)MT_*NH_*HD_];
__device__ float g_k   [(size_t)MT_*NKV_*HD_];
__device__ float g_v   [(size_t)MT_*NKV_*HD_];
__device__ float g_sc  [(size_t)B_*NH_*L_*L_];   // 128 MB
__device__ float g_o   [(size_t)MT_*NH_*HD_];
__device__ float g_gate[(size_t)MT_*INT_];
__device__ float g_up  [(size_t)MT_*INT_];

// ---------------- generic tiled SGEMM body ----------------
// C[M,N] (ldc) = scale * A[M,K](lda) @ op(B)   (+ bias) (+ C if ACC)
// TRB=0: B is [K,N] row-major (ldb = row stride)
// TRB=1: B is [N,K] row-major (ldb = row stride)  => C = A @ B^T
// Tile: BM=BN=64, BK=16, 256 threads, 4x4 per-thread micro-tile.
template<int TRB, int ACC, int BIAS>
__device__ __forceinline__ void gemm_body(
    const float* __restrict__ A, int lda,
    const float* __restrict__ B, int ldb,
    float* __restrict__ C, int ldc, int K,
    const float* __restrict__ bias, float scale)
{
    __shared__ float As[16][64];
    __shared__ float Bs[16][72];   // padded so float4 rows stay 16B-aligned

    const int tid = threadIdx.x;
    const int tx  = tid & 15;
    const int ty  = tid >> 4;
    const int m0  = blockIdx.y * 64;
    const int n0  = blockIdx.x * 64;

    float acc[4][4];
#pragma unroll
    for (int i = 0; i < 4; i++)
#pragma unroll
        for (int j = 0; j < 4; j++) acc[i][j] = 0.f;

    const int arow = tid >> 2;           // 0..63
    const int ak   = (tid & 3) << 2;     // 0,4,8,12

    for (int k0 = 0; k0 < K; k0 += 16) {
        // load A tile (64x16), store transposed As[k][m]
        float4 va = *(const float4*)&A[(size_t)(m0 + arow) * lda + (k0 + ak)];
        As[ak + 0][arow] = va.x;
        As[ak + 1][arow] = va.y;
        As[ak + 2][arow] = va.z;
        As[ak + 3][arow] = va.w;

        if (TRB) {
            // B tile from [N,K]: rows are n (64), cols are k (16)
            const int brow = tid >> 2;          // 0..63 (n within tile)
            const int bk   = (tid & 3) << 2;    // k within tile
            float4 vb = *(const float4*)&B[(size_t)(n0 + brow) * ldb + (k0 + bk)];
            Bs[bk + 0][brow] = vb.x;
            Bs[bk + 1][brow] = vb.y;
            Bs[bk + 2][brow] = vb.z;
            Bs[bk + 3][brow] = vb.w;
        } else {
            const int brow = tid >> 4;          // 0..15 (k within tile)
            const int bcol = (tid & 15) << 2;   // n within tile
            float4 vb = *(const float4*)&B[(size_t)(k0 + brow) * ldb + (n0 + bcol)];
            *(float4*)&Bs[brow][bcol] = vb;
        }
        __syncthreads();

#pragma unroll
        for (int kk = 0; kk < 16; kk++) {
            float4 ra = *(const float4*)&As[kk][ty << 2];
            float4 rb = *(const float4*)&Bs[kk][tx << 2];
            float a0 = ra.x, a1 = ra.y, a2 = ra.z, a3 = ra.w;
            float b0 = rb.x, b1 = rb.y, b2 = rb.z, b3 = rb.w;
            acc[0][0] += a0 * b0; acc[0][1] += a0 * b1; acc[0][2] += a0 * b2; acc[0][3] += a0 * b3;
            acc[1][0] += a1 * b0; acc[1][1] += a1 * b1; acc[1][2] += a1 * b2; acc[1][3] += a1 * b3;
            acc[2][0] += a2 * b0; acc[2][1] += a2 * b1; acc[2][2] += a2 * b2; acc[2][3] += a2 * b3;
            acc[3][0] += a3 * b0; acc[3][1] += a3 * b1; acc[3][2] += a3 * b2; acc[3][3] += a3 * b3;
        }
        __syncthreads();
    }

#pragma unroll
    for (int iy = 0; iy < 4; iy++) {
        float* crow = &C[(size_t)(m0 + (ty << 2) + iy) * ldc + n0 + (tx << 2)];
#pragma unroll
        for (int ix = 0; ix < 4; ix++) {
            float vv = acc[iy][ix] * scale;
            if (BIAS) vv += bias[n0 + (tx << 2) + ix];
            if (ACC)  vv += crow[ix];
            crow[ix] = vv;
        }
    }
}

// ---------------- GEMM kernels ----------------
__global__ void __launch_bounds__(256)
k_gemm_nn(const float* A, int lda, const float* B, int ldb,
          float* C, int ldc, int K)
{
    gemm_body<0, 0, 0>(A, lda, B, ldb, C, ldc, K, nullptr, 1.f);
}

__global__ void __launch_bounds__(256)
k_gemm_nn_acc(const float* A, int lda, const float* B, int ldb,
              float* C, int ldc, int K)
{
    gemm_body<0, 1, 0>(A, lda, B, ldb, C, ldc, K, nullptr, 1.f);
}

__global__ void __launch_bounds__(256)
k_gemm_nn_bias(const float* A, int lda, const float* B, int ldb,
               float* C, int ldc, int K, const float* bias)
{
    gemm_body<0, 0, 1>(A, lda, B, ldb, C, ldc, K, bias, 1.f);
}

// scores[b,h,i,j] = scale * sum_d q[b,i,h,d] * k[b,j,h/2,d]
__global__ void __launch_bounds__(256)
k_scores(const float* q, const float* kk, float* sc, float scale)
{
    int z   = blockIdx.z;
    int b   = z / NH_;
    int hh  = z % NH_;
    int kvh = hh / NREP_;
    const float* A  = q  + ((size_t)b * L_ * NH_  + hh ) * HD_;
    const float* Bp = kk + ((size_t)b * L_ * NKV_ + kvh) * HD_;
    float* C = sc + (size_t)z * L_ * L_;
    gemm_body<1, 0, 0>(A, NH_ * HD_, Bp, NKV_ * HD_, C, L_, HD_, nullptr, scale);
}

// o[b,i,h,d] = sum_j attn[b,h,i,j] * v[b,j,h/2,d]
__global__ void __launch_bounds__(256)
k_attnv(const float* sc, const float* v, float* o)
{
    int z   = blockIdx.z;
    int b   = z / NH_;
    int hh  = z % NH_;
    int kvh = hh / NREP_;
    const float* A  = sc + (size_t)z * L_ * L_;
    const float* Bp = v  + ((size_t)b * L_ * NKV_ + kvh) * HD_;
    float* C = o + ((size_t)b * L_ * NH_ + hh) * HD_;
    gemm_body<0, 0, 0>(A, L_, Bp, NKV_ * HD_, C, NH_ * HD_, L_, nullptr, 1.f);
}

// ---------------- RMSNorm over width 2048 ----------------
__global__ void __launch_bounds__(256)
k_rmsnorm(const float* __restrict__ x, const float* __restrict__ w,
          float* __restrict__ y)
{
    int row = blockIdx.x;
    const float* xr = x + (size_t)row * HID_;
    float* yr = y + (size_t)row * HID_;
    int t = threadIdx.x;

    float ss = 0.f;
    for (int j = t; j < HID_; j += 256) {
        float v = xr[j];
        ss += v * v;
    }
    __shared__ float red[256];
    red[t] = ss;
    __syncthreads();
    for (int s = 128; s > 0; s >>= 1) {
        if (t < s) red[t] += red[t + s];
        __syncthreads();
    }
    float rs = rsqrtf(red[0] / (float)HID_ + EPS_);
    for (int j = t; j < HID_; j += 256)
        yr[j] = w[j] * xr[j] * rs;
}

// ---------------- per-head RMSNorm + RoPE (in place) ----------------
// qk layout: [B, L, nheads, HD]; one block (128 threads) per (token, head)
__global__ void __launch_bounds__(128)
k_qknorm_rope(float* __restrict__ qk, const float* __restrict__ w, int nheads)
{
    int idx  = blockIdx.x;
    int head = idx % nheads;
    int tok  = idx / nheads;
    int pos  = tok % L_;
    size_t base = ((size_t)tok * nheads + head) * HD_;
    int d = threadIdx.x;

    float v = qk[base + d];
    __shared__ float sh[128];
    sh[d] = v * v;
    __syncthreads();
    for (int s = 64; s > 0; s >>= 1) {
        if (d < s) sh[d] += sh[d + s];
        __syncthreads();
    }
    float rs = rsqrtf(sh[0] / (float)HD_ + EPS_);
    __syncthreads();

    float xn = w[d] * v * rs;
    sh[d] = xn;
    __syncthreads();
    float rot = (d < 64) ? -sh[d + 64] : sh[d - 64];

    int half = d & 63;
    // inv_freq = ROPE_BASE^{-2*half/HD}, ROPE_BASE = 1e6 -> ln = 13.815510557964274
    float inv = expf(-(2.f * (float)half / (float)HD_) * 13.815510557964274f);
    float ang = (float)pos * inv;
    float c = cosf(ang), s = sinf(ang);
    qk[base + d] = xn * c + rot * s;
}

// ---------------- masked softmax (in place), row length L=1024 ----------------
// grid: B*NH*L rows, 256 threads, 4 elems/thread
__global__ void __launch_bounds__(256)
k_softmax(float* __restrict__ sc, const int* __restrict__ am, int sliding)
{
    int row = blockIdx.x;
    int i   = row % L_;
    int b   = row / (NH_ * L_);
    float* r = sc + (size_t)row * L_;
    const int* amr = am + (size_t)b * L_;
    int t = threadIdx.x;

    float4 v4 = *(const float4*)&r[t * 4];
    float vals[4] = {v4.x, v4.y, v4.z, v4.w};
    bool keep[4];
    float mx = -INFINITY;
#pragma unroll
    for (int q = 0; q < 4; q++) {
        int j = t * 4 + q;
        int dj = i - j; if (dj < 0) dj = -dj;
        keep[q] = (amr[j] != 0) && (!sliding || dj <= SW_);
        if (!keep[q]) vals[q] = -INFINITY;
        mx = fmaxf(mx, vals[q]);
    }
    __shared__ float red[256];
    red[t] = mx;
    __syncthreads();
    for (int s = 128; s > 0; s >>= 1) {
        if (t < s) red[t] = fmaxf(red[t], red[t + s]);
        __syncthreads();
    }
    float rowmax = red[0];
    __syncthreads();

    float e[4];
    float ssum = 0.f;
#pragma unroll
    for (int q = 0; q < 4; q++) {
        e[q] = keep[q] ? expf(vals[q] - rowmax) : 0.f;
        ssum += e[q];
    }
    red[t] = ssum;
    __syncthreads();
    for (int s = 128; s > 0; s >>= 1) {
        if (t < s) red[t] += red[t + s];
        __syncthreads();
    }
    float total = red[0];
    float inv = (total > 0.f) ? (1.f / total) : 0.f;

    float4 o4;
    o4.x = e[0] * inv; o4.y = e[1] * inv; o4.z = e[2] * inv; o4.w = e[3] * inv;
    *(float4*)&r[t * 4] = o4;
}

// ---------------- SiLU(gate) * up, in place into gate ----------------
__global__ void __launch_bounds__(256)
k_silu_mul(float* __restrict__ g, const float* __restrict__ u, int n)
{
    int idx = blockIdx.x * 256 + threadIdx.x;
    if (idx < n) {
        float gv = g[idx];
        float s  = gv / (1.f + expf(-gv));
        g[idx] = s * u[idx];
    }
}

// ---------------- host driver ----------------
extern "C" void kernel_launch(void* const* d_in, const int* in_sizes, int n_in,
                              void* d_out, int out_size)
{
    const float* x       = (const float*)d_in[0];
    const int*   am      = (const int*)  d_in[1];
    const float* W_embed = (const float*)d_in[2];
    const float* b_embed = (const float*)d_in[3];
    const float* Wq      = (const float*)d_in[4];
    const float* Wk      = (const float*)d_in[5];
    const float* Wv      = (const float*)d_in[6];
    const float* Wo      = (const float*)d_in[7];
    const float* w_in_ln = (const float*)d_in[8];
    const float* w_post  = (const float*)d_in[9];
    const float* w_qn    = (const float*)d_in[10];
    const float* w_kn    = (const float*)d_in[11];
    const float* Wg      = (const float*)d_in[12];
    const float* Wu      = (const float*)d_in[13];
    const float* Wd      = (const float*)d_in[14];
    const float* w_final = (const float*)d_in[15];
    float* out = (float*)d_out;

    float *h_, *hn_, *q_, *k_, *v_, *sc_, *o_, *gate_, *up_;
    cudaGetSymbolAddress((void**)&h_,    g_h);
    cudaGetSymbolAddress((void**)&hn_,   g_hn);
    cudaGetSymbolAddress((void**)&q_,    g_q);
    cudaGetSymbolAddress((void**)&k_,    g_k);
    cudaGetSymbolAddress((void**)&v_,    g_v);
    cudaGetSymbolAddress((void**)&sc_,   g_sc);
    cudaGetSymbolAddress((void**)&o_,    g_o);
    cudaGetSymbolAddress((void**)&gate_, g_gate);
    cudaGetSymbolAddress((void**)&up_,   g_up);

    const float scale = 0.08838834764831845f;  // HD^-0.5

    // embed: h = x @ W_embed + b
    k_gemm_nn_bias<<<dim3(HID_ / 64, MT_ / 64), 256>>>(
        x, TXT_, W_embed, HID_, h_, HID_, TXT_, b_embed);

    for (int i = 0; i < NL_; i++) {
        const float* wq_i = Wq + (size_t)i * HID_ * (NH_ * HD_);
        const float* wk_i = Wk + (size_t)i * HID_ * (NKV_ * HD_);
        const float* wv_i = Wv + (size_t)i * HID_ * (NKV_ * HD_);
        const float* wo_i = Wo + (size_t)i * (NH_ * HD_) * HID_;
        const float* wg_i = Wg + (size_t)i * HID_ * INT_;
        const float* wu_i = Wu + (size_t)i * HID_ * INT_;
        const float* wd_i = Wd + (size_t)i * INT_ * HID_;

        // pre-attn norm
        k_rmsnorm<<<MT_, 256>>>(h_, w_in_ln + (size_t)i * HID_, hn_);

        // QKV projections
        k_gemm_nn<<<dim3((NH_ * HD_) / 64, MT_ / 64), 256>>>(
            hn_, HID_, wq_i, NH_ * HD_, q_, NH_ * HD_, HID_);
        k_gemm_nn<<<dim3((NKV_ * HD_) / 64, MT_ / 64), 256>>>(
            hn_, HID_, wk_i, NKV_ * HD_, k_, NKV_ * HD_, HID_);
        k_gemm_nn<<<dim3((NKV_ * HD_) / 64, MT_ / 64), 256>>>(
            hn_, HID_, wv_i, NKV_ * HD_, v_, NKV_ * HD_, HID_);

        // q/k head-norm + RoPE (in place)
        k_qknorm_rope<<<MT_ * NH_, 128>>>(q_, w_qn + (size_t)i * HD_, NH_);
        k_qknorm_rope<<<MT_ * NKV_, 128>>>(k_, w_kn + (size_t)i * HD_, NKV_);

        // scores = scale * q @ k^T (batched over B*NH)
        k_scores<<<dim3(L_ / 64, L_ / 64, B_ * NH_), 256>>>(q_, k_, sc_, scale);

        // masked softmax (even layers: sliding window)
        k_softmax<<<B_ * NH_ * L_, 256>>>(sc_, am, (i % 2 == 0) ? 1 : 0);

        // o = attn @ v
        k_attnv<<<dim3(HD_ / 64, L_ / 64, B_ * NH_), 256>>>(sc_, v_, o_);

        // h = h + o @ Wo
        k_gemm_nn_acc<<<dim3(HID_ / 64, MT_ / 64), 256>>>(
            o_, NH_ * HD_, wo_i, HID_, h_, HID_, NH_ * HD_);

        // post-attn norm + MLP
        k_rmsnorm<<<MT_, 256>>>(h_, w_post + (size_t)i * HID_, hn_);
        k_gemm_nn<<<dim3(INT_ / 64, MT_ / 64), 256>>>(
            hn_, HID_, wg_i, INT_, gate_, INT_, HID_);
        k_gemm_nn<<<dim3(INT_ / 64, MT_ / 64), 256>>>(
            hn_, HID_, wu_i, INT_, up_, INT_, HID_);
        k_silu_mul<<<(MT_ * INT_) / 256, 256>>>(gate_, up_, MT_ * INT_);
        // h = h + act @ Wd
        k_gemm_nn_acc<<<dim3(HID_ / 64, MT_ / 64), 256>>>(
            gate_, INT_, wd_i, HID_, h_, HID_, INT_);
    }

    // final norm -> out
    k_rmsnorm<<<MT_, 256>>>(h_, w_final, out);
}

// round 3
// speedup vs baseline: 2.2669x; 2.2669x over previous
#include <cuda_runtime.h>
#include <cuda_bf16.h>
#include <math.h>
#include <stdint.h>

// ---------------- problem constants ----------------
#define B_    2
#define L_    1024
#define TXT_  1024
#define HID_  2048
#define INT_  6144
#define NH_   16
#define NKV_  8
#define HD_   128
#define NL_   8
#define SW_   128
#define MT_   (B_*L_)          // 2048 tokens
#define EPS_  1e-6f
#define NREP_ (NH_/NKV_)       // 2

// ---------------- scratch (static device globals; no allocation) ----------------
__device__ float g_h   [(size_t)MT_*HID_];
__device__ float g_hn  [(size_t)MT_*HID_];
__device__ float g_q   [(size_t)MT_*NH_*HD_];
__device__ float g_k   [(size_t)MT_*NKV_*HD_];
__device__ float g_v   [(size_t)MT_*NKV_*HD_];
__device__ float g_sc  [(size_t)B_*NH_*L_*L_];   // 128 MB
__device__ float g_o   [(size_t)MT_*NH_*HD_];
__device__ float g_gate[(size_t)MT_*INT_];
__device__ float g_up  [(size_t)MT_*INT_];

// ---------------- bf16 split helpers ----------------
__device__ __forceinline__ uint32_t pack_bf16(__nv_bfloat16 lo_elem, __nv_bfloat16 hi_elem) {
    // low 16 bits = first (lower-k) element
    return (uint32_t)__bfloat16_as_ushort(lo_elem) |
           ((uint32_t)__bfloat16_as_ushort(hi_elem) << 16);
}

// split two consecutive-k floats into packed hi and packed lo bf16 pairs
__device__ __forceinline__ void split2(float x0, float x1, uint32_t& hi, uint32_t& lo) {
    __nv_bfloat16 h0 = __float2bfloat16(x0);
    __nv_bfloat16 h1 = __float2bfloat16(x1);
    float r0 = x0 - __bfloat162float(h0);
    float r1 = x1 - __bfloat162float(h1);
    hi = pack_bf16(h0, h1);
    lo = pack_bf16(__float2bfloat16(r0), __float2bfloat16(r1));
}

__device__ __forceinline__ void mma_bf16(float& d0, float& d1, float& d2, float& d3,
                                         uint32_t a0, uint32_t a1, uint32_t a2, uint32_t a3,
                                         uint32_t b0, uint32_t b1)
{
    asm volatile(
        "mma.sync.aligned.m16n8k16.row.col.f32.bf16.bf16.f32 "
        "{%0,%1,%2,%3}, {%4,%5,%6,%7}, {%8,%9}, {%0,%1,%2,%3};\n"
        : "+f"(d0), "+f"(d1), "+f"(d2), "+f"(d3)
        : "r"(a0), "r"(a1), "r"(a2), "r"(a3), "r"(b0), "r"(b1));
}

// ---------------- tensor-core GEMM body (bf16x3 split precision) ----------------
// C[M,N](ldc) = scale * A[M,K](lda) @ op(B) (+bias) (+C if ACC)
// TRB=0: B is [K,N] row-major; TRB=1: B is [N,K] row-major => C = A @ B^T
// CTA tile 128x128, BK=16, 256 threads = 8 warps (4 m-rows x 2 n-cols),
// each warp computes 32x64 via m16n8k16 bf16 mma, 3 MMAs (hh, hl, lh) per product.
// Smem holds packed k-pairs: As[m][k2] (k2 = k/2, 8 per tile), Bs[k2][n].
#define AS_STR 12     // uint32 stride per m-row (8 used + pad): conflict-free frag reads
#define BS_STR 136    // uint32 stride per k2-row (128 used + pad): conflict-free frag reads
template<int TRB, int ACC, int BIAS>
__device__ __forceinline__ void mma_gemm_body(
    const float* __restrict__ A, int lda,
    const float* __restrict__ B, int ldb,
    float* __restrict__ C, int ldc, int K,
    const float* __restrict__ bias, float scale)
{
    __shared__ uint32_t As[2][128 * AS_STR];  // [hi/lo][m][k2]
    __shared__ uint32_t Bs[2][8 * BS_STR];    // [hi/lo][k2][n]

    const int tid  = threadIdx.x;
    const int lane = tid & 31;
    const int warp = tid >> 5;
    const int m0   = blockIdx.y * 128;
    const int n0   = blockIdx.x * 128;
    const int wm   = (warp >> 1) * 32;
    const int wn   = (warp & 1) * 64;
    const int g    = lane >> 2;   // 0..7
    const int t    = lane & 3;    // 0..3

    float acc[2][8][4];
#pragma unroll
    for (int mi = 0; mi < 2; mi++)
#pragma unroll
        for (int ni = 0; ni < 8; ni++)
#pragma unroll
            for (int r = 0; r < 4; r++) acc[mi][ni][r] = 0.f;

    // A loader: thread handles rows ar, ar+64; k-cols ac..ac+3 (k2 = ac/2, ac/2+1)
    const int ar = tid >> 2;           // 0..63
    const int ac = (tid & 3) << 2;     // 0,4,8,12
    const int ak2 = (tid & 3) << 1;    // 0,2,4,6
    // B loader (TRB=0): thread handles k-rows 2*br, 2*br+1; n-cols bc..bc+3
    const int br = tid >> 5;           // 0..7 (k2 index)
    const int bc = (tid & 31) << 2;    // 0..124

    for (int k0 = 0; k0 < K; k0 += 16) {
        // ---- load + split A tile (128 x 16) ----
#pragma unroll
        for (int half = 0; half < 2; half++) {
            int row = ar + half * 64;
            float4 va = *(const float4*)&A[(size_t)(m0 + row) * lda + (k0 + ac)];
            uint32_t h0, l0, h1, l1;
            split2(va.x, va.y, h0, l0);
            split2(va.z, va.w, h1, l1);
            As[0][row * AS_STR + ak2    ] = h0;
            As[0][row * AS_STR + ak2 + 1] = h1;
            As[1][row * AS_STR + ak2    ] = l0;
            As[1][row * AS_STR + ak2 + 1] = l1;
        }
        // ---- load + split B tile into Bs[k2][n] ----
        if (TRB) {
            // B is [N,K]: thread reads B[n][k..k+3] (4 consecutive k) -> 2 packed pairs
#pragma unroll
            for (int half = 0; half < 2; half++) {
                int nrow = ar + half * 64;
                float4 vb = *(const float4*)&B[(size_t)(n0 + nrow) * ldb + (k0 + ac)];
                uint32_t h0, l0, h1, l1;
                split2(vb.x, vb.y, h0, l0);
                split2(vb.z, vb.w, h1, l1);
                Bs[0][(ak2    ) * BS_STR + nrow] = h0;
                Bs[0][(ak2 + 1) * BS_STR + nrow] = h1;
                Bs[1][(ak2    ) * BS_STR + nrow] = l0;
                Bs[1][(ak2 + 1) * BS_STR + nrow] = l1;
            }
        } else {
            // B is [K,N]: thread reads rows k=2*br and 2*br+1, cols bc..bc+3, packs along k
            const float* b0p = &B[(size_t)(k0 + 2 * br    ) * ldb + (n0 + bc)];
            const float* b1p = &B[(size_t)(k0 + 2 * br + 1) * ldb + (n0 + bc)];
            float4 r0 = *(const float4*)b0p;
            float4 r1 = *(const float4*)b1p;
            uint32_t* dh = &Bs[0][br * BS_STR + bc];
            uint32_t* dl = &Bs[1][br * BS_STR + bc];
            uint32_t h, l;
            split2(r0.x, r1.x, h, l); dh[0] = h; dl[0] = l;
            split2(r0.y, r1.y, h, l); dh[1] = h; dl[1] = l;
            split2(r0.z, r1.z, h, l); dh[2] = h; dl[2] = l;
            split2(r0.w, r1.w, h, l); dh[3] = h; dl[3] = l;
        }
        __syncthreads();

        // ---- compute: one k16 slab, 3 MMAs (hh, hl, lh) per 16x8 product ----
        uint32_t ah[2][4], al[2][4];
#pragma unroll
        for (int mi = 0; mi < 2; mi++) {
            int mbase = wm + mi * 16;
#pragma unroll
            for (int q = 0; q < 2; q++) {     // q: k2 offset 0 / +4
#pragma unroll
                for (int rr = 0; rr < 2; rr++) {  // rr: row g / g+8
                    int idx = (mbase + g + rr * 8) * AS_STR + t + q * 4;
                    ah[mi][q * 2 + rr] = As[0][idx];
                    al[mi][q * 2 + rr] = As[1][idx];
                }
            }
        }
#pragma unroll
        for (int ni = 0; ni < 8; ni++) {
            int ncol = wn + ni * 8 + g;
            uint32_t bh0 = Bs[0][(t    ) * BS_STR + ncol];
            uint32_t bh1 = Bs[0][(t + 4) * BS_STR + ncol];
            uint32_t bl0 = Bs[1][(t    ) * BS_STR + ncol];
            uint32_t bl1 = Bs[1][(t + 4) * BS_STR + ncol];
#pragma unroll
            for (int mi = 0; mi < 2; mi++) {
                // correction terms first, then main product
                mma_bf16(acc[mi][ni][0], acc[mi][ni][1], acc[mi][ni][2], acc[mi][ni][3],
                         ah[mi][0], ah[mi][1], ah[mi][2], ah[mi][3], bl0, bl1);
                mma_bf16(acc[mi][ni][0], acc[mi][ni][1], acc[mi][ni][2], acc[mi][ni][3],
                         al[mi][0], al[mi][1], al[mi][2], al[mi][3], bh0, bh1);
                mma_bf16(acc[mi][ni][0], acc[mi][ni][1], acc[mi][ni][2], acc[mi][ni][3],
                         ah[mi][0], ah[mi][1], ah[mi][2], ah[mi][3], bh0, bh1);
            }
        }
        __syncthreads();
    }

    // ---- epilogue ----
#pragma unroll
    for (int mi = 0; mi < 2; mi++) {
        int row0 = m0 + wm + mi * 16 + g;
#pragma unroll
        for (int ni = 0; ni < 8; ni++) {
            int col = n0 + wn + ni * 8 + 2 * t;
            float bx = 0.f, by = 0.f;
            if (BIAS) { bx = bias[col]; by = bias[col + 1]; }
            {
                float2* cp = (float2*)&C[(size_t)row0 * ldc + col];
                float2 prev = ACC ? *cp : make_float2(0.f, 0.f);
                float2 vv;
                vv.x = acc[mi][ni][0] * scale + bx + prev.x;
                vv.y = acc[mi][ni][1] * scale + by + prev.y;
                *cp = vv;
            }
            {
                float2* cp = (float2*)&C[(size_t)(row0 + 8) * ldc + col];
                float2 prev = ACC ? *cp : make_float2(0.f, 0.f);
                float2 vv;
                vv.x = acc[mi][ni][2] * scale + bx + prev.x;
                vv.y = acc[mi][ni][3] * scale + by + prev.y;
                *cp = vv;
            }
        }
    }
}

// ---------------- GEMM kernels ----------------
__global__ void __launch_bounds__(256)
k_gemm_nn(const float* A, int lda, const float* B, int ldb,
          float* C, int ldc, int K)
{
    mma_gemm_body<0, 0, 0>(A, lda, B, ldb, C, ldc, K, nullptr, 1.f);
}

__global__ void __launch_bounds__(256)
k_gemm_nn_acc(const float* A, int lda, const float* B, int ldb,
              float* C, int ldc, int K)
{
    mma_gemm_body<0, 1, 0>(A, lda, B, ldb, C, ldc, K, nullptr, 1.f);
}

__global__ void __launch_bounds__(256)
k_gemm_nn_bias(const float* A, int lda, const float* B, int ldb,
               float* C, int ldc, int K, const float* bias)
{
    mma_gemm_body<0, 0, 1>(A, lda, B, ldb, C, ldc, K, bias, 1.f);
}

// scores[b,h,i,j] = scale * sum_d q[b,i,h,d] * k[b,j,h/2,d]
__global__ void __launch_bounds__(256)
k_scores(const float* q, const float* kk, float* sc, float scale)
{
    int z   = blockIdx.z;
    int b   = z / NH_;
    int hh  = z % NH_;
    int kvh = hh / NREP_;
    const float* A  = q  + ((size_t)b * L_ * NH_  + hh ) * HD_;
    const float* Bp = kk + ((size_t)b * L_ * NKV_ + kvh) * HD_;
    float* C = sc + (size_t)z * L_ * L_;
    mma_gemm_body<1, 0, 0>(A, NH_ * HD_, Bp, NKV_ * HD_, C, L_, HD_, nullptr, scale);
}

// o[b,i,h,d] = sum_j attn[b,h,i,j] * v[b,j,h/2,d]
__global__ void __launch_bounds__(256)
k_attnv(const float* sc, const float* v, float* o)
{
    int z   = blockIdx.z;
    int b   = z / NH_;
    int hh  = z % NH_;
    int kvh = hh / NREP_;
    const float* A  = sc + (size_t)z * L_ * L_;
    const float* Bp = v  + ((size_t)b * L_ * NKV_ + kvh) * HD_;
    float* C = o + ((size_t)b * L_ * NH_ + hh) * HD_;
    mma_gemm_body<0, 0, 0>(A, L_, Bp, NKV_ * HD_, C, NH_ * HD_, L_, nullptr, 1.f);
}

// ---------------- RMSNorm over width 2048 ----------------
__global__ void __launch_bounds__(256)
k_rmsnorm(const float* __restrict__ x, const float* __restrict__ w,
          float* __restrict__ y)
{
    int row = blockIdx.x;
    const float* xr = x + (size_t)row * HID_;
    float* yr = y + (size_t)row * HID_;
    int t = threadIdx.x;

    float ss = 0.f;
    for (int j = t; j < HID_; j += 256) {
        float v = xr[j];
        ss += v * v;
    }
    __shared__ float red[256];
    red[t] = ss;
    __syncthreads();
    for (int s = 128; s > 0; s >>= 1) {
        if (t < s) red[t] += red[t + s];
        __syncthreads();
    }
    float rs = rsqrtf(red[0] / (float)HID_ + EPS_);
    for (int j = t; j < HID_; j += 256)
        yr[j] = w[j] * xr[j] * rs;
}

// ---------------- per-head RMSNorm + RoPE (in place) ----------------
__global__ void __launch_bounds__(128)
k_qknorm_rope(float* __restrict__ qk, const float* __restrict__ w, int nheads)
{
    int idx  = blockIdx.x;
    int head = idx % nheads;
    int tok  = idx / nheads;
    int pos  = tok % L_;
    size_t base = ((size_t)tok * nheads + head) * HD_;
    int d = threadIdx.x;

    float v = qk[base + d];
    __shared__ float sh[128];
    sh[d] = v * v;
    __syncthreads();
    for (int s = 64; s > 0; s >>= 1) {
        if (d < s) sh[d] += sh[d + s];
        __syncthreads();
    }
    float rs = rsqrtf(sh[0] / (float)HD_ + EPS_);
    __syncthreads();

    float xn = w[d] * v * rs;
    sh[d] = xn;
    __syncthreads();
    float rot = (d < 64) ? -sh[d + 64] : sh[d - 64];

    int half = d & 63;
    float inv = expf(-(2.f * (float)half / (float)HD_) * 13.815510557964274f);
    float ang = (float)pos * inv;
    float c = cosf(ang), s = sinf(ang);
    qk[base + d] = xn * c + rot * s;
}

// ---------------- masked softmax (in place), row length L=1024 ----------------
__global__ void __launch_bounds__(256)
k_softmax(float* __restrict__ sc, const int* __restrict__ am, int sliding)
{
    int row = blockIdx.x;
    int i   = row % L_;
    int b   = row / (NH_ * L_);
    float* r = sc + (size_t)row * L_;
    const int* amr = am + (size_t)b * L_;
    int t = threadIdx.x;

    float4 v4 = *(const float4*)&r[t * 4];
    float vals[4] = {v4.x, v4.y, v4.z, v4.w};
    bool keep[4];
    float mx = -INFINITY;
#pragma unroll
    for (int q = 0; q < 4; q++) {
        int j = t * 4 + q;
        int dj = i - j; if (dj < 0) dj = -dj;
        keep[q] = (amr[j] != 0) && (!sliding || dj <= SW_);
        if (!keep[q]) vals[q] = -INFINITY;
        mx = fmaxf(mx, vals[q]);
    }
    __shared__ float red[256];
    red[t] = mx;
    __syncthreads();
    for (int s = 128; s > 0; s >>= 1) {
        if (t < s) red[t] = fmaxf(red[t], red[t + s]);
        __syncthreads();
    }
    float rowmax = red[0];
    __syncthreads();

    float e[4];
    float ssum = 0.f;
#pragma unroll
    for (int q = 0; q < 4; q++) {
        e[q] = keep[q] ? expf(vals[q] - rowmax) : 0.f;
        ssum += e[q];
    }
    red[t] = ssum;
    __syncthreads();
    for (int s = 128; s > 0; s >>= 1) {
        if (t < s) red[t] += red[t + s];
        __syncthreads();
    }
    float total = red[0];
    float inv = (total > 0.f) ? (1.f / total) : 0.f;

    float4 o4;
    o4.x = e[0] * inv; o4.y = e[1] * inv; o4.z = e[2] * inv; o4.w = e[3] * inv;
    *(float4*)&r[t * 4] = o4;
}

// ---------------- SiLU(gate) * up ----------------
__global__ void __launch_bounds__(256)
k_silu_mul(float* __restrict__ g, const float* __restrict__ u, int n)
{
    int idx = blockIdx.x * 256 + threadIdx.x;
    if (idx < n) {
        float gv = g[idx];
        float s  = gv / (1.f + expf(-gv));
        g[idx] = s * u[idx];
    }
}

// ---------------- host driver ----------------
extern "C" void kernel_launch(void* const* d_in, const int* in_sizes, int n_in,
                              void* d_out, int out_size)
{
    const float* x       = (const float*)d_in[0];
    const int*   am      = (const int*)  d_in[1];
    const float* W_embed = (const float*)d_in[2];
    const float* b_embed = (const float*)d_in[3];
    const float* Wq      = (const float*)d_in[4];
    const float* Wk      = (const float*)d_in[5];
    const float* Wv      = (const float*)d_in[6];
    const float* Wo      = (const float*)d_in[7];
    const float* w_in_ln = (const float*)d_in[8];
    const float* w_post  = (const float*)d_in[9];
    const float* w_qn    = (const float*)d_in[10];
    const float* w_kn    = (const float*)d_in[11];
    const float* Wg      = (const float*)d_in[12];
    const float* Wu      = (const float*)d_in[13];
    const float* Wd      = (const float*)d_in[14];
    const float* w_final = (const float*)d_in[15];
    float* out = (float*)d_out;

    float *h_, *hn_, *q_, *k_, *v_, *sc_, *o_, *gate_, *up_;
    cudaGetSymbolAddress((void**)&h_,    g_h);
    cudaGetSymbolAddress((void**)&hn_,   g_hn);
    cudaGetSymbolAddress((void**)&q_,    g_q);
    cudaGetSymbolAddress((void**)&k_,    g_k);
    cudaGetSymbolAddress((void**)&v_,    g_v);
    cudaGetSymbolAddress((void**)&sc_,   g_sc);
    cudaGetSymbolAddress((void**)&o_,    g_o);
    cudaGetSymbolAddress((void**)&gate_, g_gate);
    cudaGetSymbolAddress((void**)&up_,   g_up);

    const float scale = 0.08838834764831845f;  // HD^-0.5

    // embed: h = x @ W_embed + b
    k_gemm_nn_bias<<<dim3(HID_ / 128, MT_ / 128), 256>>>(
        x, TXT_, W_embed, HID_, h_, HID_, TXT_, b_embed);

    for (int i = 0; i < NL_; i++) {
        const float* wq_i = Wq + (size_t)i * HID_ * (NH_ * HD_);
        const float* wk_i = Wk + (size_t)i * HID_ * (NKV_ * HD_);
        const float* wv_i = Wv + (size_t)i * HID_ * (NKV_ * HD_);
        const float* wo_i = Wo + (size_t)i * (NH_ * HD_) * HID_;
        const float* wg_i = Wg + (size_t)i * HID_ * INT_;
        const float* wu_i = Wu + (size_t)i * HID_ * INT_;
        const float* wd_i = Wd + (size_t)i * INT_ * HID_;

        // pre-attn norm
        k_rmsnorm<<<MT_, 256>>>(h_, w_in_ln + (size_t)i * HID_, hn_);

        // QKV projections
        k_gemm_nn<<<dim3((NH_ * HD_) / 128, MT_ / 128), 256>>>(
            hn_, HID_, wq_i, NH_ * HD_, q_, NH_ * HD_, HID_);
        k_gemm_nn<<<dim3((NKV_ * HD_) / 128, MT_ / 128), 256>>>(
            hn_, HID_, wk_i, NKV_ * HD_, k_, NKV_ * HD_, HID_);
        k_gemm_nn<<<dim3((NKV_ * HD_) / 128, MT_ / 128), 256>>>(
            hn_, HID_, wv_i, NKV_ * HD_, v_, NKV_ * HD_, HID_);

        // q/k head-norm + RoPE (in place)
        k_qknorm_rope<<<MT_ * NH_, 128>>>(q_, w_qn + (size_t)i * HD_, NH_);
        k_qknorm_rope<<<MT_ * NKV_, 128>>>(k_, w_kn + (size_t)i * HD_, NKV_);

        // scores = scale * q @ k^T (batched over B*NH)
        k_scores<<<dim3(L_ / 128, L_ / 128, B_ * NH_), 256>>>(q_, k_, sc_, scale);

        // masked softmax (even layers: sliding window)
        k_softmax<<<B_ * NH_ * L_, 256>>>(sc_, am, (i % 2 == 0) ? 1 : 0);

        // o = attn @ v
        k_attnv<<<dim3(HD_ / 128, L_ / 128, B_ * NH_), 256>>>(sc_, v_, o_);

        // h = h + o @ Wo
        k_gemm_nn_acc<<<dim3(HID_ / 128, MT_ / 128), 256>>>(
            o_, NH_ * HD_, wo_i, HID_, h_, HID_, NH_ * HD_);

        // post-attn norm + MLP
        k_rmsnorm<<<MT_, 256>>>(h_, w_post + (size_t)i * HID_, hn_);
        k_gemm_nn<<<dim3(INT_ / 128, MT_ / 128), 256>>>(
            hn_, HID_, wg_i, INT_, gate_, INT_, HID_);
        k_gemm_nn<<<dim3(INT_ / 128, MT_ / 128), 256>>>(
            hn_, HID_, wu_i, INT_, up_, INT_, HID_);
        k_silu_mul<<<(MT_ * INT_) / 256, 256>>>(gate_, up_, MT_ * INT_);
        // h = h + act @ Wd
        k_gemm_nn_acc<<<dim3(HID_ / 128, MT_ / 128), 256>>>(
            gate_, INT_, wd_i, HID_, h_, HID_, INT_);
    }

    // final norm -> out
    k_rmsnorm<<<MT_, 256>>>(h_, w_final, out);
}

// round 4
// speedup vs baseline: 2.3476x; 1.0356x over previous
#include <cuda_runtime.h>
#include <cuda_bf16.h>
#include <math.h>
#include <stdint.h>

// ---------------- problem constants ----------------
#define B_    2
#define L_    1024
#define TXT_  1024
#define HID_  2048
#define INT_  6144
#define NH_   16
#define NKV_  8
#define HD_   128
#define NL_   8
#define SW_   128
#define MT_   (B_*L_)          // 2048 tokens
#define EPS_  1e-6f
#define NREP_ (NH_/NKV_)       // 2

// ---------------- scratch (static device globals; no allocation) ----------------
__device__ float g_h   [(size_t)MT_*HID_];
__device__ float g_hn  [(size_t)MT_*HID_];
__device__ float g_q   [(size_t)MT_*NH_*HD_];
__device__ float g_k   [(size_t)MT_*NKV_*HD_];
__device__ float g_v   [(size_t)MT_*NKV_*HD_];
__device__ float g_sc  [(size_t)B_*NH_*L_*L_];   // 128 MB
__device__ float g_o   [(size_t)MT_*NH_*HD_];
__device__ float g_gate[(size_t)MT_*INT_];
__device__ float g_up  [(size_t)MT_*INT_];

// ---------------- bf16 split helpers ----------------
__device__ __forceinline__ uint32_t pack_bf16(__nv_bfloat16 lo_elem, __nv_bfloat16 hi_elem) {
    return (uint32_t)__bfloat16_as_ushort(lo_elem) |
           ((uint32_t)__bfloat16_as_ushort(hi_elem) << 16);
}

__device__ __forceinline__ void split2(float x0, float x1, uint32_t& hi, uint32_t& lo) {
    __nv_bfloat16 h0 = __float2bfloat16(x0);
    __nv_bfloat16 h1 = __float2bfloat16(x1);
    float r0 = x0 - __bfloat162float(h0);
    float r1 = x1 - __bfloat162float(h1);
    hi = pack_bf16(h0, h1);
    lo = pack_bf16(__float2bfloat16(r0), __float2bfloat16(r1));
}

__device__ __forceinline__ void mma_bf16(float& d0, float& d1, float& d2, float& d3,
                                         uint32_t a0, uint32_t a1, uint32_t a2, uint32_t a3,
                                         uint32_t b0, uint32_t b1)
{
    asm volatile(
        "mma.sync.aligned.m16n8k16.row.col.f32.bf16.bf16.f32 "
        "{%0,%1,%2,%3}, {%4,%5,%6,%7}, {%8,%9}, {%0,%1,%2,%3};\n"
        : "+f"(d0), "+f"(d1), "+f"(d2), "+f"(d3)
        : "r"(a0), "r"(a1), "r"(a2), "r"(a3), "r"(b0), "r"(b1));
}

// ---------------- tensor-core GEMM body (bf16x3, 2-stage double buffer) ----------------
// C[M,N](ldc) = scale * A[M,K](lda) @ op(B) (+bias) (+C if ACC)
// TRB=0: B is [K,N] row-major; TRB=1: B is [N,K] row-major => C = A @ B^T
// CTA tile 128x128, BK=16, 256 threads = 8 warps (4x2), warp tile 32x64.
#define AS_STR 12     // uint32 stride per m-row: conflict-free fragment reads
#define BS_STR 136    // uint32 stride per k2-row: conflict-free fragment reads
template<int TRB, int ACC, int BIAS>
__device__ __forceinline__ void mma_gemm_body(
    const float* __restrict__ A, int lda,
    const float* __restrict__ B, int ldb,
    float* __restrict__ C, int ldc, int K,
    const float* __restrict__ bias, float scale)
{
    __shared__ uint32_t As[2][2][128 * AS_STR];  // [buf][hi/lo][m][k2]
    __shared__ uint32_t Bs[2][2][8 * BS_STR];    // [buf][hi/lo][k2][n]

    const int tid  = threadIdx.x;
    const int lane = tid & 31;
    const int warp = tid >> 5;
    const int m0   = blockIdx.y * 128;
    const int n0   = blockIdx.x * 128;
    const int wm   = (warp >> 1) * 32;
    const int wn   = (warp & 1) * 64;
    const int g    = lane >> 2;   // 0..7
    const int t    = lane & 3;    // 0..3

    float acc[2][8][4];
#pragma unroll
    for (int mi = 0; mi < 2; mi++)
#pragma unroll
        for (int ni = 0; ni < 8; ni++)
#pragma unroll
            for (int r = 0; r < 4; r++) acc[mi][ni][r] = 0.f;

    const int ar  = tid >> 2;          // 0..63
    const int ac  = (tid & 3) << 2;    // 0,4,8,12
    const int ak2 = (tid & 3) << 1;    // 0,2,4,6
    const int br  = tid >> 5;          // 0..7 (k2)
    const int bc  = (tid & 31) << 2;   // 0..124

    float4 areg[2], breg[2];

    auto load_g = [&](int k0) {
#pragma unroll
        for (int h = 0; h < 2; h++)
            areg[h] = *(const float4*)&A[(size_t)(m0 + ar + h * 64) * lda + (k0 + ac)];
        if (TRB) {
#pragma unroll
            for (int h = 0; h < 2; h++)
                breg[h] = *(const float4*)&B[(size_t)(n0 + ar + h * 64) * ldb + (k0 + ac)];
        } else {
            breg[0] = *(const float4*)&B[(size_t)(k0 + 2 * br    ) * ldb + (n0 + bc)];
            breg[1] = *(const float4*)&B[(size_t)(k0 + 2 * br + 1) * ldb + (n0 + bc)];
        }
    };

    auto store_s = [&](int buf) {
#pragma unroll
        for (int h = 0; h < 2; h++) {
            int row = ar + h * 64;
            uint32_t h0, l0, h1, l1;
            split2(areg[h].x, areg[h].y, h0, l0);
            split2(areg[h].z, areg[h].w, h1, l1);
            As[buf][0][row * AS_STR + ak2    ] = h0;
            As[buf][0][row * AS_STR + ak2 + 1] = h1;
            As[buf][1][row * AS_STR + ak2    ] = l0;
            As[buf][1][row * AS_STR + ak2 + 1] = l1;
        }
        if (TRB) {
#pragma unroll
            for (int h = 0; h < 2; h++) {
                int nrow = ar + h * 64;
                uint32_t h0, l0, h1, l1;
                split2(breg[h].x, breg[h].y, h0, l0);
                split2(breg[h].z, breg[h].w, h1, l1);
                Bs[buf][0][(ak2    ) * BS_STR + nrow] = h0;
                Bs[buf][0][(ak2 + 1) * BS_STR + nrow] = h1;
                Bs[buf][1][(ak2    ) * BS_STR + nrow] = l0;
                Bs[buf][1][(ak2 + 1) * BS_STR + nrow] = l1;
            }
        } else {
            uint32_t* dh = &Bs[buf][0][br * BS_STR + bc];
            uint32_t* dl = &Bs[buf][1][br * BS_STR + bc];
            uint32_t hh, ll;
            split2(breg[0].x, breg[1].x, hh, ll); dh[0] = hh; dl[0] = ll;
            split2(breg[0].y, breg[1].y, hh, ll); dh[1] = hh; dl[1] = ll;
            split2(breg[0].z, breg[1].z, hh, ll); dh[2] = hh; dl[2] = ll;
            split2(breg[0].w, breg[1].w, hh, ll); dh[3] = hh; dl[3] = ll;
        }
    };

    auto compute = [&](int buf) {
        uint32_t ah[2][4], al[2][4];
#pragma unroll
        for (int mi = 0; mi < 2; mi++) {
            int mbase = wm + mi * 16;
#pragma unroll
            for (int q = 0; q < 2; q++) {
#pragma unroll
                for (int rr = 0; rr < 2; rr++) {
                    int idx = (mbase + g + rr * 8) * AS_STR + t + q * 4;
                    ah[mi][q * 2 + rr] = As[buf][0][idx];
                    al[mi][q * 2 + rr] = As[buf][1][idx];
                }
            }
        }
#pragma unroll
        for (int ni = 0; ni < 8; ni++) {
            int ncol = wn + ni * 8 + g;
            uint32_t bh0 = Bs[buf][0][(t    ) * BS_STR + ncol];
            uint32_t bh1 = Bs[buf][0][(t + 4) * BS_STR + ncol];
            uint32_t bl0 = Bs[buf][1][(t    ) * BS_STR + ncol];
            uint32_t bl1 = Bs[buf][1][(t + 4) * BS_STR + ncol];
#pragma unroll
            for (int mi = 0; mi < 2; mi++) {
                mma_bf16(acc[mi][ni][0], acc[mi][ni][1], acc[mi][ni][2], acc[mi][ni][3],
                         ah[mi][0], ah[mi][1], ah[mi][2], ah[mi][3], bl0, bl1);
                mma_bf16(acc[mi][ni][0], acc[mi][ni][1], acc[mi][ni][2], acc[mi][ni][3],
                         al[mi][0], al[mi][1], al[mi][2], al[mi][3], bh0, bh1);
                mma_bf16(acc[mi][ni][0], acc[mi][ni][1], acc[mi][ni][2], acc[mi][ni][3],
                         ah[mi][0], ah[mi][1], ah[mi][2], ah[mi][3], bh0, bh1);
            }
        }
    };

    // ---- pipelined mainloop ----
    load_g(0);
    store_s(0);
    __syncthreads();
    int cur = 0;
    for (int k0 = 0; k0 < K; k0 += 16) {
        const bool more = (k0 + 16 < K);
        if (more) load_g(k0 + 16);          // global loads in flight during compute
        compute(cur);
        if (more) {
            store_s(cur ^ 1);               // write other buffer (safe: last read 2 slabs ago)
            __syncthreads();
            cur ^= 1;
        }
    }

    // ---- epilogue ----
#pragma unroll
    for (int mi = 0; mi < 2; mi++) {
        int row0 = m0 + wm + mi * 16 + g;
#pragma unroll
        for (int ni = 0; ni < 8; ni++) {
            int col = n0 + wn + ni * 8 + 2 * t;
            float bx = 0.f, by = 0.f;
            if (BIAS) { bx = bias[col]; by = bias[col + 1]; }
            {
                float2* cp = (float2*)&C[(size_t)row0 * ldc + col];
                float2 prev = ACC ? *cp : make_float2(0.f, 0.f);
                float2 vv;
                vv.x = acc[mi][ni][0] * scale + bx + prev.x;
                vv.y = acc[mi][ni][1] * scale + by + prev.y;
                *cp = vv;
            }
            {
                float2* cp = (float2*)&C[(size_t)(row0 + 8) * ldc + col];
                float2 prev = ACC ? *cp : make_float2(0.f, 0.f);
                float2 vv;
                vv.x = acc[mi][ni][2] * scale + bx + prev.x;
                vv.y = acc[mi][ni][3] * scale + by + prev.y;
                *cp = vv;
            }
        }
    }
}

// ---------------- GEMM kernels ----------------
__global__ void __launch_bounds__(256, 2)
k_gemm_nn(const float* A, int lda, const float* B, int ldb,
          float* C, int ldc, int K)
{
    mma_gemm_body<0, 0, 0>(A, lda, B, ldb, C, ldc, K, nullptr, 1.f);
}

__global__ void __launch_bounds__(256, 2)
k_gemm_nn_acc(const float* A, int lda, const float* B, int ldb,
              float* C, int ldc, int K)
{
    mma_gemm_body<0, 1, 0>(A, lda, B, ldb, C, ldc, K, nullptr, 1.f);
}

__global__ void __launch_bounds__(256, 2)
k_gemm_nn_bias(const float* A, int lda, const float* B, int ldb,
               float* C, int ldc, int K, const float* bias)
{
    mma_gemm_body<0, 0, 1>(A, lda, B, ldb, C, ldc, K, bias, 1.f);
}

// scores[b,h,i,j] = scale * sum_d q[b,i,h,d] * k[b,j,h/2,d]
__global__ void __launch_bounds__(256, 2)
k_scores(const float* q, const float* kk, float* sc, float scale)
{
    int z   = blockIdx.z;
    int b   = z / NH_;
    int hh  = z % NH_;
    int kvh = hh / NREP_;
    const float* A  = q  + ((size_t)b * L_ * NH_  + hh ) * HD_;
    const float* Bp = kk + ((size_t)b * L_ * NKV_ + kvh) * HD_;
    float* C = sc + (size_t)z * L_ * L_;
    mma_gemm_body<1, 0, 0>(A, NH_ * HD_, Bp, NKV_ * HD_, C, L_, HD_, nullptr, scale);
}

// o[b,i,h,d] = sum_j attn[b,h,i,j] * v[b,j,h/2,d]
__global__ void __launch_bounds__(256, 2)
k_attnv(const float* sc, const float* v, float* o)
{
    int z   = blockIdx.z;
    int b   = z / NH_;
    int hh  = z % NH_;
    int kvh = hh / NREP_;
    const float* A  = sc + (size_t)z * L_ * L_;
    const float* Bp = v  + ((size_t)b * L_ * NKV_ + kvh) * HD_;
    float* C = o + ((size_t)b * L_ * NH_ + hh) * HD_;
    mma_gemm_body<0, 0, 0>(A, L_, Bp, NKV_ * HD_, C, NH_ * HD_, L_, nullptr, 1.f);
}

// ---------------- RMSNorm over width 2048 ----------------
__global__ void __launch_bounds__(256)
k_rmsnorm(const float* __restrict__ x, const float* __restrict__ w,
          float* __restrict__ y)
{
    int row = blockIdx.x;
    const float* xr = x + (size_t)row * HID_;
    float* yr = y + (size_t)row * HID_;
    int t = threadIdx.x;

    float ss = 0.f;
    for (int j = t; j < HID_; j += 256) {
        float v = xr[j];
        ss += v * v;
    }
    __shared__ float red[256];
    red[t] = ss;
    __syncthreads();
    for (int s = 128; s > 0; s >>= 1) {
        if (t < s) red[t] += red[t + s];
        __syncthreads();
    }
    float rs = rsqrtf(red[0] / (float)HID_ + EPS_);
    for (int j = t; j < HID_; j += 256)
        yr[j] = w[j] * xr[j] * rs;
}

// ---------------- per-head RMSNorm + RoPE (in place) ----------------
__global__ void __launch_bounds__(128)
k_qknorm_rope(float* __restrict__ qk, const float* __restrict__ w, int nheads)
{
    int idx  = blockIdx.x;
    int head = idx % nheads;
    int tok  = idx / nheads;
    int pos  = tok % L_;
    size_t base = ((size_t)tok * nheads + head) * HD_;
    int d = threadIdx.x;

    float v = qk[base + d];
    __shared__ float sh[128];
    sh[d] = v * v;
    __syncthreads();
    for (int s = 64; s > 0; s >>= 1) {
        if (d < s) sh[d] += sh[d + s];
        __syncthreads();
    }
    float rs = rsqrtf(sh[0] / (float)HD_ + EPS_);
    __syncthreads();

    float xn = w[d] * v * rs;
    sh[d] = xn;
    __syncthreads();
    float rot = (d < 64) ? -sh[d + 64] : sh[d - 64];

    int half = d & 63;
    float inv = expf(-(2.f * (float)half / (float)HD_) * 13.815510557964274f);
    float ang = (float)pos * inv;
    float c = cosf(ang), s = sinf(ang);
    qk[base + d] = xn * c + rot * s;
}

// ---------------- masked softmax (in place), row length L=1024 ----------------
__global__ void __launch_bounds__(256)
k_softmax(float* __restrict__ sc, const int* __restrict__ am, int sliding)
{
    int row = blockIdx.x;
    int i   = row % L_;
    int b   = row / (NH_ * L_);
    float* r = sc + (size_t)row * L_;
    const int* amr = am + (size_t)b * L_;
    int t = threadIdx.x;

    float4 v4 = *(const float4*)&r[t * 4];
    float vals[4] = {v4.x, v4.y, v4.z, v4.w};
    bool keep[4];
    float mx = -INFINITY;
#pragma unroll
    for (int q = 0; q < 4; q++) {
        int j = t * 4 + q;
        int dj = i - j; if (dj < 0) dj = -dj;
        keep[q] = (amr[j] != 0) && (!sliding || dj <= SW_);
        if (!keep[q]) vals[q] = -INFINITY;
        mx = fmaxf(mx, vals[q]);
    }
    __shared__ float red[256];
    red[t] = mx;
    __syncthreads();
    for (int s = 128; s > 0; s >>= 1) {
        if (t < s) red[t] = fmaxf(red[t], red[t + s]);
        __syncthreads();
    }
    float rowmax = red[0];
    __syncthreads();

    float e[4];
    float ssum = 0.f;
#pragma unroll
    for (int q = 0; q < 4; q++) {
        e[q] = keep[q] ? expf(vals[q] - rowmax) : 0.f;
        ssum += e[q];
    }
    red[t] = ssum;
    __syncthreads();
    for (int s = 128; s > 0; s >>= 1) {
        if (t < s) red[t] += red[t + s];
        __syncthreads();
    }
    float total = red[0];
    float inv = (total > 0.f) ? (1.f / total) : 0.f;

    float4 o4;
    o4.x = e[0] * inv; o4.y = e[1] * inv; o4.z = e[2] * inv; o4.w = e[3] * inv;
    *(float4*)&r[t * 4] = o4;
}

// ---------------- SiLU(gate) * up ----------------
__global__ void __launch_bounds__(256)
k_silu_mul(float* __restrict__ g, const float* __restrict__ u, int n)
{
    int idx = blockIdx.x * 256 + threadIdx.x;
    if (idx < n) {
        float gv = g[idx];
        float s  = gv / (1.f + expf(-gv));
        g[idx] = s * u[idx];
    }
}

// ---------------- host driver ----------------
extern "C" void kernel_launch(void* const* d_in, const int* in_sizes, int n_in,
                              void* d_out, int out_size)
{
    const float* x       = (const float*)d_in[0];
    const int*   am      = (const int*)  d_in[1];
    const float* W_embed = (const float*)d_in[2];
    const float* b_embed = (const float*)d_in[3];
    const float* Wq      = (const float*)d_in[4];
    const float* Wk      = (const float*)d_in[5];
    const float* Wv      = (const float*)d_in[6];
    const float* Wo      = (const float*)d_in[7];
    const float* w_in_ln = (const float*)d_in[8];
    const float* w_post  = (const float*)d_in[9];
    const float* w_qn    = (const float*)d_in[10];
    const float* w_kn    = (const float*)d_in[11];
    const float* Wg      = (const float*)d_in[12];
    const float* Wu      = (const float*)d_in[13];
    const float* Wd      = (const float*)d_in[14];
    const float* w_final = (const float*)d_in[15];
    float* out = (float*)d_out;

    float *h_, *hn_, *q_, *k_, *v_, *sc_, *o_, *gate_, *up_;
    cudaGetSymbolAddress((void**)&h_,    g_h);
    cudaGetSymbolAddress((void**)&hn_,   g_hn);
    cudaGetSymbolAddress((void**)&q_,    g_q);
    cudaGetSymbolAddress((void**)&k_,    g_k);
    cudaGetSymbolAddress((void**)&v_,    g_v);
    cudaGetSymbolAddress((void**)&sc_,   g_sc);
    cudaGetSymbolAddress((void**)&o_,    g_o);
    cudaGetSymbolAddress((void**)&gate_, g_gate);
    cudaGetSymbolAddress((void**)&up_,   g_up);

    const float scale = 0.08838834764831845f;  // HD^-0.5

    // embed: h = x @ W_embed + b
    k_gemm_nn_bias<<<dim3(HID_ / 128, MT_ / 128), 256>>>(
        x, TXT_, W_embed, HID_, h_, HID_, TXT_, b_embed);

    for (int i = 0; i < NL_; i++) {
        const float* wq_i = Wq + (size_t)i * HID_ * (NH_ * HD_);
        const float* wk_i = Wk + (size_t)i * HID_ * (NKV_ * HD_);
        const float* wv_i = Wv + (size_t)i * HID_ * (NKV_ * HD_);
        const float* wo_i = Wo + (size_t)i * (NH_ * HD_) * HID_;
        const float* wg_i = Wg + (size_t)i * HID_ * INT_;
        const float* wu_i = Wu + (size_t)i * HID_ * INT_;
        const float* wd_i = Wd + (size_t)i * INT_ * HID_;

        // pre-attn norm
        k_rmsnorm<<<MT_, 256>>>(h_, w_in_ln + (size_t)i * HID_, hn_);

        // QKV projections
        k_gemm_nn<<<dim3((NH_ * HD_) / 128, MT_ / 128), 256>>>(
            hn_, HID_, wq_i, NH_ * HD_, q_, NH_ * HD_, HID_);
        k_gemm_nn<<<dim3((NKV_ * HD_) / 128, MT_ / 128), 256>>>(
            hn_, HID_, wk_i, NKV_ * HD_, k_, NKV_ * HD_, HID_);
        k_gemm_nn<<<dim3((NKV_ * HD_) / 128, MT_ / 128), 256>>>(
            hn_, HID_, wv_i, NKV_ * HD_, v_, NKV_ * HD_, HID_);

        // q/k head-norm + RoPE (in place)
        k_qknorm_rope<<<MT_ * NH_, 128>>>(q_, w_qn + (size_t)i * HD_, NH_);
        k_qknorm_rope<<<MT_ * NKV_, 128>>>(k_, w_kn + (size_t)i * HD_, NKV_);

        // scores = scale * q @ k^T (batched over B*NH)
        k_scores<<<dim3(L_ / 128, L_ / 128, B_ * NH_), 256>>>(q_, k_, sc_, scale);

        // masked softmax (even layers: sliding window)
        k_softmax<<<B_ * NH_ * L_, 256>>>(sc_, am, (i % 2 == 0) ? 1 : 0);

        // o = attn @ v
        k_attnv<<<dim3(HD_ / 128, L_ / 128, B_ * NH_), 256>>>(sc_, v_, o_);

        // h = h + o @ Wo
        k_gemm_nn_acc<<<dim3(HID_ / 128, MT_ / 128), 256>>>(
            o_, NH_ * HD_, wo_i, HID_, h_, HID_, NH_ * HD_);

        // post-attn norm + MLP
        k_rmsnorm<<<MT_, 256>>>(h_, w_post + (size_t)i * HID_, hn_);
        k_gemm_nn<<<dim3(INT_ / 128, MT_ / 128), 256>>>(
            hn_, HID_, wg_i, INT_, gate_, INT_, HID_);
        k_gemm_nn<<<dim3(INT_ / 128, MT_ / 128), 256>>>(
            hn_, HID_, wu_i, INT_, up_, INT_, HID_);
        k_silu_mul<<<(MT_ * INT_) / 256, 256>>>(gate_, up_, MT_ * INT_);
        // h = h + act @ Wd
        k_gemm_nn_acc<<<dim3(HID_ / 128, MT_ / 128), 256>>>(
            gate_, INT_, wd_i, HID_, h_, HID_, INT_);
    }

    // final norm -> out
    k_rmsnorm<<<MT_, 256>>>(h_, w_final, out);
}

// round 7
// speedup vs baseline: 2.3643x; 1.0071x over previous
#include <cuda_runtime.h>
#include <cuda_bf16.h>
#include <math.h>
#include <stdint.h>

// ---------------- problem constants ----------------
#define B_    2
#define L_    1024
#define TXT_  1024
#define HID_  2048
#define INT_  6144
#define NH_   16
#define NKV_  8
#define HD_   128
#define NL_   8
#define SW_   128
#define MT_   (B_*L_)          // 2048 tokens
#define EPS_  1e-6f
#define NREP_ (NH_/NKV_)       // 2

// ---------------- scratch (static device globals; no allocation) ----------------
__device__ float g_h   [(size_t)MT_*HID_];
__device__ float g_hn  [(size_t)MT_*HID_];
__device__ float g_q   [(size_t)MT_*NH_*HD_];
__device__ float g_k   [(size_t)MT_*NKV_*HD_];
__device__ float g_v   [(size_t)MT_*NKV_*HD_];
__device__ float g_sc  [(size_t)B_*NH_*L_*L_];   // 128 MB
__device__ float g_o   [(size_t)MT_*NH_*HD_];
__device__ float g_gate[(size_t)MT_*INT_];
__device__ float g_up  [(size_t)MT_*INT_];

// ---------------- bf16 split helpers ----------------
__device__ __forceinline__ uint32_t pack_bf16(__nv_bfloat16 lo_elem, __nv_bfloat16 hi_elem) {
    return (uint32_t)__bfloat16_as_ushort(lo_elem) |
           ((uint32_t)__bfloat16_as_ushort(hi_elem) << 16);
}

__device__ __forceinline__ void split2(float x0, float x1, uint32_t& hi, uint32_t& lo) {
    __nv_bfloat16 h0 = __float2bfloat16(x0);
    __nv_bfloat16 h1 = __float2bfloat16(x1);
    float r0 = x0 - __bfloat162float(h0);
    float r1 = x1 - __bfloat162float(h1);
    hi = pack_bf16(h0, h1);
    lo = pack_bf16(__float2bfloat16(r0), __float2bfloat16(r1));
}

__device__ __forceinline__ void mma_bf16(float& d0, float& d1, float& d2, float& d3,
                                         uint32_t a0, uint32_t a1, uint32_t a2, uint32_t a3,
                                         uint32_t b0, uint32_t b1)
{
    asm volatile(
        "mma.sync.aligned.m16n8k16.row.col.f32.bf16.bf16.f32 "
        "{%0,%1,%2,%3}, {%4,%5,%6,%7}, {%8,%9}, {%0,%1,%2,%3};\n"
        : "+f"(d0), "+f"(d1), "+f"(d2), "+f"(d3)
        : "r"(a0), "r"(a1), "r"(a2), "r"(a3), "r"(b0), "r"(b1));
}

// ---------------- tensor-core GEMM body (bf16x3, 2-stage double buffer) ----------------
// C[M,N](ldc) = scale * A[M,K](lda) @ op(B) (+bias) (+C if ACC)
// TRB=0: B is [K,N] row-major; TRB=1: B is [N,K] row-major => C = A @ B^T
// CTA tile 128x128, BK=16, 256 threads = 8 warps (4x2), warp tile 32x64.
#define AS_STR 12     // uint32 stride per m-row: conflict-free fragment reads
#define BS_STR 136    // uint32 stride per k2-row: conflict-free fragment reads
template<int TRB, int ACC, int BIAS>
__device__ __forceinline__ void mma_gemm_body(
    const float* __restrict__ A, int lda,
    const float* __restrict__ B, int ldb,
    float* __restrict__ C, int ldc, int K,
    const float* __restrict__ bias, float scale)
{
    __shared__ uint32_t As[2][2][128 * AS_STR];  // [buf][hi/lo][m][k2]
    __shared__ uint32_t Bs[2][2][8 * BS_STR];    // [buf][hi/lo][k2][n]

    const int tid  = threadIdx.x;
    const int lane = tid & 31;
    const int warp = tid >> 5;
    const int m0   = blockIdx.y * 128;
    const int n0   = blockIdx.x * 128;
    const int wm   = (warp >> 1) * 32;
    const int wn   = (warp & 1) * 64;
    const int g    = lane >> 2;   // 0..7
    const int t    = lane & 3;    // 0..3

    float acc[2][8][4];
#pragma unroll
    for (int mi = 0; mi < 2; mi++)
#pragma unroll
        for (int ni = 0; ni < 8; ni++)
#pragma unroll
            for (int r = 0; r < 4; r++) acc[mi][ni][r] = 0.f;

    const int ar  = tid >> 2;          // 0..63
    const int ac  = (tid & 3) << 2;    // 0,4,8,12
    const int ak2 = (tid & 3) << 1;    // 0,2,4,6
    const int br  = tid >> 5;          // 0..7 (k2)
    const int bc  = (tid & 31) << 2;   // 0..124

    float4 areg[2], breg[2];

    auto load_g = [&](int k0) {
#pragma unroll
        for (int h = 0; h < 2; h++)
            areg[h] = *(const float4*)&A[(size_t)(m0 + ar + h * 64) * lda + (k0 + ac)];
        if (TRB) {
#pragma unroll
            for (int h = 0; h < 2; h++)
                breg[h] = *(const float4*)&B[(size_t)(n0 + ar + h * 64) * ldb + (k0 + ac)];
        } else {
            breg[0] = *(const float4*)&B[(size_t)(k0 + 2 * br    ) * ldb + (n0 + bc)];
            breg[1] = *(const float4*)&B[(size_t)(k0 + 2 * br + 1) * ldb + (n0 + bc)];
        }
    };

    auto store_s = [&](int buf) {
#pragma unroll
        for (int h = 0; h < 2; h++) {
            int row = ar + h * 64;
            uint32_t h0, l0, h1, l1;
            split2(areg[h].x, areg[h].y, h0, l0);
            split2(areg[h].z, areg[h].w, h1, l1);
            As[buf][0][row * AS_STR + ak2    ] = h0;
            As[buf][0][row * AS_STR + ak2 + 1] = h1;
            As[buf][1][row * AS_STR + ak2    ] = l0;
            As[buf][1][row * AS_STR + ak2 + 1] = l1;
        }
        if (TRB) {
#pragma unroll
            for (int h = 0; h < 2; h++) {
                int nrow = ar + h * 64;
                uint32_t h0, l0, h1, l1;
                split2(breg[h].x, breg[h].y, h0, l0);
                split2(breg[h].z, breg[h].w, h1, l1);
                Bs[buf][0][(ak2    ) * BS_STR + nrow] = h0;
                Bs[buf][0][(ak2 + 1) * BS_STR + nrow] = h1;
                Bs[buf][1][(ak2    ) * BS_STR + nrow] = l0;
                Bs[buf][1][(ak2 + 1) * BS_STR + nrow] = l1;
            }
        } else {
            uint32_t* dh = &Bs[buf][0][br * BS_STR + bc];
            uint32_t* dl = &Bs[buf][1][br * BS_STR + bc];
            uint32_t hh, ll;
            split2(breg[0].x, breg[1].x, hh, ll); dh[0] = hh; dl[0] = ll;
            split2(breg[0].y, breg[1].y, hh, ll); dh[1] = hh; dl[1] = ll;
            split2(breg[0].z, breg[1].z, hh, ll); dh[2] = hh; dl[2] = ll;
            split2(breg[0].w, breg[1].w, hh, ll); dh[3] = hh; dl[3] = ll;
        }
    };

    auto compute = [&](int buf) {
        uint32_t ah[2][4], al[2][4];
#pragma unroll
        for (int mi = 0; mi < 2; mi++) {
            int mbase = wm + mi * 16;
#pragma unroll
            for (int q = 0; q < 2; q++) {
#pragma unroll
                for (int rr = 0; rr < 2; rr++) {
                    int idx = (mbase + g + rr * 8) * AS_STR + t + q * 4;
                    ah[mi][q * 2 + rr] = As[buf][0][idx];
                    al[mi][q * 2 + rr] = As[buf][1][idx];
                }
            }
        }
#pragma unroll
        for (int ni = 0; ni < 8; ni++) {
            int ncol = wn + ni * 8 + g;
            uint32_t bh0 = Bs[buf][0][(t    ) * BS_STR + ncol];
            uint32_t bh1 = Bs[buf][0][(t + 4) * BS_STR + ncol];
            uint32_t bl0 = Bs[buf][1][(t    ) * BS_STR + ncol];
            uint32_t bl1 = Bs[buf][1][(t + 4) * BS_STR + ncol];
#pragma unroll
            for (int mi = 0; mi < 2; mi++) {
                mma_bf16(acc[mi][ni][0], acc[mi][ni][1], acc[mi][ni][2], acc[mi][ni][3],
                         ah[mi][0], ah[mi][1], ah[mi][2], ah[mi][3], bl0, bl1);
                mma_bf16(acc[mi][ni][0], acc[mi][ni][1], acc[mi][ni][2], acc[mi][ni][3],
                         al[mi][0], al[mi][1], al[mi][2], al[mi][3], bh0, bh1);
                mma_bf16(acc[mi][ni][0], acc[mi][ni][1], acc[mi][ni][2], acc[mi][ni][3],
                         ah[mi][0], ah[mi][1], ah[mi][2], ah[mi][3], bh0, bh1);
            }
        }
    };

    // ---- pipelined mainloop ----
    load_g(0);
    store_s(0);
    __syncthreads();
    int cur = 0;
    for (int k0 = 0; k0 < K; k0 += 16) {
        const bool more = (k0 + 16 < K);
        if (more) load_g(k0 + 16);          // global loads in flight during compute
        compute(cur);
        if (more) {
            store_s(cur ^ 1);               // write other buffer (safe: last read 2 slabs ago)
            __syncthreads();
            cur ^= 1;
        }
    }

    // ---- epilogue ----
#pragma unroll
    for (int mi = 0; mi < 2; mi++) {
        int row0 = m0 + wm + mi * 16 + g;
#pragma unroll
        for (int ni = 0; ni < 8; ni++) {
            int col = n0 + wn + ni * 8 + 2 * t;
            float bx = 0.f, by = 0.f;
            if (BIAS) { bx = bias[col]; by = bias[col + 1]; }
            {
                float2* cp = (float2*)&C[(size_t)row0 * ldc + col];
                float2 prev = ACC ? *cp : make_float2(0.f, 0.f);
                float2 vv;
                vv.x = acc[mi][ni][0] * scale + bx + prev.x;
                vv.y = acc[mi][ni][1] * scale + by + prev.y;
                *cp = vv;
            }
            {
                float2* cp = (float2*)&C[(size_t)(row0 + 8) * ldc + col];
                float2 prev = ACC ? *cp : make_float2(0.f, 0.f);
                float2 vv;
                vv.x = acc[mi][ni][2] * scale + bx + prev.x;
                vv.y = acc[mi][ni][3] * scale + by + prev.y;
                *cp = vv;
            }
        }
    }
}

// ---------------- GEMM kernels ----------------
__global__ void __launch_bounds__(256, 2)
k_gemm_nn(const float* A, int lda, const float* B, int ldb,
          float* C, int ldc, int K)
{
    mma_gemm_body<0, 0, 0>(A, lda, B, ldb, C, ldc, K, nullptr, 1.f);
}

__global__ void __launch_bounds__(256, 2)
k_gemm_nn_acc(const float* A, int lda, const float* B, int ldb,
              float* C, int ldc, int K)
{
    mma_gemm_body<0, 1, 0>(A, lda, B, ldb, C, ldc, K, nullptr, 1.f);
}

__global__ void __launch_bounds__(256, 2)
k_gemm_nn_bias(const float* A, int lda, const float* B, int ldb,
               float* C, int ldc, int K, const float* bias)
{
    mma_gemm_body<0, 0, 1>(A, lda, B, ldb, C, ldc, K, bias, 1.f);
}

// scores[b,h,i,j] = scale * sum_d q[b,i,h,d] * k[b,j,h/2,d]
__global__ void __launch_bounds__(256, 2)
k_scores(const float* q, const float* kk, float* sc, float scale)
{
    int z   = blockIdx.z;
    int b   = z / NH_;
    int hh  = z % NH_;
    int kvh = hh / NREP_;
    const float* A  = q  + ((size_t)b * L_ * NH_  + hh ) * HD_;
    const float* Bp = kk + ((size_t)b * L_ * NKV_ + kvh) * HD_;
    float* C = sc + (size_t)z * L_ * L_;
    mma_gemm_body<1, 0, 0>(A, NH_ * HD_, Bp, NKV_ * HD_, C, L_, HD_, nullptr, scale);
}

// o[b,i,h,d] = sum_j attn[b,h,i,j] * v[b,j,h/2,d]
__global__ void __launch_bounds__(256, 2)
k_attnv(const float* sc, const float* v, float* o)
{
    int z   = blockIdx.z;
    int b   = z / NH_;
    int hh  = z % NH_;
    int kvh = hh / NREP_;
    const float* A  = sc + (size_t)z * L_ * L_;
    const float* Bp = v  + ((size_t)b * L_ * NKV_ + kvh) * HD_;
    float* C = o + ((size_t)b * L_ * NH_ + hh) * HD_;
    mma_gemm_body<0, 0, 0>(A, L_, Bp, NKV_ * HD_, C, NH_ * HD_, L_, nullptr, 1.f);
}

// ---------------- RMSNorm over width 2048 ----------------
__global__ void __launch_bounds__(256)
k_rmsnorm(const float* __restrict__ x, const float* __restrict__ w,
          float* __restrict__ y)
{
    int row = blockIdx.x;
    const float* xr = x + (size_t)row * HID_;
    float* yr = y + (size_t)row * HID_;
    int t = threadIdx.x;

    float ss = 0.f;
    for (int j = t; j < HID_; j += 256) {
        float v = xr[j];
        ss += v * v;
    }
    __shared__ float red[256];
    red[t] = ss;
    __syncthreads();
    for (int s = 128; s > 0; s >>= 1) {
        if (t < s) red[t] += red[t + s];
        __syncthreads();
    }
    float rs = rsqrtf(red[0] / (float)HID_ + EPS_);
    for (int j = t; j < HID_; j += 256)
        yr[j] = w[j] * xr[j] * rs;
}

// ---------------- per-head RMSNorm + RoPE (in place) ----------------
__global__ void __launch_bounds__(128)
k_qknorm_rope(float* __restrict__ qk, const float* __restrict__ w, int nheads)
{
    int idx  = blockIdx.x;
    int head = idx % nheads;
    int tok  = idx / nheads;
    int pos  = tok % L_;
    size_t base = ((size_t)tok * nheads + head) * HD_;
    int d = threadIdx.x;

    float v = qk[base + d];
    __shared__ float sh[128];
    sh[d] = v * v;
    __syncthreads();
    for (int s = 64; s > 0; s >>= 1) {
        if (d < s) sh[d] += sh[d + s];
        __syncthreads();
    }
    float rs = rsqrtf(sh[0] / (float)HD_ + EPS_);
    __syncthreads();

    float xn = w[d] * v * rs;
    sh[d] = xn;
    __syncthreads();
    float rot = (d < 64) ? -sh[d + 64] : sh[d - 64];

    int half = d & 63;
    float inv = expf(-(2.f * (float)half / (float)HD_) * 13.815510557964274f);
    float ang = (float)pos * inv;
    float c = cosf(ang), s = sinf(ang);
    qk[base + d] = xn * c + rot * s;
}

// ---------------- masked softmax (in place), row length L=1024 ----------------
__global__ void __launch_bounds__(256)
k_softmax(float* __restrict__ sc, const int* __restrict__ am, int sliding)
{
    int row = blockIdx.x;
    int i   = row % L_;
    int b   = row / (NH_ * L_);
    float* r = sc + (size_t)row * L_;
    const int* amr = am + (size_t)b * L_;
    int t = threadIdx.x;

    float4 v4 = *(const float4*)&r[t * 4];
    float vals[4] = {v4.x, v4.y, v4.z, v4.w};
    bool keep[4];
    float mx = -INFINITY;
#pragma unroll
    for (int q = 0; q < 4; q++) {
        int j = t * 4 + q;
        int dj = i - j; if (dj < 0) dj = -dj;
        keep[q] = (amr[j] != 0) && (!sliding || dj <= SW_);
        if (!keep[q]) vals[q] = -INFINITY;
        mx = fmaxf(mx, vals[q]);
    }
    __shared__ float red[256];
    red[t] = mx;
    __syncthreads();
    for (int s = 128; s > 0; s >>= 1) {
        if (t < s) red[t] = fmaxf(red[t], red[t + s]);
        __syncthreads();
    }
    float rowmax = red[0];
    __syncthreads();

    float e[4];
    float ssum = 0.f;
#pragma unroll
    for (int q = 0; q < 4; q++) {
        e[q] = keep[q] ? expf(vals[q] - rowmax) : 0.f;
        ssum += e[q];
    }
    red[t] = ssum;
    __syncthreads();
    for (int s = 128; s > 0; s >>= 1) {
        if (t < s) red[t] += red[t + s];
        __syncthreads();
    }
    float total = red[0];
    float inv = (total > 0.f) ? (1.f / total) : 0.f;

    float4 o4;
    o4.x = e[0] * inv; o4.y = e[1] * inv; o4.z = e[2] * inv; o4.w = e[3] * inv;
    *(float4*)&r[t * 4] = o4;
}

// ---------------- SiLU(gate) * up ----------------
__global__ void __launch_bounds__(256)
k_silu_mul(float* __restrict__ g, const float* __restrict__ u, int n)
{
    int idx = blockIdx.x * 256 + threadIdx.x;
    if (idx < n) {
        float gv = g[idx];
        float s  = gv / (1.f + expf(-gv));
        g[idx] = s * u[idx];
    }
}

// ---------------- host driver ----------------
extern "C" void kernel_launch(void* const* d_in, const int* in_sizes, int n_in,
                              void* d_out, int out_size)
{
    const float* x       = (const float*)d_in[0];
    const int*   am      = (const int*)  d_in[1];
    const float* W_embed = (const float*)d_in[2];
    const float* b_embed = (const float*)d_in[3];
    const float* Wq      = (const float*)d_in[4];
    const float* Wk      = (const float*)d_in[5];
    const float* Wv      = (const float*)d_in[6];
    const float* Wo      = (const float*)d_in[7];
    const float* w_in_ln = (const float*)d_in[8];
    const float* w_post  = (const float*)d_in[9];
    const float* w_qn    = (const float*)d_in[10];
    const float* w_kn    = (const float*)d_in[11];
    const float* Wg      = (const float*)d_in[12];
    const float* Wu      = (const float*)d_in[13];
    const float* Wd      = (const float*)d_in[14];
    const float* w_final = (const float*)d_in[15];
    float* out = (float*)d_out;

    float *h_, *hn_, *q_, *k_, *v_, *sc_, *o_, *gate_, *up_;
    cudaGetSymbolAddress((void**)&h_,    g_h);
    cudaGetSymbolAddress((void**)&hn_,   g_hn);
    cudaGetSymbolAddress((void**)&q_,    g_q);
    cudaGetSymbolAddress((void**)&k_,    g_k);
    cudaGetSymbolAddress((void**)&v_,    g_v);
    cudaGetSymbolAddress((void**)&sc_,   g_sc);
    cudaGetSymbolAddress((void**)&o_,    g_o);
    cudaGetSymbolAddress((void**)&gate_, g_gate);
    cudaGetSymbolAddress((void**)&up_,   g_up);

    const float scale = 0.08838834764831845f;  // HD^-0.5

    // embed: h = x @ W_embed + b
    k_gemm_nn_bias<<<dim3(HID_ / 128, MT_ / 128), 256>>>(
        x, TXT_, W_embed, HID_, h_, HID_, TXT_, b_embed);

    for (int i = 0; i < NL_; i++) {
        const float* wq_i = Wq + (size_t)i * HID_ * (NH_ * HD_);
        const float* wk_i = Wk + (size_t)i * HID_ * (NKV_ * HD_);
        const float* wv_i = Wv + (size_t)i * HID_ * (NKV_ * HD_);
        const float* wo_i = Wo + (size_t)i * (NH_ * HD_) * HID_;
        const float* wg_i = Wg + (size_t)i * HID_ * INT_;
        const float* wu_i = Wu + (size_t)i * HID_ * INT_;
        const float* wd_i = Wd + (size_t)i * INT_ * HID_;

        // pre-attn norm
        k_rmsnorm<<<MT_, 256>>>(h_, w_in_ln + (size_t)i * HID_, hn_);

        // QKV projections
        k_gemm_nn<<<dim3((NH_ * HD_) / 128, MT_ / 128), 256>>>(
            hn_, HID_, wq_i, NH_ * HD_, q_, NH_ * HD_, HID_);
        k_gemm_nn<<<dim3((NKV_ * HD_) / 128, MT_ / 128), 256>>>(
            hn_, HID_, wk_i, NKV_ * HD_, k_, NKV_ * HD_, HID_);
        k_gemm_nn<<<dim3((NKV_ * HD_) / 128, MT_ / 128), 256>>>(
            hn_, HID_, wv_i, NKV_ * HD_, v_, NKV_ * HD_, HID_);

        // q/k head-norm + RoPE (in place)
        k_qknorm_rope<<<MT_ * NH_, 128>>>(q_, w_qn + (size_t)i * HD_, NH_);
        k_qknorm_rope<<<MT_ * NKV_, 128>>>(k_, w_kn + (size_t)i * HD_, NKV_);

        // scores = scale * q @ k^T (batched over B*NH)
        k_scores<<<dim3(L_ / 128, L_ / 128, B_ * NH_), 256>>>(q_, k_, sc_, scale);

        // masked softmax (even layers: sliding window)
        k_softmax<<<B_ * NH_ * L_, 256>>>(sc_, am, (i % 2 == 0) ? 1 : 0);

        // o = attn @ v
        k_attnv<<<dim3(HD_ / 128, L_ / 128, B_ * NH_), 256>>>(sc_, v_, o_);

        // h = h + o @ Wo
        k_gemm_nn_acc<<<dim3(HID_ / 128, MT_ / 128), 256>>>(
            o_, NH_ * HD_, wo_i, HID_, h_, HID_, NH_ * HD_);

        // post-attn norm + MLP
        k_rmsnorm<<<MT_, 256>>>(h_, w_post + (size_t)i * HID_, hn_);
        k_gemm_nn<<<dim3(INT_ / 128, MT_ / 128), 256>>>(
            hn_, HID_, wg_i, INT_, gate_, INT_, HID_);
        k_gemm_nn<<<dim3(INT_ / 128, MT_ / 128), 256>>>(
            hn_, HID_, wu_i, INT_, up_, INT_, HID_);
        k_silu_mul<<<(MT_ * INT_) / 256, 256>>>(gate_, up_, MT_ * INT_);
        // h = h + act @ Wd
        k_gemm_nn_acc<<<dim3(HID_ / 128, MT_ / 128), 256>>>(
            gate_, INT_, wd_i, HID_, h_, HID_, INT_);
    }

    // final norm -> out
    k_rmsnorm<<<MT_, 256>>>(h_, w_final, out);
}

// round 13
// speedup vs baseline: 2.4919x; 1.0540x over previous
#include <cuda_runtime.h>
#include <cuda_bf16.h>
#include <math.h>
#include <stdint.h>

#define B_ 2
#define L_ 1024
#define TXT_ 1024
#define HID_ 2048
#define INT_ 6144
#define NH_ 16
#define NKV_ 8
#define HD_ 128
#define NL_ 8
#define SW_ 128
#define MT_ (B_*L_)
#define EPS_ 1e-6f
#define NREP_ 2

typedef __nv_bfloat16 bf16;
typedef unsigned int u32;

// ---- packed weight layout (u32 = bf16 k-pair), per layer: [QKV][O][GU][D] ----
#define PZ_EMB  (512ull*2048ull)
#define PZ_QKV  (1024ull*4096ull)
#define PZ_O    (1024ull*2048ull)
#define PZ_GU   (1024ull*12288ull)
#define PZ_D    (3072ull*2048ull)
#define PZ_LAYER (PZ_QKV + PZ_O + PZ_GU + PZ_D)
#define WP_TOTAL (PZ_EMB + 8ull*PZ_LAYER)

// ---- scratch ----
__device__ __align__(16) float g_h   [(size_t)MT_*HID_];
__device__ __align__(16) float g_qkv [(size_t)MT_*4096];
__device__ __align__(16) float g_gu  [(size_t)MT_*12288];
__device__ __align__(16) float g_sc  [(size_t)B_*NH_*L_*L_];
__device__ __align__(16) u32  g_wphi [WP_TOTAL];
__device__ __align__(16) u32  g_wplo [WP_TOTAL];
__device__ __align__(16) bf16 g_xhi  [(size_t)MT_*TXT_];
__device__ __align__(16) bf16 g_xlo  [(size_t)MT_*TXT_];
__device__ __align__(16) bf16 g_hnhi [(size_t)MT_*HID_];
__device__ __align__(16) bf16 g_hnlo [(size_t)MT_*HID_];
__device__ __align__(16) bf16 g_qhi  [(size_t)MT_*2048];
__device__ __align__(16) bf16 g_qlo  [(size_t)MT_*2048];
__device__ __align__(16) u32  g_kphi [16ull*64*L_];
__device__ __align__(16) u32  g_kplo [16ull*64*L_];
__device__ __align__(16) u32  g_vphi [16ull*512*128];
__device__ __align__(16) u32  g_vplo [16ull*512*128];
__device__ __align__(16) bf16 g_schi [(size_t)B_*NH_*L_*L_];
__device__ __align__(16) bf16 g_sclo [(size_t)B_*NH_*L_*L_];
__device__ __align__(16) bf16 g_ohi  [(size_t)MT_*2048];
__device__ __align__(16) bf16 g_olo  [(size_t)MT_*2048];
__device__ __align__(16) bf16 g_achi [(size_t)MT_*INT_];
__device__ __align__(16) bf16 g_aclo [(size_t)MT_*INT_];

// ---- helpers ----
__device__ __forceinline__ u32 smem_u32(const void* p){
    u32 a; asm("{ .reg .u64 t; cvta.to.shared.u64 t, %1; cvt.u32.u64 %0, t; }":"=r"(a):"l"(p)); return a;
}
__device__ __forceinline__ u32 pack2(bf16 a, bf16 b){
    return (u32)__bfloat16_as_ushort(a) | ((u32)__bfloat16_as_ushort(b)<<16);
}
__device__ __forceinline__ void split_pack(float v0, float v1, u32& hi, u32& lo){
    bf16 h0=__float2bfloat16(v0), h1=__float2bfloat16(v1);
    hi = pack2(h0,h1);
    lo = pack2(__float2bfloat16(v0-__bfloat162float(h0)), __float2bfloat16(v1-__bfloat162float(h1)));
}
__device__ __forceinline__ void mma_bf16(float& d0,float& d1,float& d2,float& d3,
    u32 a0,u32 a1,u32 a2,u32 a3,u32 b0,u32 b1)
{
    asm volatile("mma.sync.aligned.m16n8k16.row.col.f32.bf16.bf16.f32 "
        "{%0,%1,%2,%3}, {%4,%5,%6,%7}, {%8,%9}, {%0,%1,%2,%3};\n"
        : "+f"(d0),"+f"(d1),"+f"(d2),"+f"(d3)
        : "r"(a0),"r"(a1),"r"(a2),"r"(a3),"r"(b0),"r"(b1));
}
__device__ __forceinline__ void cp16(u32 dst, const void* src){
    asm volatile("cp.async.ca.shared.global [%0], [%1], 16;"::"r"(dst),"l"(src):"memory");
}
#define CP_COMMIT() asm volatile("cp.async.commit_group;":::"memory")
#define CP_WAIT2()  asm volatile("cp.async.wait_group 2;":::"memory")

// ================ GEMM body: C[128,128] tile of A[M,K] @ B[N,K]^T ================
// A: planar bf16 hi/lo, K contiguous (lda = row stride in elems).
// B: packed u32 hi/lo, layout [K/2][PN] (k-pair in u32, n contiguous).
// 4-stage cp.async pipeline, BK=16, 256 threads, 8 warps (4x2), warp tile 32x64.
// EPI: 0 = C := scale*acc  1 = C += acc  2 = C := acc + bias  3 = bf16 split out (Ohi/Olo)
#define AS_STR 12
#define BS_STR 136
#define STG_U32 5248                 // 2*128*12 + 2*8*136
#define SMEM_BYTES (4*STG_U32*4)     // 83968

template<int EPI>
__device__ __forceinline__ void gbody(
    const bf16* __restrict__ Ahi, const bf16* __restrict__ Alo, int lda,
    const u32* __restrict__ BPhi, const u32* __restrict__ BPlo, int PN,
    float* __restrict__ C, bf16* __restrict__ Ohi, bf16* __restrict__ Olo, int ldc,
    int m0, int n0, int kbeg, int kend, const float* __restrict__ bias, float scale)
{
    extern __shared__ __align__(16) u32 dynsm[];
    const u32 sb = smem_u32(dynsm);
    const int tid=threadIdx.x, lane=tid&31, warp=tid>>5;
    const int wm=(warp>>1)*32, wn=(warp&1)*64, g=lane>>2, t=lane&3;
    const int nslab = (kend-kbeg)>>4;

    float acc[2][8][4];
#pragma unroll
    for(int mi=0;mi<2;mi++)
#pragma unroll
        for(int ni=0;ni<8;ni++)
#pragma unroll
            for(int r=0;r<4;r++) acc[mi][ni][r]=0.f;

    const int arow = tid>>1, ach = tid&1;      // A: 128 rows x 2 chunks(16B)
    const int brow = tid>>5, bch = tid&31;     // B: 8 k2-rows x 32 chunks

    auto load_stage = [&](int s){
        int st = s & 3;
        u32 base = sb + (u32)(st*STG_U32)*4u;
        int k0 = kbeg + s*16;
        size_t ga = (size_t)(m0+arow)*lda + k0 + ach*8;
        cp16(base + (u32)(arow*AS_STR + ach*4)*4u,          Ahi + ga);
        cp16(base + (u32)(1536 + arow*AS_STR + ach*4)*4u,   Alo + ga);
        size_t kk2 = (size_t)((kbeg>>1) + s*8 + brow);
        size_t gb = kk2*PN + n0 + bch*4;
        cp16(base + (u32)(3072 + brow*BS_STR + bch*4)*4u,   BPhi + gb);
        cp16(base + (u32)(4160 + brow*BS_STR + bch*4)*4u,   BPlo + gb);
    };

    for (int p=0;p<3;p++){ if (p<nslab) load_stage(p); CP_COMMIT(); }

    for (int s=0;s<nslab;s++){
        CP_WAIT2();
        __syncthreads();
        if (s+3<nslab) load_stage(s+3);
        CP_COMMIT();

        int st = s & 3;
        const u32* As0 = dynsm + st*STG_U32;
        const u32* As1 = As0 + 1536;
        const u32* Bs0 = As0 + 3072;
        const u32* Bs1 = As0 + 4160;

        u32 ah[2][4], al[2][4];
#pragma unroll
        for(int mi=0;mi<2;mi++){
            int mb=wm+mi*16;
#pragma unroll
            for(int q=0;q<2;q++)
#pragma unroll
                for(int rr=0;rr<2;rr++){
                    int idx=(mb+g+rr*8)*AS_STR+t+q*4;
                    ah[mi][q*2+rr]=As0[idx]; al[mi][q*2+rr]=As1[idx];
                }
        }
#pragma unroll
        for(int ni=0;ni<8;ni++){
            int nc=wn+ni*8+g;
            u32 bh0=Bs0[t*BS_STR+nc], bh1=Bs0[(t+4)*BS_STR+nc];
            u32 bl0=Bs1[t*BS_STR+nc], bl1=Bs1[(t+4)*BS_STR+nc];
#pragma unroll
            for(int mi=0;mi<2;mi++){
                mma_bf16(acc[mi][ni][0],acc[mi][ni][1],acc[mi][ni][2],acc[mi][ni][3],
                         ah[mi][0],ah[mi][1],ah[mi][2],ah[mi][3],bl0,bl1);
                mma_bf16(acc[mi][ni][0],acc[mi][ni][1],acc[mi][ni][2],acc[mi][ni][3],
                         al[mi][0],al[mi][1],al[mi][2],al[mi][3],bh0,bh1);
                mma_bf16(acc[mi][ni][0],acc[mi][ni][1],acc[mi][ni][2],acc[mi][ni][3],
                         ah[mi][0],ah[mi][1],ah[mi][2],ah[mi][3],bh0,bh1);
            }
        }
    }

    // ---- epilogue ----
#pragma unroll
    for(int mi=0;mi<2;mi++){
        int row0=m0+wm+mi*16+g;
#pragma unroll
        for(int ni=0;ni<8;ni++){
            int col=n0+wn+ni*8+2*t;
            float vx0=acc[mi][ni][0]*scale, vy0=acc[mi][ni][1]*scale;
            float vx1=acc[mi][ni][2]*scale, vy1=acc[mi][ni][3]*scale;
            if (EPI==2){ vx0+=bias[col]; vy0+=bias[col+1]; vx1+=bias[col]; vy1+=bias[col+1]; }
            if (EPI==3){
                *(u32*)&Ohi[(size_t)row0*ldc+col] = pack2(__float2bfloat16(vx0),__float2bfloat16(vy0));
                *(u32*)&Olo[(size_t)row0*ldc+col] = pack2(
                    __float2bfloat16(vx0-__bfloat162float(__float2bfloat16(vx0))),
                    __float2bfloat16(vy0-__bfloat162float(__float2bfloat16(vy0))));
                *(u32*)&Ohi[(size_t)(row0+8)*ldc+col] = pack2(__float2bfloat16(vx1),__float2bfloat16(vy1));
                *(u32*)&Olo[(size_t)(row0+8)*ldc+col] = pack2(
                    __float2bfloat16(vx1-__bfloat162float(__float2bfloat16(vx1))),
                    __float2bfloat16(vy1-__bfloat162float(__float2bfloat16(vy1))));
            } else {
                float2* cp=(float2*)&C[(size_t)row0*ldc+col];
                float2 v; v.x=vx0; v.y=vy0;
                if (EPI==1){ float2 p=*cp; v.x+=p.x; v.y+=p.y; }
                *cp=v;
                cp=(float2*)&C[(size_t)(row0+8)*ldc+col];
                v.x=vx1; v.y=vy1;
                if (EPI==1){ float2 p=*cp; v.x+=p.x; v.y+=p.y; }
                *cp=v;
            }
        }
    }
}

template<int EPI>
__global__ void __launch_bounds__(256,2) k_dense(
    const bf16* Ahi, const bf16* Alo, int lda,
    const u32* BPhi, const u32* BPlo, int PN,
    float* C, int ldc, int K, const float* bias)
{
    gbody<EPI>(Ahi,Alo,lda,BPhi,BPlo,PN,C,nullptr,nullptr,ldc,
               blockIdx.y*128, blockIdx.x*128, 0, K, bias, 1.f);
}

__global__ void __launch_bounds__(256,2) k_scores(
    const bf16* qhi, const bf16* qlo, const u32* kphi, const u32* kplo,
    float* sc, float scale, int sliding)
{
    int z=blockIdx.z, b=z/NH_, h=z%NH_, kv=h/NREP_;
    int m0=blockIdx.y*128, n0=blockIdx.x*128;
    if (sliding && (n0 <= m0-256 || n0 >= m0+256)) return;
    size_t ao = (size_t)b*L_*2048 + (size_t)h*HD_;
    size_t bo = (size_t)(b*NKV_+kv)*64*L_;
    gbody<0>(qhi+ao, qlo+ao, 2048, kphi+bo, kplo+bo, L_,
             sc + (size_t)z*L_*L_, nullptr, nullptr, L_,
             m0, n0, 0, HD_, nullptr, scale);
}

__global__ void __launch_bounds__(256,2) k_attnv(
    const bf16* schi, const bf16* sclo, const u32* vphi, const u32* vplo,
    bf16* ohi, bf16* olo, int sliding)
{
    int z=blockIdx.z, b=z/NH_, h=z%NH_, kv=h/NREP_;
    int m0=blockIdx.y*128;
    int kb=0, ke=L_;
    if (sliding){ kb = (m0>=128)? m0-128 : 0; ke = (m0+256<=L_)? m0+256 : L_; }
    size_t ao = (size_t)z*L_*L_;
    size_t bo = (size_t)(b*NKV_+kv)*512*128;
    size_t oo = (size_t)b*L_*2048 + (size_t)h*HD_;
    gbody<3>(schi+ao, sclo+ao, L_, vphi+bo, vplo+bo, 128,
             nullptr, ohi+oo, olo+oo, 2048,
             m0, 0, kb, ke, nullptr, 1.f);
}

// ================ weight pack: W[K,N] f32 -> [K/2][PNout] u32 hi/lo at coloff ================
__global__ void __launch_bounds__(256) k_wpack(const float* __restrict__ W, int K, int N,
    u32* __restrict__ Phi, u32* __restrict__ Plo, int PNout, int coloff)
{
    int idx = blockIdx.x*256 + threadIdx.x;
    int tot = (K>>1)*N;
    if (idx >= tot) return;
    int k2 = idx / N, n = idx % N;
    float v0 = W[(size_t)(2*k2)*N + n], v1 = W[(size_t)(2*k2+1)*N + n];
    u32 hi, lo; split_pack(v0, v1, hi, lo);
    size_t o = (size_t)k2*PNout + coloff + n;
    Phi[o]=hi; Plo[o]=lo;
}

// ================ elementwise ================
__global__ void __launch_bounds__(256) k_split(const float* __restrict__ x,
    bf16* __restrict__ hi, bf16* __restrict__ lo, int n)
{
    int i = blockIdx.x*256+threadIdx.x;
    if (i<n){ float v=x[i]; bf16 h=__float2bfloat16(v);
        hi[i]=h; lo[i]=__float2bfloat16(v-__bfloat162float(h)); }
}
__global__ void __launch_bounds__(256) k_rmsnorm_split(const float* __restrict__ x,
    const float* __restrict__ w, bf16* __restrict__ hi, bf16* __restrict__ lo)
{
    int row=blockIdx.x; const float* xr=x+(size_t)row*HID_;
    int t=threadIdx.x; float ss=0.f;
    for(int j=t;j<HID_;j+=256){ float v=xr[j]; ss+=v*v; }
    __shared__ float red[256]; red[t]=ss; __syncthreads();
    for(int s=128;s>0;s>>=1){ if(t<s) red[t]+=red[t+s]; __syncthreads(); }
    float rs=rsqrtf(red[0]/(float)HID_+EPS_);
    for(int j=t;j<HID_;j+=256){
        float v=w[j]*xr[j]*rs; bf16 h=__float2bfloat16(v);
        size_t o=(size_t)row*HID_+j; hi[o]=h; lo[o]=__float2bfloat16(v-__bfloat162float(h));
    }
}
__global__ void __launch_bounds__(256) k_rmsnorm(const float* __restrict__ x,
    const float* __restrict__ w, float* __restrict__ y)
{
    int row=blockIdx.x; const float* xr=x+(size_t)row*HID_;
    float* yr=y+(size_t)row*HID_;
    int t=threadIdx.x; float ss=0.f;
    for(int j=t;j<HID_;j+=256){ float v=xr[j]; ss+=v*v; }
    __shared__ float red[256]; red[t]=ss; __syncthreads();
    for(int s=128;s>0;s>>=1){ if(t<s) red[t]+=red[t+s]; __syncthreads(); }
    float rs=rsqrtf(red[0]/(float)HID_+EPS_);
    for(int j=t;j<HID_;j+=256) yr[j]=w[j]*xr[j]*rs;
}
__global__ void __launch_bounds__(256) k_silu_split(const float* __restrict__ gu,
    bf16* __restrict__ hi, bf16* __restrict__ lo)
{
    int idx = blockIdx.x*256+threadIdx.x;   // over MT*INT
    int row = idx / INT_, j = idx % INT_;
    float gv = gu[(size_t)row*12288 + j];
    float uv = gu[(size_t)row*12288 + 6144 + j];
    float v = gv/(1.f+expf(-gv))*uv;
    bf16 h=__float2bfloat16(v);
    hi[idx]=h; lo[idx]=__float2bfloat16(v-__bfloat162float(h));
}

// q rope: read g_qkv q-section, write planar hi/lo
__global__ void __launch_bounds__(128) k_qrope(const float* __restrict__ qkv,
    const float* __restrict__ w, bf16* __restrict__ qhi, bf16* __restrict__ qlo)
{
    int idx=blockIdx.x, head=idx%NH_, tok=idx/NH_, pos=tok%L_;
    int d=threadIdx.x;
    float v = qkv[(size_t)tok*4096 + head*128 + d];
    __shared__ float sh[128];
    sh[d]=v*v; __syncthreads();
    for(int s=64;s>0;s>>=1){ if(d<s) sh[d]+=sh[d+s]; __syncthreads(); }
    float rs=rsqrtf(sh[0]/(float)HD_+EPS_);
    __syncthreads();
    float xn=w[d]*v*rs;
    sh[d]=xn; __syncthreads();
    float rot=(d<64)? -sh[d+64] : sh[d-64];
    int half=d&63;
    float inv=expf(-(2.f*(float)half/(float)HD_)*13.815510557964274f);
    float ang=(float)pos*inv;
    float val = xn*cosf(ang)+rot*sinf(ang);
    bf16 h=__float2bfloat16(val);
    size_t o=(size_t)tok*2048 + head*128 + d;
    qhi[o]=h; qlo[o]=__float2bfloat16(val-__bfloat162float(h));
}

// k rope: read g_qkv k-section, write packed [b*8+kv][HD/2][L] u32 hi/lo
__global__ void __launch_bounds__(128) k_krope(const float* __restrict__ qkv,
    const float* __restrict__ w, u32* __restrict__ kphi, u32* __restrict__ kplo)
{
    int idx=blockIdx.x, kv=idx%NKV_, tok=idx/NKV_, pos=tok%L_;
    int b=tok/L_, j=tok%L_;
    int d=threadIdx.x;
    float v = qkv[(size_t)tok*4096 + 2048 + kv*128 + d];
    __shared__ float sh[128];
    sh[d]=v*v; __syncthreads();
    for(int s=64;s>0;s>>=1){ if(d<s) sh[d]+=sh[d+s]; __syncthreads(); }
    float rs=rsqrtf(sh[0]/(float)HD_+EPS_);
    __syncthreads();
    float xn=w[d]*v*rs;
    sh[d]=xn; __syncthreads();
    float rot=(d<64)? -sh[d+64] : sh[d-64];
    int half=d&63;
    float inv=expf(-(2.f*(float)half/(float)HD_)*13.815510557964274f);
    float ang=(float)pos*inv;
    float val = xn*cosf(ang)+rot*sinf(ang);
    __syncthreads();
    sh[d]=val; __syncthreads();
    if (d<64){
        u32 hi, lo; split_pack(sh[2*d], sh[2*d+1], hi, lo);
        size_t o = ((size_t)(b*NKV_+kv)*64 + d)*L_ + j;
        kphi[o]=hi; kplo[o]=lo;
    }
}

// v pack: g_qkv v-section -> packed token-pairs [b*8+kv][L/2][HD] u32 hi/lo
__global__ void __launch_bounds__(256) k_vpack(const float* __restrict__ qkv,
    u32* __restrict__ vphi, u32* __restrict__ vplo)
{
    int idx = blockIdx.x*256+threadIdx.x;        // 16*512*128
    int bk = idx / (512*128), r = idx % (512*128);
    int j2 = r / 128, d = r % 128;
    int b = bk/NKV_, kv = bk%NKV_;
    size_t s0 = ((size_t)(b*L_ + 2*j2))*4096 + 3072 + kv*128 + d;
    float v0 = qkv[s0], v1 = qkv[s0 + 4096];
    u32 hi, lo; split_pack(v0, v1, hi, lo);
    vphi[idx]=hi; vplo[idx]=lo;
}

// softmax: read fp32 scores, write bf16 hi/lo planar
__global__ void __launch_bounds__(256) k_softmax(const float* __restrict__ sc,
    bf16* __restrict__ shi, bf16* __restrict__ slo, const int* __restrict__ am, int sliding)
{
    int row=blockIdx.x, i=row%L_, b=row/(NH_*L_);
    const float* r=sc+(size_t)row*L_;
    const int* amr=am+(size_t)b*L_;
    int t=threadIdx.x;
    float4 v4=*(const float4*)&r[t*4];
    float vals[4]={v4.x,v4.y,v4.z,v4.w};
    bool keep[4]; float mx=-INFINITY;
#pragma unroll
    for(int q=0;q<4;q++){
        int j=t*4+q, dj=i-j; if(dj<0)dj=-dj;
        keep[q]=(amr[j]!=0)&&(!sliding||dj<=SW_);
        if(!keep[q]) vals[q]=-INFINITY;
        mx=fmaxf(mx,vals[q]);
    }
    __shared__ float red[256];
    red[t]=mx; __syncthreads();
    for(int s=128;s>0;s>>=1){ if(t<s) red[t]=fmaxf(red[t],red[t+s]); __syncthreads(); }
    float rm=red[0]; __syncthreads();
    float e[4], ssum=0.f;
#pragma unroll
    for(int q=0;q<4;q++){ e[q]=keep[q]?expf(vals[q]-rm):0.f; ssum+=e[q]; }
    red[t]=ssum; __syncthreads();
    for(int s=128;s>0;s>>=1){ if(t<s) red[t]+=red[t+s]; __syncthreads(); }
    float tot=red[0];
    float inv=(tot>0.f)?(1.f/tot):0.f;
    u32* oh = (u32*)(shi + (size_t)row*L_) + t*2;
    u32* ol = (u32*)(slo + (size_t)row*L_) + t*2;
    u32 h0,l0,h1,l1;
    split_pack(e[0]*inv, e[1]*inv, h0, l0);
    split_pack(e[2]*inv, e[3]*inv, h1, l1);
    oh[0]=h0; oh[1]=h1; ol[0]=l0; ol[1]=l1;
}

// ================ host driver ================
extern "C" void kernel_launch(void* const* d_in, const int* in_sizes, int n_in,
                              void* d_out, int out_size)
{
    const float* x       = (const float*)d_in[0];
    const int*   am      = (const int*)  d_in[1];
    const float* W_embed = (const float*)d_in[2];
    const float* b_embed = (const float*)d_in[3];
    const float* Wq      = (const float*)d_in[4];
    const float* Wk      = (const float*)d_in[5];
    const float* Wv      = (const float*)d_in[6];
    const float* Wo      = (const float*)d_in[7];
    const float* w_in_ln = (const float*)d_in[8];
    const float* w_post  = (const float*)d_in[9];
    const float* w_qn    = (const float*)d_in[10];
    const float* w_kn    = (const float*)d_in[11];
    const float* Wg      = (const float*)d_in[12];
    const float* Wu      = (const float*)d_in[13];
    const float* Wd      = (const float*)d_in[14];
    const float* w_final = (const float*)d_in[15];
    float* out = (float*)d_out;

    float *h_, *qkv_, *gu_, *sc_;
    u32 *wphi, *wplo, *kphi, *kplo, *vphi, *vplo;
    bf16 *xhi,*xlo,*hnhi,*hnlo,*qhi,*qlo,*schi,*sclo,*ohi,*olo,*achi,*aclo;
    cudaGetSymbolAddress((void**)&h_, g_h);      cudaGetSymbolAddress((void**)&qkv_, g_qkv);
    cudaGetSymbolAddress((void**)&gu_, g_gu);    cudaGetSymbolAddress((void**)&sc_, g_sc);
    cudaGetSymbolAddress((void**)&wphi, g_wphi); cudaGetSymbolAddress((void**)&wplo, g_wplo);
    cudaGetSymbolAddress((void**)&xhi, g_xhi);   cudaGetSymbolAddress((void**)&xlo, g_xlo);
    cudaGetSymbolAddress((void**)&hnhi, g_hnhi); cudaGetSymbolAddress((void**)&hnlo, g_hnlo);
    cudaGetSymbolAddress((void**)&qhi, g_qhi);   cudaGetSymbolAddress((void**)&qlo, g_qlo);
    cudaGetSymbolAddress((void**)&kphi, g_kphi); cudaGetSymbolAddress((void**)&kplo, g_kplo);
    cudaGetSymbolAddress((void**)&vphi, g_vphi); cudaGetSymbolAddress((void**)&vplo, g_vplo);
    cudaGetSymbolAddress((void**)&schi, g_schi); cudaGetSymbolAddress((void**)&sclo, g_sclo);
    cudaGetSymbolAddress((void**)&ohi, g_ohi);   cudaGetSymbolAddress((void**)&olo, g_olo);
    cudaGetSymbolAddress((void**)&achi, g_achi); cudaGetSymbolAddress((void**)&aclo, g_aclo);

    cudaFuncSetAttribute(k_dense<0>, cudaFuncAttributeMaxDynamicSharedMemorySize, SMEM_BYTES);
    cudaFuncSetAttribute(k_dense<1>, cudaFuncAttributeMaxDynamicSharedMemorySize, SMEM_BYTES);
    cudaFuncSetAttribute(k_dense<2>, cudaFuncAttributeMaxDynamicSharedMemorySize, SMEM_BYTES);
    cudaFuncSetAttribute(k_scores,   cudaFuncAttributeMaxDynamicSharedMemorySize, SMEM_BYTES);
    cudaFuncSetAttribute(k_attnv,    cudaFuncAttributeMaxDynamicSharedMemorySize, SMEM_BYTES);

    const float scale = 0.08838834764831845f;

    // ---- pack weights (per call; deterministic) ----
    k_wpack<<<(512*2048+255)/256, 256>>>(W_embed, 1024, 2048, wphi, wplo, 2048, 0);
    for (int i=0;i<NL_;i++){
        size_t lb = PZ_EMB + (size_t)i*PZ_LAYER;
        size_t oqkv=lb, oo=oqkv+PZ_QKV, ogu=oo+PZ_O, od=ogu+PZ_GU;
        k_wpack<<<(1024*2048+255)/256, 256>>>(Wq+(size_t)i*2048*2048, 2048, 2048, wphi+oqkv, wplo+oqkv, 4096, 0);
        k_wpack<<<(1024*1024+255)/256, 256>>>(Wk+(size_t)i*2048*1024, 2048, 1024, wphi+oqkv, wplo+oqkv, 4096, 2048);
        k_wpack<<<(1024*1024+255)/256, 256>>>(Wv+(size_t)i*2048*1024, 2048, 1024, wphi+oqkv, wplo+oqkv, 4096, 3072);
        k_wpack<<<(1024*2048+255)/256, 256>>>(Wo+(size_t)i*2048*2048, 2048, 2048, wphi+oo, wplo+oo, 2048, 0);
        k_wpack<<<(1024*6144+255)/256, 256>>>(Wg+(size_t)i*2048*6144, 2048, 6144, wphi+ogu, wplo+ogu, 12288, 0);
        k_wpack<<<(1024*6144+255)/256, 256>>>(Wu+(size_t)i*2048*6144, 2048, 6144, wphi+ogu, wplo+ogu, 12288, 6144);
        k_wpack<<<(3072*2048+255)/256, 256>>>(Wd+(size_t)i*6144*2048, 6144, 2048, wphi+od, wplo+od, 2048, 0);
    }

    // ---- embed ----
    k_split<<<(MT_*TXT_)/256, 256>>>(x, xhi, xlo, MT_*TXT_);
    k_dense<2><<<dim3(16,16), 256, SMEM_BYTES>>>(xhi, xlo, 1024, wphi, wplo, 2048, h_, 2048, 1024, b_embed);

    for (int i=0;i<NL_;i++){
        size_t lb = PZ_EMB + (size_t)i*PZ_LAYER;
        size_t oqkv=lb, oo=oqkv+PZ_QKV, ogu=oo+PZ_O, od=ogu+PZ_GU;
        int sl = (i%2==0) ? 1 : 0;

        k_rmsnorm_split<<<MT_, 256>>>(h_, w_in_ln+(size_t)i*HID_, hnhi, hnlo);
        k_dense<0><<<dim3(32,16), 256, SMEM_BYTES>>>(hnhi, hnlo, 2048, wphi+oqkv, wplo+oqkv, 4096, qkv_, 4096, 2048, nullptr);

        k_qrope<<<MT_*NH_, 128>>>(qkv_, w_qn+(size_t)i*HD_, qhi, qlo);
        k_krope<<<MT_*NKV_, 128>>>(qkv_, w_kn+(size_t)i*HD_, kphi, kplo);
        k_vpack<<<(16*512*128)/256, 256>>>(qkv_, vphi, vplo);

        k_scores<<<dim3(8,8,32), 256, SMEM_BYTES>>>(qhi, qlo, kphi, kplo, sc_, scale, sl);
        k_softmax<<<B_*NH_*L_, 256>>>(sc_, schi, sclo, am, sl);
        k_attnv<<<dim3(1,8,32), 256, SMEM_BYTES>>>(schi, sclo, vphi, vplo, ohi, olo, sl);

        k_dense<1><<<dim3(16,16), 256, SMEM_BYTES>>>(ohi, olo, 2048, wphi+oo, wplo+oo, 2048, h_, 2048, 2048, nullptr);

        k_rmsnorm_split<<<MT_, 256>>>(h_, w_post+(size_t)i*HID_, hnhi, hnlo);
        k_dense<0><<<dim3(96,16), 256, SMEM_BYTES>>>(hnhi, hnlo, 2048, wphi+ogu, wplo+ogu, 12288, gu_, 12288, 2048, nullptr);
        k_silu_split<<<(MT_*INT_)/256, 256>>>(gu_, achi, aclo);
        k_dense<1><<<dim3(16,16), 256, SMEM_BYTES>>>(achi, aclo, 6144, wphi+od, wplo+od, 2048, h_, 2048, 6144, nullptr);
    }

    k_rmsnorm<<<MT_, 256>>>(h_, w_final, out);
}

// round 14
// speedup vs baseline: 2.6722x; 1.0724x over previous
#include <cuda_runtime.h>
#include <cuda_bf16.h>
#include <math.h>
#include <stdint.h>

#define B_ 2
#define L_ 1024
#define TXT_ 1024
#define HID_ 2048
#define INT_ 6144
#define NH_ 16
#define NKV_ 8
#define HD_ 128
#define NL_ 8
#define SW_ 128
#define MT_ (B_*L_)
#define EPS_ 1e-6f
#define NREP_ 2

typedef __nv_bfloat16 bf16;
typedef unsigned int u32;

// ---- split weights: planar bf16 hi/lo, [N][K] K-major per matrix ----
#define WZ_EMB (2048ull*1024ull)
#define WZ_QKV (4096ull*2048ull)
#define WZ_O   (2048ull*2048ull)
#define WZ_GU  (12288ull*2048ull)
#define WZ_D   (2048ull*6144ull)
#define WZ_LAYER (WZ_QKV + WZ_O + WZ_GU + WZ_D)
#define WB_TOTAL (WZ_EMB + 8ull*WZ_LAYER)

// ---- scratch ----
__device__ __align__(16) float g_h   [(size_t)MT_*HID_];
__device__ __align__(16) float g_qkv [(size_t)MT_*4096];
__device__ __align__(16) float g_gu  [(size_t)MT_*12288];
__device__ __align__(16) float g_sc  [(size_t)B_*NH_*L_*L_];
__device__ __align__(16) bf16 g_whi  [WB_TOTAL];
__device__ __align__(16) bf16 g_wlo  [WB_TOTAL];
__device__ __align__(16) bf16 g_xhi  [(size_t)MT_*TXT_];
__device__ __align__(16) bf16 g_xlo  [(size_t)MT_*TXT_];
__device__ __align__(16) bf16 g_hnhi [(size_t)MT_*HID_];
__device__ __align__(16) bf16 g_hnlo [(size_t)MT_*HID_];
__device__ __align__(16) bf16 g_qhi  [(size_t)MT_*2048];
__device__ __align__(16) bf16 g_qlo  [(size_t)MT_*2048];
__device__ __align__(16) bf16 g_khi  [16ull*L_*HD_];
__device__ __align__(16) bf16 g_klo  [16ull*L_*HD_];
__device__ __align__(16) bf16 g_vthi [16ull*HD_*L_];
__device__ __align__(16) bf16 g_vtlo [16ull*HD_*L_];
__device__ __align__(16) bf16 g_schi [(size_t)B_*NH_*L_*L_];
__device__ __align__(16) bf16 g_sclo [(size_t)B_*NH_*L_*L_];
__device__ __align__(16) bf16 g_ohi  [(size_t)MT_*2048];
__device__ __align__(16) bf16 g_olo  [(size_t)MT_*2048];
__device__ __align__(16) bf16 g_achi [(size_t)MT_*INT_];
__device__ __align__(16) bf16 g_aclo [(size_t)MT_*INT_];

// ---- helpers ----
__device__ __forceinline__ u32 smem_u32(const void* p){
    u32 a; asm("{ .reg .u64 t; cvta.to.shared.u64 t, %1; cvt.u32.u64 %0, t; }":"=r"(a):"l"(p)); return a;
}
__device__ __forceinline__ u32 pack2(bf16 a, bf16 b){
    return (u32)__bfloat16_as_ushort(a) | ((u32)__bfloat16_as_ushort(b)<<16);
}
__device__ __forceinline__ void mma_bf16(float& d0,float& d1,float& d2,float& d3,
    u32 a0,u32 a1,u32 a2,u32 a3,u32 b0,u32 b1)
{
    asm volatile("mma.sync.aligned.m16n8k16.row.col.f32.bf16.bf16.f32 "
        "{%0,%1,%2,%3}, {%4,%5,%6,%7}, {%8,%9}, {%0,%1,%2,%3};\n"
        : "+f"(d0),"+f"(d1),"+f"(d2),"+f"(d3)
        : "r"(a0),"r"(a1),"r"(a2),"r"(a3),"r"(b0),"r"(b1));
}
__device__ __forceinline__ void cp16(u32 dst, const void* src){
    asm volatile("cp.async.ca.shared.global [%0], [%1], 16;"::"r"(dst),"l"(src):"memory");
}
#define CP_COMMIT() asm volatile("cp.async.commit_group;":::"memory")
#define CP_WAIT2()  asm volatile("cp.async.wait_group 2;":::"memory")
#define LDM4(r, a) asm volatile( \
    "ldmatrix.sync.aligned.m8n8.x4.shared.b16 {%0,%1,%2,%3}, [%4];" \
    : "=r"((r)[0]),"=r"((r)[1]),"=r"((r)[2]),"=r"((r)[3]) : "r"(a))

// ================ GEMM body: C[128,128] tile of A[M,K] @ B[N,K]^T ================
// A, B: planar bf16 hi/lo, K contiguous (lda/ldb = row stride in elems).
// Smem per 16-k stage: A 128 rows * 12 u32 * {hi,lo}, B same. 4-stage cp.async.
// 256 threads, 8 warps (4x2), warp tile 32x64. Fragments via ldmatrix.x4.
// EPI: 0 = C := scale*acc  1 = C += acc  2 = C := acc + bias  3 = bf16 split out
#define STG_U32 6144
#define SMEM_BYTES (4*STG_U32*4)   // 98304

template<int EPI>
__device__ __forceinline__ void gbody(
    const bf16* __restrict__ Ahi, const bf16* __restrict__ Alo, int lda,
    const bf16* __restrict__ Bhi, const bf16* __restrict__ Blo, int ldb,
    float* __restrict__ C, bf16* __restrict__ Ohi, bf16* __restrict__ Olo, int ldc,
    int m0, int n0, int kbeg, int kend, const float* __restrict__ bias, float scale)
{
    extern __shared__ __align__(16) u32 dynsm[];
    const u32 sb = smem_u32(dynsm);
    const int tid=threadIdx.x, lane=tid&31, warp=tid>>5;
    const int wm=(warp>>1)*32, wn=(warp&1)*64, g=lane>>2, t=lane&3;
    const int nslab=(kend-kbeg)>>4;

    float acc[2][8][4];
#pragma unroll
    for(int mi=0;mi<2;mi++)
#pragma unroll
        for(int ni=0;ni<8;ni++)
#pragma unroll
            for(int r=0;r<4;r++) acc[mi][ni][r]=0.f;

    const int lrow = tid>>1, lch = tid&1;

    auto load_stage = [&](int s){
        u32 base = sb + (u32)((s&3)*STG_U32)*4u;
        int k0 = kbeg + s*16;
        size_t ga = (size_t)(m0+lrow)*lda + k0 + lch*8;
        u32 da = base + (u32)(lrow*12 + lch*4)*4u;
        cp16(da,           Ahi+ga);
        cp16(da + 6144,    Alo+ga);            // +1536 u32
        size_t gb = (size_t)(n0+lrow)*ldb + k0 + lch*8;
        u32 db = base + 12288u + (u32)(lrow*12 + lch*4)*4u;   // +3072 u32
        cp16(db,           Bhi+gb);
        cp16(db + 6144,    Blo+gb);
    };

    // ldmatrix per-lane byte offsets
    const int sel = lane>>3, lr = lane&7;
    const u32 aoff = (u32)((wm + lr + ((sel&1)<<3))*48 + ((sel>>1)<<4));
    const u32 boff = 12288u + (u32)((wn + lr + ((sel>>1)<<3))*48 + ((sel&1)<<4));

    for (int p=0;p<3;p++){ if(p<nslab) load_stage(p); CP_COMMIT(); }

    for (int s=0;s<nslab;s++){
        CP_WAIT2();
        __syncthreads();
        if (s+3<nslab) load_stage(s+3);
        CP_COMMIT();

        u32 base = sb + (u32)((s&3)*STG_U32)*4u;
        u32 ah[2][4], al[2][4];
#pragma unroll
        for(int mi=0;mi<2;mi++){
            LDM4(ah[mi], base + aoff + mi*768);
            LDM4(al[mi], base + aoff + mi*768 + 6144);
        }
#pragma unroll
        for(int p=0;p<4;p++){
            u32 bh[4], bl[4];
            LDM4(bh, base + boff + p*768);
            LDM4(bl, base + boff + p*768 + 6144);
#pragma unroll
            for(int q=0;q<2;q++){
                int ni=p*2+q;
                u32 b0h=bh[q*2], b1h=bh[q*2+1], b0l=bl[q*2], b1l=bl[q*2+1];
#pragma unroll
                for(int mi=0;mi<2;mi++){
                    mma_bf16(acc[mi][ni][0],acc[mi][ni][1],acc[mi][ni][2],acc[mi][ni][3],
                             ah[mi][0],ah[mi][1],ah[mi][2],ah[mi][3],b0l,b1l);
                    mma_bf16(acc[mi][ni][0],acc[mi][ni][1],acc[mi][ni][2],acc[mi][ni][3],
                             al[mi][0],al[mi][1],al[mi][2],al[mi][3],b0h,b1h);
                    mma_bf16(acc[mi][ni][0],acc[mi][ni][1],acc[mi][ni][2],acc[mi][ni][3],
                             ah[mi][0],ah[mi][1],ah[mi][2],ah[mi][3],b0h,b1h);
                }
            }
        }
    }

    // ---- epilogue ----
#pragma unroll
    for(int mi=0;mi<2;mi++){
        int row0=m0+wm+mi*16+g;
#pragma unroll
        for(int ni=0;ni<8;ni++){
            int col=n0+wn+ni*8+2*t;
            float vx0=acc[mi][ni][0]*scale, vy0=acc[mi][ni][1]*scale;
            float vx1=acc[mi][ni][2]*scale, vy1=acc[mi][ni][3]*scale;
            if (EPI==2){ vx0+=bias[col]; vy0+=bias[col+1]; vx1+=bias[col]; vy1+=bias[col+1]; }
            if (EPI==3){
                bf16 h0=__float2bfloat16(vx0), h1=__float2bfloat16(vy0);
                *(u32*)&Ohi[(size_t)row0*ldc+col] = pack2(h0,h1);
                *(u32*)&Olo[(size_t)row0*ldc+col] = pack2(
                    __float2bfloat16(vx0-__bfloat162float(h0)),
                    __float2bfloat16(vy0-__bfloat162float(h1)));
                bf16 h2=__float2bfloat16(vx1), h3=__float2bfloat16(vy1);
                *(u32*)&Ohi[(size_t)(row0+8)*ldc+col] = pack2(h2,h3);
                *(u32*)&Olo[(size_t)(row0+8)*ldc+col] = pack2(
                    __float2bfloat16(vx1-__bfloat162float(h2)),
                    __float2bfloat16(vy1-__bfloat162float(h3)));
            } else {
                float2* cp=(float2*)&C[(size_t)row0*ldc+col];
                float2 v; v.x=vx0; v.y=vy0;
                if (EPI==1){ float2 p=*cp; v.x+=p.x; v.y+=p.y; }
                *cp=v;
                cp=(float2*)&C[(size_t)(row0+8)*ldc+col];
                v.x=vx1; v.y=vy1;
                if (EPI==1){ float2 p=*cp; v.x+=p.x; v.y+=p.y; }
                *cp=v;
            }
        }
    }
}

template<int EPI>
__global__ void __launch_bounds__(256,2) k_dense(
    const bf16* Ahi, const bf16* Alo, int lda,
    const bf16* Bhi, const bf16* Blo, int ldb,
    float* C, int ldc, int K, const float* bias)
{
    gbody<EPI>(Ahi,Alo,lda,Bhi,Blo,ldb,C,nullptr,nullptr,ldc,
               blockIdx.y*128, blockIdx.x*128, 0, K, bias, 1.f);
}

__global__ void __launch_bounds__(256,2) k_scores(
    const bf16* qhi, const bf16* qlo, const bf16* khi, const bf16* klo,
    float* sc, float scale, int sliding)
{
    int z=blockIdx.z, b=z/NH_, h=z%NH_, kv=h/NREP_;
    int m0=blockIdx.y*128, n0=blockIdx.x*128;
    if (sliding && (n0 <= m0-256 || n0 >= m0+256)) return;
    size_t ao = (size_t)b*L_*2048 + (size_t)h*HD_;
    size_t bo = (size_t)(b*NKV_+kv)*L_*HD_;
    gbody<0>(qhi+ao, qlo+ao, 2048, khi+bo, klo+bo, HD_,
             sc + (size_t)z*L_*L_, nullptr, nullptr, L_,
             m0, n0, 0, HD_, nullptr, scale);
}

__global__ void __launch_bounds__(256,2) k_attnv(
    const bf16* schi, const bf16* sclo, const bf16* vthi, const bf16* vtlo,
    bf16* ohi, bf16* olo, int sliding)
{
    int z=blockIdx.z, b=z/NH_, h=z%NH_, kv=h/NREP_;
    int m0=blockIdx.y*128;
    int kb=0, ke=L_;
    if (sliding){ kb = (m0>=128)? m0-128 : 0; ke = (m0+256<=L_)? m0+256 : L_; }
    size_t ao = (size_t)z*L_*L_;
    size_t bo = (size_t)(b*NKV_+kv)*HD_*L_;
    size_t oo = (size_t)b*L_*2048 + (size_t)h*HD_;
    gbody<3>(schi+ao, sclo+ao, L_, vthi+bo, vtlo+bo, L_,
             nullptr, ohi+oo, olo+oo, 2048,
             m0, 0, kb, ke, nullptr, 1.f);
}

// ================ weight transpose+split: W[K,N] f32 -> planar bf16 hi/lo [rowoff+N][K] ================
__global__ void k_wsplit(const float* __restrict__ W, int K, int N,
    bf16* __restrict__ hi, bf16* __restrict__ lo, int rowoff)
{
    __shared__ float tsm[32][33];
    int n0 = blockIdx.x*32, k0 = blockIdx.y*32;
    int tx = threadIdx.x, ty = threadIdx.y;
#pragma unroll
    for (int i=0;i<4;i++)
        tsm[ty+i*8][tx] = W[(size_t)(k0+ty+i*8)*N + n0+tx];
    __syncthreads();
#pragma unroll
    for (int i=0;i<4;i++){
        float v = tsm[tx][ty+i*8];
        bf16 h = __float2bfloat16(v);
        size_t o = (size_t)(rowoff+n0+ty+i*8)*K + k0+tx;
        hi[o]=h; lo[o]=__float2bfloat16(v-__bfloat162float(h));
    }
}

// ================ elementwise ================
__global__ void __launch_bounds__(256) k_split(const float* __restrict__ x,
    bf16* __restrict__ hi, bf16* __restrict__ lo, int n)
{
    int i = blockIdx.x*256+threadIdx.x;
    if (i<n){ float v=x[i]; bf16 h=__float2bfloat16(v);
        hi[i]=h; lo[i]=__float2bfloat16(v-__bfloat162float(h)); }
}
__global__ void __launch_bounds__(256) k_rmsnorm_split(const float* __restrict__ x,
    const float* __restrict__ w, bf16* __restrict__ hi, bf16* __restrict__ lo)
{
    int row=blockIdx.x; const float* xr=x+(size_t)row*HID_;
    int t=threadIdx.x; float ss=0.f;
    for(int j=t;j<HID_;j+=256){ float v=xr[j]; ss+=v*v; }
    __shared__ float red[256]; red[t]=ss; __syncthreads();
    for(int s=128;s>0;s>>=1){ if(t<s) red[t]+=red[t+s]; __syncthreads(); }
    float rs=rsqrtf(red[0]/(float)HID_+EPS_);
    for(int j=t;j<HID_;j+=256){
        float v=w[j]*xr[j]*rs; bf16 h=__float2bfloat16(v);
        size_t o=(size_t)row*HID_+j; hi[o]=h; lo[o]=__float2bfloat16(v-__bfloat162float(h));
    }
}
__global__ void __launch_bounds__(256) k_rmsnorm(const float* __restrict__ x,
    const float* __restrict__ w, float* __restrict__ y)
{
    int row=blockIdx.x; const float* xr=x+(size_t)row*HID_;
    float* yr=y+(size_t)row*HID_;
    int t=threadIdx.x; float ss=0.f;
    for(int j=t;j<HID_;j+=256){ float v=xr[j]; ss+=v*v; }
    __shared__ float red[256]; red[t]=ss; __syncthreads();
    for(int s=128;s>0;s>>=1){ if(t<s) red[t]+=red[t+s]; __syncthreads(); }
    float rs=rsqrtf(red[0]/(float)HID_+EPS_);
    for(int j=t;j<HID_;j+=256) yr[j]=w[j]*xr[j]*rs;
}
__global__ void __launch_bounds__(256) k_silu_split(const float* __restrict__ gu,
    bf16* __restrict__ hi, bf16* __restrict__ lo)
{
    int idx = blockIdx.x*256+threadIdx.x;   // over MT*INT
    int row = idx / INT_, j = idx % INT_;
    float gv = gu[(size_t)row*12288 + j];
    float uv = gu[(size_t)row*12288 + 6144 + j];
    float v = gv/(1.f+expf(-gv))*uv;
    bf16 h=__float2bfloat16(v);
    hi[idx]=h; lo[idx]=__float2bfloat16(v-__bfloat162float(h));
}

// q rope: planar hi/lo [tok][2048]
__global__ void __launch_bounds__(128) k_qrope(const float* __restrict__ qkv,
    const float* __restrict__ w, bf16* __restrict__ qhi, bf16* __restrict__ qlo)
{
    int idx=blockIdx.x, head=idx%NH_, tok=idx/NH_, pos=tok%L_;
    int d=threadIdx.x;
    float v = qkv[(size_t)tok*4096 + head*128 + d];
    __shared__ float sh[128];
    sh[d]=v*v; __syncthreads();
    for(int s=64;s>0;s>>=1){ if(d<s) sh[d]+=sh[d+s]; __syncthreads(); }
    float rs=rsqrtf(sh[0]/(float)HD_+EPS_);
    __syncthreads();
    float xn=w[d]*v*rs;
    sh[d]=xn; __syncthreads();
    float rot=(d<64)? -sh[d+64] : sh[d-64];
    int half=d&63;
    float inv=expf(-(2.f*(float)half/(float)HD_)*13.815510557964274f);
    float ang=(float)pos*inv;
    float val = xn*cosf(ang)+rot*sinf(ang);
    bf16 h=__float2bfloat16(val);
    size_t o=(size_t)tok*2048 + head*128 + d;
    qhi[o]=h; qlo[o]=__float2bfloat16(val-__bfloat162float(h));
}

// k rope: planar hi/lo [b*8+kv][j][d]  (K-major rows = tokens)
__global__ void __launch_bounds__(128) k_krope(const float* __restrict__ qkv,
    const float* __restrict__ w, bf16* __restrict__ khi, bf16* __restrict__ klo)
{
    int idx=blockIdx.x, kv=idx%NKV_, tok=idx/NKV_, pos=tok%L_;
    int b=tok/L_, j=tok%L_;
    int d=threadIdx.x;
    float v = qkv[(size_t)tok*4096 + 2048 + kv*128 + d];
    __shared__ float sh[128];
    sh[d]=v*v; __syncthreads();
    for(int s=64;s>0;s>>=1){ if(d<s) sh[d]+=sh[d+s]; __syncthreads(); }
    float rs=rsqrtf(sh[0]/(float)HD_+EPS_);
    __syncthreads();
    float xn=w[d]*v*rs;
    sh[d]=xn; __syncthreads();
    float rot=(d<64)? -sh[d+64] : sh[d-64];
    int half=d&63;
    float inv=expf(-(2.f*(float)half/(float)HD_)*13.815510557964274f);
    float ang=(float)pos*inv;
    float val = xn*cosf(ang)+rot*sinf(ang);
    bf16 h=__float2bfloat16(val);
    size_t o = ((size_t)(b*NKV_+kv)*L_ + j)*HD_ + d;
    khi[o]=h; klo[o]=__float2bfloat16(val-__bfloat162float(h));
}

// v transpose+split: qkv v-section [tok][d] -> planar [b*8+kv][d][j]
__global__ void k_vtrans(const float* __restrict__ qkv,
    bf16* __restrict__ vthi, bf16* __restrict__ vtlo)
{
    __shared__ float tsm[32][33];
    int j0 = blockIdx.x*32, d0 = blockIdx.y*32, bk = blockIdx.z;
    int b = bk>>3, kv = bk&7;
    int tx = threadIdx.x, ty = threadIdx.y;
#pragma unroll
    for (int i=0;i<4;i++)
        tsm[ty+i*8][tx] = qkv[(size_t)(b*L_ + j0+ty+i*8)*4096 + 3072 + kv*128 + d0+tx];
    __syncthreads();
#pragma unroll
    for (int i=0;i<4;i++){
        float v = tsm[tx][ty+i*8];
        bf16 h = __float2bfloat16(v);
        size_t o = ((size_t)bk*HD_ + d0+ty+i*8)*L_ + j0+tx;
        vthi[o]=h; vtlo[o]=__float2bfloat16(v-__bfloat162float(h));
    }
}

// softmax: fp32 scores -> bf16 hi/lo planar probs
__global__ void __launch_bounds__(256) k_softmax(const float* __restrict__ sc,
    bf16* __restrict__ shi, bf16* __restrict__ slo, const int* __restrict__ am, int sliding)
{
    int row=blockIdx.x, i=row%L_, b=row/(NH_*L_);
    const float* r=sc+(size_t)row*L_;
    const int* amr=am+(size_t)b*L_;
    int t=threadIdx.x;
    float4 v4=*(const float4*)&r[t*4];
    float vals[4]={v4.x,v4.y,v4.z,v4.w};
    bool keep[4]; float mx=-INFINITY;
#pragma unroll
    for(int q=0;q<4;q++){
        int j=t*4+q, dj=i-j; if(dj<0)dj=-dj;
        keep[q]=(amr[j]!=0)&&(!sliding||dj<=SW_);
        if(!keep[q]) vals[q]=-INFINITY;
        mx=fmaxf(mx,vals[q]);
    }
    __shared__ float red[256];
    red[t]=mx; __syncthreads();
    for(int s=128;s>0;s>>=1){ if(t<s) red[t]=fmaxf(red[t],red[t+s]); __syncthreads(); }
    float rm=red[0]; __syncthreads();
    float e[4], ssum=0.f;
#pragma unroll
    for(int q=0;q<4;q++){ e[q]=keep[q]?expf(vals[q]-rm):0.f; ssum+=e[q]; }
    red[t]=ssum; __syncthreads();
    for(int s=128;s>0;s>>=1){ if(t<s) red[t]+=red[t+s]; __syncthreads(); }
    float tot=red[0];
    float inv=(tot>0.f)?(1.f/tot):0.f;
    u32* oh = (u32*)(shi + (size_t)row*L_) + t*2;
    u32* ol = (u32*)(slo + (size_t)row*L_) + t*2;
#pragma unroll
    for(int q=0;q<2;q++){
        float a0=e[q*2]*inv, a1=e[q*2+1]*inv;
        bf16 h0=__float2bfloat16(a0), h1=__float2bfloat16(a1);
        oh[q]=pack2(h0,h1);
        ol[q]=pack2(__float2bfloat16(a0-__bfloat162float(h0)),
                    __float2bfloat16(a1-__bfloat162float(h1)));
    }
}

// ================ host driver ================
extern "C" void kernel_launch(void* const* d_in, const int* in_sizes, int n_in,
                              void* d_out, int out_size)
{
    const float* x       = (const float*)d_in[0];
    const int*   am      = (const int*)  d_in[1];
    const float* W_embed = (const float*)d_in[2];
    const float* b_embed = (const float*)d_in[3];
    const float* Wq      = (const float*)d_in[4];
    const float* Wk      = (const float*)d_in[5];
    const float* Wv      = (const float*)d_in[6];
    const float* Wo      = (const float*)d_in[7];
    const float* w_in_ln = (const float*)d_in[8];
    const float* w_post  = (const float*)d_in[9];
    const float* w_qn    = (const float*)d_in[10];
    const float* w_kn    = (const float*)d_in[11];
    const float* Wg      = (const float*)d_in[12];
    const float* Wu      = (const float*)d_in[13];
    const float* Wd      = (const float*)d_in[14];
    const float* w_final = (const float*)d_in[15];
    float* out = (float*)d_out;

    float *h_, *qkv_, *gu_, *sc_;
    bf16 *whi,*wlo,*xhi,*xlo,*hnhi,*hnlo,*qhi,*qlo,*khi,*klo,*vthi,*vtlo;
    bf16 *schi,*sclo,*ohi,*olo,*achi,*aclo;
    cudaGetSymbolAddress((void**)&h_, g_h);      cudaGetSymbolAddress((void**)&qkv_, g_qkv);
    cudaGetSymbolAddress((void**)&gu_, g_gu);    cudaGetSymbolAddress((void**)&sc_, g_sc);
    cudaGetSymbolAddress((void**)&whi, g_whi);   cudaGetSymbolAddress((void**)&wlo, g_wlo);
    cudaGetSymbolAddress((void**)&xhi, g_xhi);   cudaGetSymbolAddress((void**)&xlo, g_xlo);
    cudaGetSymbolAddress((void**)&hnhi, g_hnhi); cudaGetSymbolAddress((void**)&hnlo, g_hnlo);
    cudaGetSymbolAddress((void**)&qhi, g_qhi);   cudaGetSymbolAddress((void**)&qlo, g_qlo);
    cudaGetSymbolAddress((void**)&khi, g_khi);   cudaGetSymbolAddress((void**)&klo, g_klo);
    cudaGetSymbolAddress((void**)&vthi, g_vthi); cudaGetSymbolAddress((void**)&vtlo, g_vtlo);
    cudaGetSymbolAddress((void**)&schi, g_schi); cudaGetSymbolAddress((void**)&sclo, g_sclo);
    cudaGetSymbolAddress((void**)&ohi, g_ohi);   cudaGetSymbolAddress((void**)&olo, g_olo);
    cudaGetSymbolAddress((void**)&achi, g_achi); cudaGetSymbolAddress((void**)&aclo, g_aclo);

    cudaFuncSetAttribute(k_dense<0>, cudaFuncAttributeMaxDynamicSharedMemorySize, SMEM_BYTES);
    cudaFuncSetAttribute(k_dense<1>, cudaFuncAttributeMaxDynamicSharedMemorySize, SMEM_BYTES);
    cudaFuncSetAttribute(k_dense<2>, cudaFuncAttributeMaxDynamicSharedMemorySize, SMEM_BYTES);
    cudaFuncSetAttribute(k_scores,   cudaFuncAttributeMaxDynamicSharedMemorySize, SMEM_BYTES);
    cudaFuncSetAttribute(k_attnv,    cudaFuncAttributeMaxDynamicSharedMemorySize, SMEM_BYTES);

    const float scale = 0.08838834764831845f;
    dim3 tb(32,8);

    // ---- weight transpose+split ----
    k_wsplit<<<dim3(2048/32, 1024/32), tb>>>(W_embed, 1024, 2048, whi, wlo, 0);
    for (int i=0;i<NL_;i++){
        size_t lb = WZ_EMB + (size_t)i*WZ_LAYER;
        size_t oqkv=lb, oo=oqkv+WZ_QKV, ogu=oo+WZ_O, od=ogu+WZ_GU;
        k_wsplit<<<dim3(64,64), tb>>>(Wq+(size_t)i*2048*2048, 2048, 2048, whi+oqkv, wlo+oqkv, 0);
        k_wsplit<<<dim3(32,64), tb>>>(Wk+(size_t)i*2048*1024, 2048, 1024, whi+oqkv, wlo+oqkv, 2048);
        k_wsplit<<<dim3(32,64), tb>>>(Wv+(size_t)i*2048*1024, 2048, 1024, whi+oqkv, wlo+oqkv, 3072);
        k_wsplit<<<dim3(64,64), tb>>>(Wo+(size_t)i*2048*2048, 2048, 2048, whi+oo, wlo+oo, 0);
        k_wsplit<<<dim3(192,64), tb>>>(Wg+(size_t)i*2048*6144, 2048, 6144, whi+ogu, wlo+ogu, 0);
        k_wsplit<<<dim3(192,64), tb>>>(Wu+(size_t)i*2048*6144, 2048, 6144, whi+ogu, wlo+ogu, 6144);
        k_wsplit<<<dim3(64,192), tb>>>(Wd+(size_t)i*6144*2048, 6144, 2048, whi+od, wlo+od, 0);
    }

    // ---- embed ----
    k_split<<<(MT_*TXT_)/256, 256>>>(x, xhi, xlo, MT_*TXT_);
    k_dense<2><<<dim3(16,16), 256, SMEM_BYTES>>>(xhi, xlo, 1024, whi, wlo, 1024, h_, 2048, 1024, b_embed);

    for (int i=0;i<NL_;i++){
        size_t lb = WZ_EMB + (size_t)i*WZ_LAYER;
        size_t oqkv=lb, oo=oqkv+WZ_QKV, ogu=oo+WZ_O, od=ogu+WZ_GU;
        int sl = (i%2==0) ? 1 : 0;

        k_rmsnorm_split<<<MT_, 256>>>(h_, w_in_ln+(size_t)i*HID_, hnhi, hnlo);
        k_dense<0><<<dim3(32,16), 256, SMEM_BYTES>>>(hnhi, hnlo, 2048, whi+oqkv, wlo+oqkv, 2048, qkv_, 4096, 2048, nullptr);

        k_qrope<<<MT_*NH_, 128>>>(qkv_, w_qn+(size_t)i*HD_, qhi, qlo);
        k_krope<<<MT_*NKV_, 128>>>(qkv_, w_kn+(size_t)i*HD_, khi, klo);
        k_vtrans<<<dim3(L_/32, HD_/32, 16), tb>>>(qkv_, vthi, vtlo);

        k_scores<<<dim3(8,8,32), 256, SMEM_BYTES>>>(qhi, qlo, khi, klo, sc_, scale, sl);
        k_softmax<<<B_*NH_*L_, 256>>>(sc_, schi, sclo, am, sl);
        k_attnv<<<dim3(1,8,32), 256, SMEM_BYTES>>>(schi, sclo, vthi, vtlo, ohi, olo, sl);

        k_dense<1><<<dim3(16,16), 256, SMEM_BYTES>>>(ohi, olo, 2048, whi+oo, wlo+oo, 2048, h_, 2048, 2048, nullptr);

        k_rmsnorm_split<<<MT_, 256>>>(h_, w_post+(size_t)i*HID_, hnhi, hnlo);
        k_dense<0><<<dim3(96,16), 256, SMEM_BYTES>>>(hnhi, hnlo, 2048, whi+ogu, wlo+ogu, 2048, gu_, 12288, 2048, nullptr);
        k_silu_split<<<(MT_*INT_)/256, 256>>>(gu_, achi, aclo);
        k_dense<1><<<dim3(16,16), 256, SMEM_BYTES>>>(achi, aclo, 6144, whi+od, wlo+od, 6144, h_, 2048, 6144, nullptr);
    }

    k_rmsnorm<<<MT_, 256>>>(h_, w_final, out);
}

// round 15
// speedup vs baseline: 2.7885x; 1.0435x over previous
#include <cuda_runtime.h>
#include <cuda_bf16.h>
#include <math.h>
#include <stdint.h>

#define B_ 2
#define L_ 1024
#define TXT_ 1024
#define HID_ 2048
#define INT_ 6144
#define NH_ 16
#define NKV_ 8
#define HD_ 128
#define NL_ 8
#define SW_ 128
#define MT_ (B_*L_)
#define EPS_ 1e-6f
#define NREP_ 2

typedef __nv_bfloat16 bf16;
typedef unsigned int u32;

// ---- split weights: planar bf16 hi/lo, [K][N] row-major (trans-B layout) ----
#define WZ_EMB (2048ull*1024ull)
#define WZ_QKV (4096ull*2048ull)
#define WZ_O   (2048ull*2048ull)
#define WZ_GU  (12288ull*2048ull)
#define WZ_D   (2048ull*6144ull)
#define WZ_LAYER (WZ_QKV + WZ_O + WZ_GU + WZ_D)
#define WB_TOTAL (WZ_EMB + 8ull*WZ_LAYER)

// ---- scratch ----
__device__ __align__(16) float g_h   [(size_t)MT_*HID_];
__device__ __align__(16) float g_qkv [(size_t)MT_*4096];
__device__ __align__(16) float g_gu  [(size_t)MT_*12288];
__device__ __align__(16) float g_sc  [(size_t)B_*NH_*L_*L_];
__device__ __align__(16) bf16 g_whi  [WB_TOTAL];
__device__ __align__(16) bf16 g_wlo  [WB_TOTAL];
__device__ __align__(16) bf16 g_xhi  [(size_t)MT_*TXT_];
__device__ __align__(16) bf16 g_xlo  [(size_t)MT_*TXT_];
__device__ __align__(16) bf16 g_hnhi [(size_t)MT_*HID_];
__device__ __align__(16) bf16 g_hnlo [(size_t)MT_*HID_];
__device__ __align__(16) bf16 g_qhi  [(size_t)MT_*2048];
__device__ __align__(16) bf16 g_qlo  [(size_t)MT_*2048];
__device__ __align__(16) bf16 g_khi  [16ull*L_*HD_];
__device__ __align__(16) bf16 g_klo  [16ull*L_*HD_];
__device__ __align__(16) bf16 g_vhi  [16ull*L_*HD_];
__device__ __align__(16) bf16 g_vlo  [16ull*L_*HD_];
__device__ __align__(16) bf16 g_schi [(size_t)B_*NH_*L_*L_];
__device__ __align__(16) bf16 g_sclo [(size_t)B_*NH_*L_*L_];
__device__ __align__(16) bf16 g_ohi  [(size_t)MT_*2048];
__device__ __align__(16) bf16 g_olo  [(size_t)MT_*2048];
__device__ __align__(16) bf16 g_achi [(size_t)MT_*INT_];
__device__ __align__(16) bf16 g_aclo [(size_t)MT_*INT_];

// ---- helpers ----
__device__ __forceinline__ u32 smem_u32(const void* p){
    u32 a; asm("{ .reg .u64 t; cvta.to.shared.u64 t, %1; cvt.u32.u64 %0, t; }":"=r"(a):"l"(p)); return a;
}
__device__ __forceinline__ u32 pack2(bf16 a, bf16 b){
    return (u32)__bfloat16_as_ushort(a) | ((u32)__bfloat16_as_ushort(b)<<16);
}
__device__ __forceinline__ void mma_bf16(float& d0,float& d1,float& d2,float& d3,
    u32 a0,u32 a1,u32 a2,u32 a3,u32 b0,u32 b1)
{
    asm volatile("mma.sync.aligned.m16n8k16.row.col.f32.bf16.bf16.f32 "
        "{%0,%1,%2,%3}, {%4,%5,%6,%7}, {%8,%9}, {%0,%1,%2,%3};\n"
        : "+f"(d0),"+f"(d1),"+f"(d2),"+f"(d3)
        : "r"(a0),"r"(a1),"r"(a2),"r"(a3),"r"(b0),"r"(b1));
}
__device__ __forceinline__ void cp16(u32 dst, const void* src){
    asm volatile("cp.async.ca.shared.global [%0], [%1], 16;"::"r"(dst),"l"(src):"memory");
}
#define CP_COMMIT() asm volatile("cp.async.commit_group;":::"memory")
#define CP_WAIT2()  asm volatile("cp.async.wait_group 2;":::"memory")
#define LDM4(r, a) asm volatile( \
    "ldmatrix.sync.aligned.m8n8.x4.shared.b16 {%0,%1,%2,%3}, [%4];" \
    : "=r"((r)[0]),"=r"((r)[1]),"=r"((r)[2]),"=r"((r)[3]) : "r"(a))
#define LDM4T(r, a) asm volatile( \
    "ldmatrix.sync.aligned.m8n8.x4.trans.shared.b16 {%0,%1,%2,%3}, [%4];" \
    : "=r"((r)[0]),"=r"((r)[1]),"=r"((r)[2]),"=r"((r)[3]) : "r"(a))

// ================ GEMM body ================
// C[128,NT] tile of A[M,K] @ B^T.  A planar bf16 hi/lo [M][K].
// TRB=0: B planar [N][K] (K contiguous), non-trans ldmatrix (stride 12 u32).
// TRB=1: B planar [K][N] (N contiguous), trans ldmatrix (row stride NT/2+4 u32).
// MI=2: CTA 128x128, warps 4x2 (32x64), 2 CTA/SM.  MI=4: CTA 128x256, warps 2x4 (64x64), 1 CTA/SM.
// 4-stage cp.async, BK=16.  EPI: 0 scale-store, 1 accumulate, 2 +bias, 3 bf16-split out.
template<int MI, int TRB, int EPI>
__device__ __forceinline__ void gbody(
    const bf16* __restrict__ Ahi, const bf16* __restrict__ Alo, int lda,
    const bf16* __restrict__ Bhi, const bf16* __restrict__ Blo, int ldb,
    float* __restrict__ C, bf16* __restrict__ Ohi, bf16* __restrict__ Olo, int ldc,
    int m0, int n0, int kbeg, int kend, const float* __restrict__ bias, float scale)
{
    constexpr int NT     = (MI==4) ? 256 : 128;
    constexpr int BSTR   = TRB ? (NT/2 + 4) : 12;          // u32 per B smem row
    constexpr int BPLANE = TRB ? 16*BSTR : NT*12;          // u32 per B plane
    constexpr int STGU   = 3072 + 2*BPLANE;                // u32 per stage

    extern __shared__ __align__(16) u32 dynsm[];
    const u32 sb = smem_u32(dynsm);
    const int tid=threadIdx.x, lane=tid&31, warp=tid>>5;
    const int wm = (MI==4) ? (warp>>2)*64 : (warp>>1)*32;
    const int wn = (MI==4) ? (warp&3)*64 : (warp&1)*64;
    const int g=lane>>2, t=lane&3;
    const int nslab=(kend-kbeg)>>4;

    float acc[MI][8][4];
#pragma unroll
    for(int mi=0;mi<MI;mi++)
#pragma unroll
        for(int ni=0;ni<8;ni++)
#pragma unroll
            for(int r=0;r<4;r++) acc[mi][ni][r]=0.f;

    const int lrow = tid>>1, lch = tid&1;

    auto load_stage = [&](int s){
        u32 base = sb + (u32)((s&3)*STGU)*4u;
        int k0 = kbeg + s*16;
        size_t ga = (size_t)(m0+lrow)*lda + k0 + lch*8;
        u32 da = base + (u32)(lrow*12 + lch*4)*4u;
        cp16(da,        Ahi+ga);
        cp16(da+6144,   Alo+ga);
        if (TRB){
#pragma unroll
            for (int it=0; it<NT/128; it++){
                int idx = tid + it*256;
                int krow = idx/(NT/8), nch = idx%(NT/8);
                u32 db = base + (u32)(3072 + krow*BSTR + nch*4)*4u;
                size_t gb = (size_t)(k0+krow)*ldb + n0 + nch*8;
                cp16(db,                  Bhi+gb);
                cp16(db + (u32)BPLANE*4u, Blo+gb);
            }
        } else {
#pragma unroll
            for (int it=0; it<NT/128; it++){
                int row = lrow + it*128;
                u32 db = base + (u32)(3072 + row*12 + lch*4)*4u;
                size_t gb = (size_t)(n0+row)*ldb + k0 + lch*8;
                cp16(db,                  Bhi+gb);
                cp16(db + (u32)BPLANE*4u, Blo+gb);
            }
        }
    };

    // ldmatrix per-lane byte offsets
    const int sel = lane>>3, lr = lane&7;
    const u32 aoff = (u32)((wm + lr + ((sel&1)<<3))*48 + ((sel>>1)<<4));
    u32 boff;
    if (TRB) boff = 12288u + (u32)((lr + ((sel&1)<<3))*(BSTR*4) + wn*2 + ((sel>>1)<<4));
    else     boff = 12288u + (u32)((wn + lr + ((sel>>1)<<3))*48 + ((sel&1)<<4));

    for (int p=0;p<3;p++){ if(p<nslab) load_stage(p); CP_COMMIT(); }

    for (int s=0;s<nslab;s++){
        CP_WAIT2();
        __syncthreads();
        if (s+3<nslab) load_stage(s+3);
        CP_COMMIT();

        u32 base = sb + (u32)((s&3)*STGU)*4u;
        u32 ah[MI][4], al[MI][4];
#pragma unroll
        for(int mi=0;mi<MI;mi++){
            LDM4(ah[mi], base + aoff + mi*768);
            LDM4(al[mi], base + aoff + mi*768 + 6144);
        }
#pragma unroll
        for(int p=0;p<4;p++){
            u32 bh[4], bl[4];
            if (TRB){
                LDM4T(bh, base + boff + p*32);
                LDM4T(bl, base + boff + p*32 + BPLANE*4);
            } else {
                LDM4(bh, base + boff + p*768);
                LDM4(bl, base + boff + p*768 + BPLANE*4);
            }
#pragma unroll
            for(int q=0;q<2;q++){
                int ni=p*2+q;
                u32 b0h=bh[q*2], b1h=bh[q*2+1], b0l=bl[q*2], b1l=bl[q*2+1];
#pragma unroll
                for(int mi=0;mi<MI;mi++){
                    mma_bf16(acc[mi][ni][0],acc[mi][ni][1],acc[mi][ni][2],acc[mi][ni][3],
                             ah[mi][0],ah[mi][1],ah[mi][2],ah[mi][3],b0l,b1l);
                    mma_bf16(acc[mi][ni][0],acc[mi][ni][1],acc[mi][ni][2],acc[mi][ni][3],
                             al[mi][0],al[mi][1],al[mi][2],al[mi][3],b0h,b1h);
                    mma_bf16(acc[mi][ni][0],acc[mi][ni][1],acc[mi][ni][2],acc[mi][ni][3],
                             ah[mi][0],ah[mi][1],ah[mi][2],ah[mi][3],b0h,b1h);
                }
            }
        }
    }

    // ---- epilogue ----
#pragma unroll
    for(int mi=0;mi<MI;mi++){
        int row0=m0+wm+mi*16+g;
#pragma unroll
        for(int ni=0;ni<8;ni++){
            int col=n0+wn+ni*8+2*t;
            float vx0=acc[mi][ni][0]*scale, vy0=acc[mi][ni][1]*scale;
            float vx1=acc[mi][ni][2]*scale, vy1=acc[mi][ni][3]*scale;
            if (EPI==2){ vx0+=bias[col]; vy0+=bias[col+1]; vx1+=bias[col]; vy1+=bias[col+1]; }
            if (EPI==3){
                bf16 h0=__float2bfloat16(vx0), h1=__float2bfloat16(vy0);
                *(u32*)&Ohi[(size_t)row0*ldc+col] = pack2(h0,h1);
                *(u32*)&Olo[(size_t)row0*ldc+col] = pack2(
                    __float2bfloat16(vx0-__bfloat162float(h0)),
                    __float2bfloat16(vy0-__bfloat162float(h1)));
                bf16 h2=__float2bfloat16(vx1), h3=__float2bfloat16(vy1);
                *(u32*)&Ohi[(size_t)(row0+8)*ldc+col] = pack2(h2,h3);
                *(u32*)&Olo[(size_t)(row0+8)*ldc+col] = pack2(
                    __float2bfloat16(vx1-__bfloat162float(h2)),
                    __float2bfloat16(vy1-__bfloat162float(h3)));
            } else {
                float2* cp=(float2*)&C[(size_t)row0*ldc+col];
                float2 v; v.x=vx0; v.y=vy0;
                if (EPI==1){ float2 p=*cp; v.x+=p.x; v.y+=p.y; }
                *cp=v;
                cp=(float2*)&C[(size_t)(row0+8)*ldc+col];
                v.x=vx1; v.y=vy1;
                if (EPI==1){ float2 p=*cp; v.x+=p.x; v.y+=p.y; }
                *cp=v;
            }
        }
    }
}

#define SM_DENSE  116736   // MI=4, TRB=1
#define SM_SCORES 98304    // MI=2, TRB=0
#define SM_ATTNV  83968    // MI=2, TRB=1

template<int EPI>
__global__ void __launch_bounds__(256,1) k_dense(
    const bf16* Ahi, const bf16* Alo, int lda,
    const bf16* Bhi, const bf16* Blo, int ldb,
    float* C, int ldc, int K, const float* bias)
{
    gbody<4,1,EPI>(Ahi,Alo,lda,Bhi,Blo,ldb,C,nullptr,nullptr,ldc,
                   blockIdx.y*128, blockIdx.x*256, 0, K, bias, 1.f);
}

__global__ void __launch_bounds__(256,2) k_scores(
    const bf16* qhi, const bf16* qlo, const bf16* khi, const bf16* klo,
    float* sc, float scale, int sliding)
{
    int z=blockIdx.z, b=z/NH_, h=z%NH_, kv=h/NREP_;
    int m0=blockIdx.y*128, n0=blockIdx.x*128;
    if (sliding && (n0 <= m0-256 || n0 >= m0+256)) return;
    size_t ao = (size_t)b*L_*2048 + (size_t)h*HD_;
    size_t bo = (size_t)(b*NKV_+kv)*L_*HD_;
    gbody<2,0,0>(qhi+ao, qlo+ao, 2048, khi+bo, klo+bo, HD_,
                 sc + (size_t)z*L_*L_, nullptr, nullptr, L_,
                 m0, n0, 0, HD_, nullptr, scale);
}

__global__ void __launch_bounds__(256,2) k_attnv(
    const bf16* schi, const bf16* sclo, const bf16* vhi, const bf16* vlo,
    bf16* ohi, bf16* olo, int sliding)
{
    int z=blockIdx.z, b=z/NH_, h=z%NH_, kv=h/NREP_;
    int m0=blockIdx.y*128;
    int kb=0, ke=L_;
    if (sliding){ kb = (m0>=128)? m0-128 : 0; ke = (m0+256<=L_)? m0+256 : L_; }
    size_t ao = (size_t)z*L_*L_;
    size_t bo = (size_t)(b*NKV_+kv)*L_*HD_;   // V [token][d]
    size_t oo = (size_t)b*L_*2048 + (size_t)h*HD_;
    gbody<2,1,3>(schi+ao, sclo+ao, L_, vhi+bo, vlo+bo, HD_,
                 nullptr, ohi+oo, olo+oo, 2048,
                 m0, 0, kb, ke, nullptr, 1.f);
}

// ================ weight pack: W[K,N] f32 -> planar bf16 hi/lo [K][PN] at coloff (NO transpose) ================
__global__ void __launch_bounds__(256) k_wpack(const float* __restrict__ W, int K, int N,
    bf16* __restrict__ hi, bf16* __restrict__ lo, int PN, int coloff)
{
    int idx = blockIdx.x*256 + threadIdx.x;
    if (idx >= K*N) return;
    int k = idx / N, n = idx % N;
    float v = W[idx];
    bf16 h = __float2bfloat16(v);
    size_t o = (size_t)k*PN + coloff + n;
    hi[o]=h; lo[o]=__float2bfloat16(v-__bfloat162float(h));
}

// ================ elementwise ================
__global__ void __launch_bounds__(256) k_split(const float* __restrict__ x,
    bf16* __restrict__ hi, bf16* __restrict__ lo, int n)
{
    int i = blockIdx.x*256+threadIdx.x;
    if (i<n){ float v=x[i]; bf16 h=__float2bfloat16(v);
        hi[i]=h; lo[i]=__float2bfloat16(v-__bfloat162float(h)); }
}
__global__ void __launch_bounds__(256) k_rmsnorm_split(const float* __restrict__ x,
    const float* __restrict__ w, bf16* __restrict__ hi, bf16* __restrict__ lo)
{
    int row=blockIdx.x; const float* xr=x+(size_t)row*HID_;
    int t=threadIdx.x; float ss=0.f;
    for(int j=t;j<HID_;j+=256){ float v=xr[j]; ss+=v*v; }
    __shared__ float red[256]; red[t]=ss; __syncthreads();
    for(int s=128;s>0;s>>=1){ if(t<s) red[t]+=red[t+s]; __syncthreads(); }
    float rs=rsqrtf(red[0]/(float)HID_+EPS_);
    for(int j=t;j<HID_;j+=256){
        float v=w[j]*xr[j]*rs; bf16 h=__float2bfloat16(v);
        size_t o=(size_t)row*HID_+j; hi[o]=h; lo[o]=__float2bfloat16(v-__bfloat162float(h));
    }
}
__global__ void __launch_bounds__(256) k_rmsnorm(const float* __restrict__ x,
    const float* __restrict__ w, float* __restrict__ y)
{
    int row=blockIdx.x; const float* xr=x+(size_t)row*HID_;
    float* yr=y+(size_t)row*HID_;
    int t=threadIdx.x; float ss=0.f;
    for(int j=t;j<HID_;j+=256){ float v=xr[j]; ss+=v*v; }
    __shared__ float red[256]; red[t]=ss; __syncthreads();
    for(int s=128;s>0;s>>=1){ if(t<s) red[t]+=red[t+s]; __syncthreads(); }
    float rs=rsqrtf(red[0]/(float)HID_+EPS_);
    for(int j=t;j<HID_;j+=256) yr[j]=w[j]*xr[j]*rs;
}
__global__ void __launch_bounds__(256) k_silu_split(const float* __restrict__ gu,
    bf16* __restrict__ hi, bf16* __restrict__ lo)
{
    int idx = blockIdx.x*256+threadIdx.x;   // over MT*INT
    int row = idx / INT_, j = idx % INT_;
    float gv = gu[(size_t)row*12288 + j];
    float uv = gu[(size_t)row*12288 + 6144 + j];
    float v = gv/(1.f+expf(-gv))*uv;
    bf16 h=__float2bfloat16(v);
    hi[idx]=h; lo[idx]=__float2bfloat16(v-__bfloat162float(h));
}

// q rope: planar hi/lo [tok][2048]
__global__ void __launch_bounds__(128) k_qrope(const float* __restrict__ qkv,
    const float* __restrict__ w, bf16* __restrict__ qhi, bf16* __restrict__ qlo)
{
    int idx=blockIdx.x, head=idx%NH_, tok=idx/NH_, pos=tok%L_;
    int d=threadIdx.x;
    float v = qkv[(size_t)tok*4096 + head*128 + d];
    __shared__ float sh[128];
    sh[d]=v*v; __syncthreads();
    for(int s=64;s>0;s>>=1){ if(d<s) sh[d]+=sh[d+s]; __syncthreads(); }
    float rs=rsqrtf(sh[0]/(float)HD_+EPS_);
    __syncthreads();
    float xn=w[d]*v*rs;
    sh[d]=xn; __syncthreads();
    float rot=(d<64)? -sh[d+64] : sh[d-64];
    int half=d&63;
    float inv=expf(-(2.f*(float)half/(float)HD_)*13.815510557964274f);
    float ang=(float)pos*inv;
    float val = xn*cosf(ang)+rot*sinf(ang);
    bf16 h=__float2bfloat16(val);
    size_t o=(size_t)tok*2048 + head*128 + d;
    qhi[o]=h; qlo[o]=__float2bfloat16(val-__bfloat162float(h));
}

// k rope: planar hi/lo [b*8+kv][token][d]
__global__ void __launch_bounds__(128) k_krope(const float* __restrict__ qkv,
    const float* __restrict__ w, bf16* __restrict__ khi, bf16* __restrict__ klo)
{
    int idx=blockIdx.x, kv=idx%NKV_, tok=idx/NKV_, pos=tok%L_;
    int b=tok/L_, j=tok%L_;
    int d=threadIdx.x;
    float v = qkv[(size_t)tok*4096 + 2048 + kv*128 + d];
    __shared__ float sh[128];
    sh[d]=v*v; __syncthreads();
    for(int s=64;s>0;s>>=1){ if(d<s) sh[d]+=sh[d+s]; __syncthreads(); }
    float rs=rsqrtf(sh[0]/(float)HD_+EPS_);
    __syncthreads();
    float xn=w[d]*v*rs;
    sh[d]=xn; __syncthreads();
    float rot=(d<64)? -sh[d+64] : sh[d-64];
    int half=d&63;
    float inv=expf(-(2.f*(float)half/(float)HD_)*13.815510557964274f);
    float ang=(float)pos*inv;
    float val = xn*cosf(ang)+rot*sinf(ang);
    bf16 h=__float2bfloat16(val);
    size_t o = ((size_t)(b*NKV_+kv)*L_ + j)*HD_ + d;
    khi[o]=h; klo[o]=__float2bfloat16(val-__bfloat162float(h));
}

// v split: qkv v-section -> planar hi/lo [b*8+kv][token][d] (natural order, no transpose)
__global__ void __launch_bounds__(256) k_vsplit(const float* __restrict__ qkv,
    bf16* __restrict__ vhi, bf16* __restrict__ vlo)
{
    int idx = blockIdx.x*256+threadIdx.x;   // MT_ * 1024
    int tok = idx >> 10, r = idx & 1023;
    int kv = r >> 7, d = r & 127;
    int b = tok / L_, j = tok % L_;
    float v = qkv[(size_t)tok*4096 + 3072 + kv*128 + d];
    bf16 h = __float2bfloat16(v);
    size_t o = ((size_t)(b*NKV_+kv)*L_ + j)*HD_ + d;
    vhi[o]=h; vlo[o]=__float2bfloat16(v-__bfloat162float(h));
}

// softmax: fp32 scores -> bf16 hi/lo planar probs
__global__ void __launch_bounds__(256) k_softmax(const float* __restrict__ sc,
    bf16* __restrict__ shi, bf16* __restrict__ slo, const int* __restrict__ am, int sliding)
{
    int row=blockIdx.x, i=row%L_, b=row/(NH_*L_);
    const float* r=sc+(size_t)row*L_;
    const int* amr=am+(size_t)b*L_;
    int t=threadIdx.x;
    float4 v4=*(const float4*)&r[t*4];
    float vals[4]={v4.x,v4.y,v4.z,v4.w};
    bool keep[4]; float mx=-INFINITY;
#pragma unroll
    for(int q=0;q<4;q++){
        int j=t*4+q, dj=i-j; if(dj<0)dj=-dj;
        keep[q]=(amr[j]!=0)&&(!sliding||dj<=SW_);
        if(!keep[q]) vals[q]=-INFINITY;
        mx=fmaxf(mx,vals[q]);
    }
    __shared__ float red[256];
    red[t]=mx; __syncthreads();
    for(int s=128;s>0;s>>=1){ if(t<s) red[t]=fmaxf(red[t],red[t+s]); __syncthreads(); }
    float rm=red[0]; __syncthreads();
    float e[4], ssum=0.f;
#pragma unroll
    for(int q=0;q<4;q++){ e[q]=keep[q]?expf(vals[q]-rm):0.f; ssum+=e[q]; }
    red[t]=ssum; __syncthreads();
    for(int s=128;s>0;s>>=1){ if(t<s) red[t]+=red[t+s]; __syncthreads(); }
    float tot=red[0];
    float inv=(tot>0.f)?(1.f/tot):0.f;
    u32* oh = (u32*)(shi + (size_t)row*L_) + t*2;
    u32* ol = (u32*)(slo + (size_t)row*L_) + t*2;
#pragma unroll
    for(int q=0;q<2;q++){
        float a0=e[q*2]*inv, a1=e[q*2+1]*inv;
        bf16 h0=__float2bfloat16(a0), h1=__float2bfloat16(a1);
        oh[q]=pack2(h0,h1);
        ol[q]=pack2(__float2bfloat16(a0-__bfloat162float(h0)),
                    __float2bfloat16(a1-__bfloat162float(h1)));
    }
}

// ================ host driver ================
extern "C" void kernel_launch(void* const* d_in, const int* in_sizes, int n_in,
                              void* d_out, int out_size)
{
    const float* x       = (const float*)d_in[0];
    const int*   am      = (const int*)  d_in[1];
    const float* W_embed = (const float*)d_in[2];
    const float* b_embed = (const float*)d_in[3];
    const float* Wq      = (const float*)d_in[4];
    const float* Wk      = (const float*)d_in[5];
    const float* Wv      = (const float*)d_in[6];
    const float* Wo      = (const float*)d_in[7];
    const float* w_in_ln = (const float*)d_in[8];
    const float* w_post  = (const float*)d_in[9];
    const float* w_qn    = (const float*)d_in[10];
    const float* w_kn    = (const float*)d_in[11];
    const float* Wg      = (const float*)d_in[12];
    const float* Wu      = (const float*)d_in[13];
    const float* Wd      = (const float*)d_in[14];
    const float* w_final = (const float*)d_in[15];
    float* out = (float*)d_out;

    float *h_, *qkv_, *gu_, *sc_;
    bf16 *whi,*wlo,*xhi,*xlo,*hnhi,*hnlo,*qhi,*qlo,*khi,*klo,*vhi,*vlo;
    bf16 *schi,*sclo,*ohi,*olo,*achi,*aclo;
    cudaGetSymbolAddress((void**)&h_, g_h);      cudaGetSymbolAddress((void**)&qkv_, g_qkv);
    cudaGetSymbolAddress((void**)&gu_, g_gu);    cudaGetSymbolAddress((void**)&sc_, g_sc);
    cudaGetSymbolAddress((void**)&whi, g_whi);   cudaGetSymbolAddress((void**)&wlo, g_wlo);
    cudaGetSymbolAddress((void**)&xhi, g_xhi);   cudaGetSymbolAddress((void**)&xlo, g_xlo);
    cudaGetSymbolAddress((void**)&hnhi, g_hnhi); cudaGetSymbolAddress((void**)&hnlo, g_hnlo);
    cudaGetSymbolAddress((void**)&qhi, g_qhi);   cudaGetSymbolAddress((void**)&qlo, g_qlo);
    cudaGetSymbolAddress((void**)&khi, g_khi);   cudaGetSymbolAddress((void**)&klo, g_klo);
    cudaGetSymbolAddress((void**)&vhi, g_vhi);   cudaGetSymbolAddress((void**)&vlo, g_vlo);
    cudaGetSymbolAddress((void**)&schi, g_schi); cudaGetSymbolAddress((void**)&sclo, g_sclo);
    cudaGetSymbolAddress((void**)&ohi, g_ohi);   cudaGetSymbolAddress((void**)&olo, g_olo);
    cudaGetSymbolAddress((void**)&achi, g_achi); cudaGetSymbolAddress((void**)&aclo, g_aclo);

    cudaFuncSetAttribute(k_dense<0>, cudaFuncAttributeMaxDynamicSharedMemorySize, SM_DENSE);
    cudaFuncSetAttribute(k_dense<1>, cudaFuncAttributeMaxDynamicSharedMemorySize, SM_DENSE);
    cudaFuncSetAttribute(k_dense<2>, cudaFuncAttributeMaxDynamicSharedMemorySize, SM_DENSE);
    cudaFuncSetAttribute(k_scores,   cudaFuncAttributeMaxDynamicSharedMemorySize, SM_SCORES);
    cudaFuncSetAttribute(k_attnv,    cudaFuncAttributeMaxDynamicSharedMemorySize, SM_ATTNV);

    const float scale = 0.08838834764831845f;

    // ---- weight split (streaming, no transpose): out layout [K][PN] ----
    k_wpack<<<(1024*2048)/256, 256>>>(W_embed, 1024, 2048, whi, wlo, 2048, 0);
    for (int i=0;i<NL_;i++){
        size_t lb = WZ_EMB + (size_t)i*WZ_LAYER;
        size_t oqkv=lb, oo=oqkv+WZ_QKV, ogu=oo+WZ_O, od=ogu+WZ_GU;
        k_wpack<<<(2048*2048)/256, 256>>>(Wq+(size_t)i*2048*2048, 2048, 2048, whi+oqkv, wlo+oqkv, 4096, 0);
        k_wpack<<<(2048*1024)/256, 256>>>(Wk+(size_t)i*2048*1024, 2048, 1024, whi+oqkv, wlo+oqkv, 4096, 2048);
        k_wpack<<<(2048*1024)/256, 256>>>(Wv+(size_t)i*2048*1024, 2048, 1024, whi+oqkv, wlo+oqkv, 4096, 3072);
        k_wpack<<<(2048*2048)/256, 256>>>(Wo+(size_t)i*2048*2048, 2048, 2048, whi+oo, wlo+oo, 2048, 0);
        k_wpack<<<(2048*6144)/256, 256>>>(Wg+(size_t)i*2048*6144, 2048, 6144, whi+ogu, wlo+ogu, 12288, 0);
        k_wpack<<<(2048*6144)/256, 256>>>(Wu+(size_t)i*2048*6144, 2048, 6144, whi+ogu, wlo+ogu, 12288, 6144);
        k_wpack<<<(6144*2048)/256, 256>>>(Wd+(size_t)i*6144*2048, 6144, 2048, whi+od, wlo+od, 2048, 0);
    }

    // ---- embed ----
    k_split<<<(MT_*TXT_)/256, 256>>>(x, xhi, xlo, MT_*TXT_);
    k_dense<2><<<dim3(8,16), 256, SM_DENSE>>>(xhi, xlo, 1024, whi, wlo, 2048, h_, 2048, 1024, b_embed);

    for (int i=0;i<NL_;i++){
        size_t lb = WZ_EMB + (size_t)i*WZ_LAYER;
        size_t oqkv=lb, oo=oqkv+WZ_QKV, ogu=oo+WZ_O, od=ogu+WZ_GU;
        int sl = (i%2==0) ? 1 : 0;

        k_rmsnorm_split<<<MT_, 256>>>(h_, w_in_ln+(size_t)i*HID_, hnhi, hnlo);
        k_dense<0><<<dim3(16,16), 256, SM_DENSE>>>(hnhi, hnlo, 2048, whi+oqkv, wlo+oqkv, 4096, qkv_, 4096, 2048, nullptr);

        k_qrope<<<MT_*NH_, 128>>>(qkv_, w_qn+(size_t)i*HD_, qhi, qlo);
        k_krope<<<MT_*NKV_, 128>>>(qkv_, w_kn+(size_t)i*HD_, khi, klo);
        k_vsplit<<<(MT_*1024)/256, 256>>>(qkv_, vhi, vlo);

        k_scores<<<dim3(8,8,32), 256, SM_SCORES>>>(qhi, qlo, khi, klo, sc_, scale, sl);
        k_softmax<<<B_*NH_*L_, 256>>>(sc_, schi, sclo, am, sl);
        k_attnv<<<dim3(1,8,32), 256, SM_ATTNV>>>(schi, sclo, vhi, vlo, ohi, olo, sl);

        k_dense<1><<<dim3(8,16), 256, SM_DENSE>>>(ohi, olo, 2048, whi+oo, wlo+oo, 2048, h_, 2048, 2048, nullptr);

        k_rmsnorm_split<<<MT_, 256>>>(h_, w_post+(size_t)i*HID_, hnhi, hnlo);
        k_dense<0><<<dim3(48,16), 256, SM_DENSE>>>(hnhi, hnlo, 2048, whi+ogu, wlo+ogu, 12288, gu_, 12288, 2048, nullptr);
        k_silu_split<<<(MT_*INT_)/256, 256>>>(gu_, achi, aclo);
        k_dense<1><<<dim3(8,16), 256, SM_DENSE>>>(achi, aclo, 6144, whi+od, wlo+od, 2048, h_, 2048, 6144, nullptr);
    }

    k_rmsnorm<<<MT_, 256>>>(h_, w_final, out);
}

// round 17
// speedup vs baseline: 2.9417x; 1.0550x over previous
#include <cuda_runtime.h>
#include <cuda_bf16.h>
#include <math.h>
#include <stdint.h>

#define B_ 2
#define L_ 1024
#define TXT_ 1024
#define HID_ 2048
#define INT_ 6144
#define NH_ 16
#define NKV_ 8
#define HD_ 128
#define NL_ 8
#define SW_ 128
#define MT_ (B_*L_)
#define EPS_ 1e-6f
#define NREP_ 2

typedef __nv_bfloat16 bf16;
typedef unsigned int u32;

// ---- split weights: planar bf16 hi/lo, [K][N] row-major (trans-B layout) ----
#define WZ_EMB (2048ull*1024ull)
#define WZ_QKV (4096ull*2048ull)
#define WZ_O   (2048ull*2048ull)
#define WZ_GU  (12288ull*2048ull)
#define WZ_D   (2048ull*6144ull)
#define WZ_LAYER (WZ_QKV + WZ_O + WZ_GU + WZ_D)
#define WB_TOTAL (WZ_EMB + 8ull*WZ_LAYER)

// ---- scratch ----
__device__ __align__(16) float g_h   [(size_t)MT_*HID_];
__device__ __align__(16) float g_qkv [(size_t)MT_*4096];
__device__ __align__(16) float g_gu  [(size_t)MT_*12288];
__device__ __align__(16) float g_sc  [(size_t)B_*NH_*L_*L_];
__device__ __align__(16) bf16 g_whi  [WB_TOTAL];
__device__ __align__(16) bf16 g_wlo  [WB_TOTAL];
__device__ __align__(16) bf16 g_xhi  [(size_t)MT_*TXT_];
__device__ __align__(16) bf16 g_xlo  [(size_t)MT_*TXT_];
__device__ __align__(16) bf16 g_hnhi [(size_t)MT_*HID_];
__device__ __align__(16) bf16 g_hnlo [(size_t)MT_*HID_];
__device__ __align__(16) bf16 g_qhi  [(size_t)MT_*2048];
__device__ __align__(16) bf16 g_qlo  [(size_t)MT_*2048];
__device__ __align__(16) bf16 g_khi  [16ull*L_*HD_];
__device__ __align__(16) bf16 g_klo  [16ull*L_*HD_];
__device__ __align__(16) bf16 g_vhi  [16ull*L_*HD_];
__device__ __align__(16) bf16 g_vlo  [16ull*L_*HD_];
__device__ __align__(16) bf16 g_schi [(size_t)B_*NH_*L_*L_];
__device__ __align__(16) bf16 g_sclo [(size_t)B_*NH_*L_*L_];
__device__ __align__(16) bf16 g_ohi  [(size_t)MT_*2048];
__device__ __align__(16) bf16 g_olo  [(size_t)MT_*2048];
__device__ __align__(16) bf16 g_achi [(size_t)MT_*INT_];
__device__ __align__(16) bf16 g_aclo [(size_t)MT_*INT_];

// ---- helpers ----
__device__ __forceinline__ u32 smem_u32(const void* p){
    u32 a; asm("{ .reg .u64 t; cvta.to.shared.u64 t, %1; cvt.u32.u64 %0, t; }":"=r"(a):"l"(p)); return a;
}
__device__ __forceinline__ u32 pack2(bf16 a, bf16 b){
    return (u32)__bfloat16_as_ushort(a) | ((u32)__bfloat16_as_ushort(b)<<16);
}
__device__ __forceinline__ void split2u(float v0, float v1, u32& hw, u32& lw){
    bf16 h0=__float2bfloat16(v0), h1=__float2bfloat16(v1);
    hw = pack2(h0,h1);
    lw = pack2(__float2bfloat16(v0-__bfloat162float(h0)),
               __float2bfloat16(v1-__bfloat162float(h1)));
}
__device__ __forceinline__ void mma_bf16(float& d0,float& d1,float& d2,float& d3,
    u32 a0,u32 a1,u32 a2,u32 a3,u32 b0,u32 b1)
{
    asm volatile("mma.sync.aligned.m16n8k16.row.col.f32.bf16.bf16.f32 "
        "{%0,%1,%2,%3}, {%4,%5,%6,%7}, {%8,%9}, {%0,%1,%2,%3};\n"
        : "+f"(d0),"+f"(d1),"+f"(d2),"+f"(d3)
        : "r"(a0),"r"(a1),"r"(a2),"r"(a3),"r"(b0),"r"(b1));
}
__device__ __forceinline__ void cp16(u32 dst, const void* src){
    asm volatile("cp.async.ca.shared.global [%0], [%1], 16;"::"r"(dst),"l"(src):"memory");
}
#define CP_COMMIT() asm volatile("cp.async.commit_group;":::"memory")
#define CP_WAIT2()  asm volatile("cp.async.wait_group 2;":::"memory")
#define LDM4(r, a) asm volatile( \
    "ldmatrix.sync.aligned.m8n8.x4.shared.b16 {%0,%1,%2,%3}, [%4];" \
    : "=r"((r)[0]),"=r"((r)[1]),"=r"((r)[2]),"=r"((r)[3]) : "r"(a))
#define LDM4T(r, a) asm volatile( \
    "ldmatrix.sync.aligned.m8n8.x4.trans.shared.b16 {%0,%1,%2,%3}, [%4];" \
    : "=r"((r)[0]),"=r"((r)[1]),"=r"((r)[2]),"=r"((r)[3]) : "r"(a))

// ================ GEMM body (unchanged from R15) ================
template<int MI, int TRB, int EPI>
__device__ __forceinline__ void gbody(
    const bf16* __restrict__ Ahi, const bf16* __restrict__ Alo, int lda,
    const bf16* __restrict__ Bhi, const bf16* __restrict__ Blo, int ldb,
    float* __restrict__ C, bf16* __restrict__ Ohi, bf16* __restrict__ Olo, int ldc,
    int m0, int n0, int kbeg, int kend, const float* __restrict__ bias, float scale)
{
    constexpr int NT     = (MI==4) ? 256 : 128;
    constexpr int BSTR   = TRB ? (NT/2 + 4) : 12;
    constexpr int BPLANE = TRB ? 16*BSTR : NT*12;
    constexpr int STGU   = 3072 + 2*BPLANE;

    extern __shared__ __align__(16) u32 dynsm[];
    const u32 sb = smem_u32(dynsm);
    const int tid=threadIdx.x, lane=tid&31, warp=tid>>5;
    const int wm = (MI==4) ? (warp>>2)*64 : (warp>>1)*32;
    const int wn = (MI==4) ? (warp&3)*64 : (warp&1)*64;
    const int g=lane>>2, t=lane&3;
    const int nslab=(kend-kbeg)>>4;

    float acc[MI][8][4];
#pragma unroll
    for(int mi=0;mi<MI;mi++)
#pragma unroll
        for(int ni=0;ni<8;ni++)
#pragma unroll
            for(int r=0;r<4;r++) acc[mi][ni][r]=0.f;

    const int lrow = tid>>1, lch = tid&1;

    auto load_stage = [&](int s){
        u32 base = sb + (u32)((s&3)*STGU)*4u;
        int k0 = kbeg + s*16;
        size_t ga = (size_t)(m0+lrow)*lda + k0 + lch*8;
        u32 da = base + (u32)(lrow*12 + lch*4)*4u;
        cp16(da,        Ahi+ga);
        cp16(da+6144,   Alo+ga);
        if (TRB){
#pragma unroll
            for (int it=0; it<NT/128; it++){
                int idx = tid + it*256;
                int krow = idx/(NT/8), nch = idx%(NT/8);
                u32 db = base + (u32)(3072 + krow*BSTR + nch*4)*4u;
                size_t gb = (size_t)(k0+krow)*ldb + n0 + nch*8;
                cp16(db,                  Bhi+gb);
                cp16(db + (u32)BPLANE*4u, Blo+gb);
            }
        } else {
#pragma unroll
            for (int it=0; it<NT/128; it++){
                int row = lrow + it*128;
                u32 db = base + (u32)(3072 + row*12 + lch*4)*4u;
                size_t gb = (size_t)(n0+row)*ldb + k0 + lch*8;
                cp16(db,                  Bhi+gb);
                cp16(db + (u32)BPLANE*4u, Blo+gb);
            }
        }
    };

    const int sel = lane>>3, lr = lane&7;
    const u32 aoff = (u32)((wm + lr + ((sel&1)<<3))*48 + ((sel>>1)<<4));
    u32 boff;
    if (TRB) boff = 12288u + (u32)((lr + ((sel&1)<<3))*(BSTR*4) + wn*2 + ((sel>>1)<<4));
    else     boff = 12288u + (u32)((wn + lr + ((sel>>1)<<3))*48 + ((sel&1)<<4));

    for (int p=0;p<3;p++){ if(p<nslab) load_stage(p); CP_COMMIT(); }

    for (int s=0;s<nslab;s++){
        CP_WAIT2();
        __syncthreads();
        if (s+3<nslab) load_stage(s+3);
        CP_COMMIT();

        u32 base = sb + (u32)((s&3)*STGU)*4u;
        u32 ah[MI][4], al[MI][4];
#pragma unroll
        for(int mi=0;mi<MI;mi++){
            LDM4(ah[mi], base + aoff + mi*768);
            LDM4(al[mi], base + aoff + mi*768 + 6144);
        }
#pragma unroll
        for(int p=0;p<4;p++){
            u32 bh[4], bl[4];
            if (TRB){
                LDM4T(bh, base + boff + p*32);
                LDM4T(bl, base + boff + p*32 + BPLANE*4);
            } else {
                LDM4(bh, base + boff + p*768);
                LDM4(bl, base + boff + p*768 + BPLANE*4);
            }
#pragma unroll
            for(int q=0;q<2;q++){
                int ni=p*2+q;
                u32 b0h=bh[q*2], b1h=bh[q*2+1], b0l=bl[q*2], b1l=bl[q*2+1];
#pragma unroll
                for(int mi=0;mi<MI;mi++){
                    mma_bf16(acc[mi][ni][0],acc[mi][ni][1],acc[mi][ni][2],acc[mi][ni][3],
                             ah[mi][0],ah[mi][1],ah[mi][2],ah[mi][3],b0l,b1l);
                    mma_bf16(acc[mi][ni][0],acc[mi][ni][1],acc[mi][ni][2],acc[mi][ni][3],
                             al[mi][0],al[mi][1],al[mi][2],al[mi][3],b0h,b1h);
                    mma_bf16(acc[mi][ni][0],acc[mi][ni][1],acc[mi][ni][2],acc[mi][ni][3],
                             ah[mi][0],ah[mi][1],ah[mi][2],ah[mi][3],b0h,b1h);
                }
            }
        }
    }

#pragma unroll
    for(int mi=0;mi<MI;mi++){
        int row0=m0+wm+mi*16+g;
#pragma unroll
        for(int ni=0;ni<8;ni++){
            int col=n0+wn+ni*8+2*t;
            float vx0=acc[mi][ni][0]*scale, vy0=acc[mi][ni][1]*scale;
            float vx1=acc[mi][ni][2]*scale, vy1=acc[mi][ni][3]*scale;
            if (EPI==2){ vx0+=bias[col]; vy0+=bias[col+1]; vx1+=bias[col]; vy1+=bias[col+1]; }
            if (EPI==3){
                u32 hw,lw;
                split2u(vx0,vy0,hw,lw);
                *(u32*)&Ohi[(size_t)row0*ldc+col]=hw;
                *(u32*)&Olo[(size_t)row0*ldc+col]=lw;
                split2u(vx1,vy1,hw,lw);
                *(u32*)&Ohi[(size_t)(row0+8)*ldc+col]=hw;
                *(u32*)&Olo[(size_t)(row0+8)*ldc+col]=lw;
            } else {
                float2* cp=(float2*)&C[(size_t)row0*ldc+col];
                float2 v; v.x=vx0; v.y=vy0;
                if (EPI==1){ float2 p=*cp; v.x+=p.x; v.y+=p.y; }
                *cp=v;
                cp=(float2*)&C[(size_t)(row0+8)*ldc+col];
                v.x=vx1; v.y=vy1;
                if (EPI==1){ float2 p=*cp; v.x+=p.x; v.y+=p.y; }
                *cp=v;
            }
        }
    }
}

#define SM_DENSE  116736
#define SM_SCORES 98304
#define SM_ATTNV  83968

template<int EPI>
__global__ void __launch_bounds__(256,1) k_dense(
    const bf16* Ahi, const bf16* Alo, int lda,
    const bf16* Bhi, const bf16* Blo, int ldb,
    float* C, int ldc, int K, const float* bias)
{
    gbody<4,1,EPI>(Ahi,Alo,lda,Bhi,Blo,ldb,C,nullptr,nullptr,ldc,
                   blockIdx.y*128, blockIdx.x*256, 0, K, bias, 1.f);
}

__global__ void __launch_bounds__(256,2) k_scores(
    const bf16* qhi, const bf16* qlo, const bf16* khi, const bf16* klo,
    float* sc, float scale, int sliding)
{
    int z=blockIdx.z, b=z/NH_, h=z%NH_, kv=h/NREP_;
    int m0=blockIdx.y*128, n0=blockIdx.x*128;
    if (sliding && (n0 <= m0-256 || n0 >= m0+256)) return;
    size_t ao = (size_t)b*L_*2048 + (size_t)h*HD_;
    size_t bo = (size_t)(b*NKV_+kv)*L_*HD_;
    gbody<2,0,0>(qhi+ao, qlo+ao, 2048, khi+bo, klo+bo, HD_,
                 sc + (size_t)z*L_*L_, nullptr, nullptr, L_,
                 m0, n0, 0, HD_, nullptr, scale);
}

__global__ void __launch_bounds__(256,2) k_attnv(
    const bf16* schi, const bf16* sclo, const bf16* vhi, const bf16* vlo,
    bf16* ohi, bf16* olo, int sliding)
{
    int z=blockIdx.z, b=z/NH_, h=z%NH_, kv=h/NREP_;
    int m0=blockIdx.y*128;
    int kb=0, ke=L_;
    if (sliding){ kb = (m0>=128)? m0-128 : 0; ke = (m0+256<=L_)? m0+256 : L_; }
    size_t ao = (size_t)z*L_*L_;
    size_t bo = (size_t)(b*NKV_+kv)*L_*HD_;
    size_t oo = (size_t)b*L_*2048 + (size_t)h*HD_;
    gbody<2,1,3>(schi+ao, sclo+ao, L_, vhi+bo, vlo+bo, HD_,
                 nullptr, ohi+oo, olo+oo, 2048,
                 m0, 0, kb, ke, nullptr, 1.f);
}

// ================ weight pack, 8-wide vectorized ================
__global__ void __launch_bounds__(256) k_wpack8(const float* __restrict__ W, int N,
    bf16* __restrict__ hi, bf16* __restrict__ lo, int PN, int coloff, int total8)
{
    int idx = blockIdx.x*256 + threadIdx.x;
    if (idx >= total8) return;
    size_t e = (size_t)idx*8;
    int k = (int)(e / (size_t)N), n = (int)(e % (size_t)N);
    float4 a = *(const float4*)(W+e);
    float4 b = *(const float4*)(W+e+4);
    float v[8] = {a.x,a.y,a.z,a.w,b.x,b.y,b.z,b.w};
    u32 hw[4], lw[4];
#pragma unroll
    for (int q=0;q<4;q++) split2u(v[2*q], v[2*q+1], hw[q], lw[q]);
    size_t o = (size_t)k*PN + coloff + n;
    *(uint4*)(hi+o) = make_uint4(hw[0],hw[1],hw[2],hw[3]);
    *(uint4*)(lo+o) = make_uint4(lw[0],lw[1],lw[2],lw[3]);
}

// ================ elementwise (vectorized x4) ================
__global__ void __launch_bounds__(256) k_split4(const float* __restrict__ x,
    bf16* __restrict__ hi, bf16* __restrict__ lo, int n4)
{
    int i = blockIdx.x*256+threadIdx.x;
    if (i<n4){
        float4 v = *(const float4*)(x + (size_t)i*4);
        u32 h0,l0,h1,l1;
        split2u(v.x,v.y,h0,l0); split2u(v.z,v.w,h1,l1);
        *(uint2*)(hi+(size_t)i*4) = make_uint2(h0,h1);
        *(uint2*)(lo+(size_t)i*4) = make_uint2(l0,l1);
    }
}
__global__ void __launch_bounds__(256) k_rmsnorm_split(const float* __restrict__ x,
    const float* __restrict__ w, bf16* __restrict__ hi, bf16* __restrict__ lo)
{
    int row=blockIdx.x; const float* xr=x+(size_t)row*HID_;
    int t=threadIdx.x;
    float4 xv[2];
    float ss=0.f;
#pragma unroll
    for(int it=0;it<2;it++){
        xv[it] = *(const float4*)&xr[(t+it*256)*4];
        ss += xv[it].x*xv[it].x + xv[it].y*xv[it].y + xv[it].z*xv[it].z + xv[it].w*xv[it].w;
    }
    __shared__ float red[256]; red[t]=ss; __syncthreads();
    for(int s=128;s>0;s>>=1){ if(t<s) red[t]+=red[t+s]; __syncthreads(); }
    float rs=rsqrtf(red[0]/(float)HID_+EPS_);
#pragma unroll
    for(int it=0;it<2;it++){
        int j4=(t+it*256)*4;
        float4 wv = *(const float4*)&w[j4];
        float o0=wv.x*xv[it].x*rs, o1=wv.y*xv[it].y*rs;
        float o2=wv.z*xv[it].z*rs, o3=wv.w*xv[it].w*rs;
        u32 h0,l0,h1,l1;
        split2u(o0,o1,h0,l0); split2u(o2,o3,h1,l1);
        *(uint2*)(hi+(size_t)row*HID_+j4) = make_uint2(h0,h1);
        *(uint2*)(lo+(size_t)row*HID_+j4) = make_uint2(l0,l1);
    }
}
__global__ void __launch_bounds__(256) k_rmsnorm(const float* __restrict__ x,
    const float* __restrict__ w, float* __restrict__ y)
{
    int row=blockIdx.x; const float* xr=x+(size_t)row*HID_;
    float* yr=y+(size_t)row*HID_;
    int t=threadIdx.x; float ss=0.f;
    for(int j=t;j<HID_;j+=256){ float v=xr[j]; ss+=v*v; }
    __shared__ float red[256]; red[t]=ss; __syncthreads();
    for(int s=128;s>0;s>>=1){ if(t<s) red[t]+=red[t+s]; __syncthreads(); }
    float rs=rsqrtf(red[0]/(float)HID_+EPS_);
    for(int j=t;j<HID_;j+=256) yr[j]=w[j]*xr[j]*rs;
}
__global__ void __launch_bounds__(256) k_silu_split4(const float* __restrict__ gu,
    bf16* __restrict__ hi, bf16* __restrict__ lo)
{
    int idx = blockIdx.x*256+threadIdx.x;      // over MT*INT/4
    int row = idx / (INT_/4), c4 = idx % (INT_/4);
    float4 gv = *(const float4*)(gu + (size_t)row*12288 + c4*4);
    float4 uv = *(const float4*)(gu + (size_t)row*12288 + 6144 + c4*4);
    float o0 = gv.x/(1.f+expf(-gv.x))*uv.x;
    float o1 = gv.y/(1.f+expf(-gv.y))*uv.y;
    float o2 = gv.z/(1.f+expf(-gv.z))*uv.z;
    float o3 = gv.w/(1.f+expf(-gv.w))*uv.w;
    u32 h0,l0,h1,l1;
    split2u(o0,o1,h0,l0); split2u(o2,o3,h1,l1);
    size_t o = (size_t)row*INT_ + c4*4;
    *(uint2*)(hi+o) = make_uint2(h0,h1);
    *(uint2*)(lo+o) = make_uint2(l0,l1);
}

// q rope: planar hi/lo [tok][2048]
__global__ void __launch_bounds__(128) k_qrope(const float* __restrict__ qkv,
    const float* __restrict__ w, bf16* __restrict__ qhi, bf16* __restrict__ qlo)
{
    int idx=blockIdx.x, head=idx%NH_, tok=idx/NH_, pos=tok%L_;
    int d=threadIdx.x;
    float v = qkv[(size_t)tok*4096 + head*128 + d];
    __shared__ float sh[128];
    sh[d]=v*v; __syncthreads();
    for(int s=64;s>0;s>>=1){ if(d<s) sh[d]+=sh[d+s]; __syncthreads(); }
    float rs=rsqrtf(sh[0]/(float)HD_+EPS_);
    __syncthreads();
    float xn=w[d]*v*rs;
    sh[d]=xn; __syncthreads();
    float rot=(d<64)? -sh[d+64] : sh[d-64];
    int half=d&63;
    float inv=expf(-(2.f*(float)half/(float)HD_)*13.815510557964274f);
    float ang=(float)pos*inv;
    float val = xn*cosf(ang)+rot*sinf(ang);
    bf16 h=__float2bfloat16(val);
    size_t o=(size_t)tok*2048 + head*128 + d;
    qhi[o]=h; qlo[o]=__float2bfloat16(val-__bfloat162float(h));
}

// k rope: planar hi/lo [b*8+kv][token][d]
__global__ void __launch_bounds__(128) k_krope(const float* __restrict__ qkv,
    const float* __restrict__ w, bf16* __restrict__ khi, bf16* __restrict__ klo)
{
    int idx=blockIdx.x, kv=idx%NKV_, tok=idx/NKV_, pos=tok%L_;
    int b=tok/L_, j=tok%L_;
    int d=threadIdx.x;
    float v = qkv[(size_t)tok*4096 + 2048 + kv*128 + d];
    __shared__ float sh[128];
    sh[d]=v*v; __syncthreads();
    for(int s=64;s>0;s>>=1){ if(d<s) sh[d]+=sh[d+s]; __syncthreads(); }
    float rs=rsqrtf(sh[0]/(float)HD_+EPS_);
    __syncthreads();
    float xn=w[d]*v*rs;
    sh[d]=xn; __syncthreads();
    float rot=(d<64)? -sh[d+64] : sh[d-64];
    int half=d&63;
    float inv=expf(-(2.f*(float)half/(float)HD_)*13.815510557964274f);
    float ang=(float)pos*inv;
    float val = xn*cosf(ang)+rot*sinf(ang);
    bf16 h=__float2bfloat16(val);
    size_t o = ((size_t)(b*NKV_+kv)*L_ + j)*HD_ + d;
    khi[o]=h; klo[o]=__float2bfloat16(val-__bfloat162float(h));
}

// v split (vectorized x4): qkv v-section -> planar hi/lo [b*8+kv][token][d]
__global__ void __launch_bounds__(256) k_vsplit4(const float* __restrict__ qkv,
    bf16* __restrict__ vhi, bf16* __restrict__ vlo)
{
    int idx = blockIdx.x*256+threadIdx.x;      // MT_ * 1024 / 4
    int tok = idx >> 8, r = idx & 255;
    int kv = r >> 5, d4 = (r & 31)*4;
    int b = tok / L_, j = tok % L_;
    float4 v = *(const float4*)(qkv + (size_t)tok*4096 + 3072 + kv*128 + d4);
    u32 h0,l0,h1,l1;
    split2u(v.x,v.y,h0,l0); split2u(v.z,v.w,h1,l1);
    size_t o = ((size_t)(b*NKV_+kv)*L_ + j)*HD_ + d4;
    *(uint2*)(vhi+o) = make_uint2(h0,h1);
    *(uint2*)(vlo+o) = make_uint2(l0,l1);
}

// softmax: fp32 scores -> bf16 hi/lo probs. Sliding layers touch only the
// 384-col window [m0-128, m0+256) — exactly the range k_attnv reads.
__global__ void __launch_bounds__(256) k_softmax(const float* __restrict__ sc,
    bf16* __restrict__ shi, bf16* __restrict__ slo, const int* __restrict__ am, int sliding)
{
    int row=blockIdx.x, i=row%L_, b=row/(NH_*L_);
    const float* r=sc+(size_t)row*L_;
    const int* amr=am+(size_t)b*L_;
    int t=threadIdx.x;
    int jb=0, je=L_;
    if (sliding){
        int m0 = i & ~127;
        jb = (m0>=128)? m0-128 : 0;
        je = (m0+256<=L_)? m0+256 : L_;
    }
    float vals[2][2]; bool keep[2][2]; bool act[2];
    float mx=-INFINITY;
#pragma unroll
    for(int it=0;it<2;it++){
        int j0 = jb + t*2 + it*512;
        act[it] = (j0 < je);
        if (act[it]){
            float2 v2 = *(const float2*)&r[j0];
            vals[it][0]=v2.x; vals[it][1]=v2.y;
#pragma unroll
            for(int q=0;q<2;q++){
                int j=j0+q, dj=i-j; if(dj<0)dj=-dj;
                keep[it][q]=(amr[j]!=0)&&(!sliding||dj<=SW_);
                if(!keep[it][q]) vals[it][q]=-INFINITY;
                mx=fmaxf(mx,vals[it][q]);
            }
        }
    }
    __shared__ float red[256];
    red[t]=mx; __syncthreads();
    for(int s=128;s>0;s>>=1){ if(t<s) red[t]=fmaxf(red[t],red[t+s]); __syncthreads(); }
    float rm=red[0]; __syncthreads();
    float e[2][2]; float ssum=0.f;
#pragma unroll
    for(int it=0;it<2;it++)
#pragma unroll
        for(int q=0;q<2;q++){
            e[it][q] = (act[it] && keep[it][q]) ? expf(vals[it][q]-rm) : 0.f;
            ssum += e[it][q];
        }
    red[t]=ssum; __syncthreads();
    for(int s=128;s>0;s>>=1){ if(t<s) red[t]+=red[t+s]; __syncthreads(); }
    float tot=red[0];
    float inv=(tot>0.f)?(1.f/tot):0.f;
#pragma unroll
    for(int it=0;it<2;it++){
        int j0 = jb + t*2 + it*512;
        if (act[it]){
            u32 hw,lw;
            split2u(e[it][0]*inv, e[it][1]*inv, hw, lw);
            *(u32*)(shi + (size_t)row*L_ + j0) = hw;
            *(u32*)(slo + (size_t)row*L_ + j0) = lw;
        }
    }
}

// ================ host driver ================
extern "C" void kernel_launch(void* const* d_in, const int* in_sizes, int n_in,
                              void* d_out, int out_size)
{
    const float* x       = (const float*)d_in[0];
    const int*   am      = (const int*)  d_in[1];
    const float* W_embed = (const float*)d_in[2];
    const float* b_embed = (const float*)d_in[3];
    const float* Wq      = (const float*)d_in[4];
    const float* Wk      = (const float*)d_in[5];
    const float* Wv      = (const float*)d_in[6];
    const float* Wo      = (const float*)d_in[7];
    const float* w_in_ln = (const float*)d_in[8];
    const float* w_post  = (const float*)d_in[9];
    const float* w_qn    = (const float*)d_in[10];
    const float* w_kn    = (const float*)d_in[11];
    const float* Wg      = (const float*)d_in[12];
    const float* Wu      = (const float*)d_in[13];
    const float* Wd      = (const float*)d_in[14];
    const float* w_final = (const float*)d_in[15];
    float* out = (float*)d_out;

    float *h_, *qkv_, *gu_, *sc_;
    bf16 *whi,*wlo,*xhi,*xlo,*hnhi,*hnlo,*qhi,*qlo,*khi,*klo,*vhi,*vlo;
    bf16 *schi,*sclo,*ohi,*olo,*achi,*aclo;
    cudaGetSymbolAddress((void**)&h_, g_h);      cudaGetSymbolAddress((void**)&qkv_, g_qkv);
    cudaGetSymbolAddress((void**)&gu_, g_gu);    cudaGetSymbolAddress((void**)&sc_, g_sc);
    cudaGetSymbolAddress((void**)&whi, g_whi);   cudaGetSymbolAddress((void**)&wlo, g_wlo);
    cudaGetSymbolAddress((void**)&xhi, g_xhi);   cudaGetSymbolAddress((void**)&xlo, g_xlo);
    cudaGetSymbolAddress((void**)&hnhi, g_hnhi); cudaGetSymbolAddress((void**)&hnlo, g_hnlo);
    cudaGetSymbolAddress((void**)&qhi, g_qhi);   cudaGetSymbolAddress((void**)&qlo, g_qlo);
    cudaGetSymbolAddress((void**)&khi, g_khi);   cudaGetSymbolAddress((void**)&klo, g_klo);
    cudaGetSymbolAddress((void**)&vhi, g_vhi);   cudaGetSymbolAddress((void**)&vlo, g_vlo);
    cudaGetSymbolAddress((void**)&schi, g_schi); cudaGetSymbolAddress((void**)&sclo, g_sclo);
    cudaGetSymbolAddress((void**)&ohi, g_ohi);   cudaGetSymbolAddress((void**)&olo, g_olo);
    cudaGetSymbolAddress((void**)&achi, g_achi); cudaGetSymbolAddress((void**)&aclo, g_aclo);

    cudaFuncSetAttribute(k_dense<0>, cudaFuncAttributeMaxDynamicSharedMemorySize, SM_DENSE);
    cudaFuncSetAttribute(k_dense<1>, cudaFuncAttributeMaxDynamicSharedMemorySize, SM_DENSE);
    cudaFuncSetAttribute(k_dense<2>, cudaFuncAttributeMaxDynamicSharedMemorySize, SM_DENSE);
    cudaFuncSetAttribute(k_scores,   cudaFuncAttributeMaxDynamicSharedMemorySize, SM_SCORES);
    cudaFuncSetAttribute(k_attnv,    cudaFuncAttributeMaxDynamicSharedMemorySize, SM_ATTNV);

    const float scale = 0.08838834764831845f;

    // ---- packs needed for the embed GEMM first, so launch #6 is k_dense (ncu -s 5) ----
    size_t lb0 = WZ_EMB;
    size_t oqkv0=lb0, oo0=oqkv0+WZ_QKV, ogu0=oo0+WZ_O, od0=ogu0+WZ_GU;
    k_wpack8<<<1024, 256>>>(W_embed, 2048, whi, wlo, 2048, 0, 1024*2048/8);        // 1
    k_wpack8<<<2048, 256>>>(Wq, 2048, whi+oqkv0, wlo+oqkv0, 4096, 0, 2048*2048/8); // 2
    k_wpack8<<<1024, 256>>>(Wk, 1024, whi+oqkv0, wlo+oqkv0, 4096, 2048, 2048*1024/8); // 3
    k_wpack8<<<1024, 256>>>(Wv, 1024, whi+oqkv0, wlo+oqkv0, 4096, 3072, 2048*1024/8); // 4
    k_split4<<<(MT_*TXT_/4)/256, 256>>>(x, xhi, xlo, MT_*TXT_/4);                  // 5
    k_dense<2><<<dim3(8,16), 256, SM_DENSE>>>(xhi, xlo, 1024, whi, wlo, 2048, h_, 2048, 1024, b_embed); // 6 (profiled)

    // ---- remaining weight packs ----
    k_wpack8<<<2048, 256>>>(Wo, 2048, whi+oo0, wlo+oo0, 2048, 0, 2048*2048/8);
    k_wpack8<<<6144, 256>>>(Wg, 6144, whi+ogu0, wlo+ogu0, 12288, 0, 2048*6144/8);
    k_wpack8<<<6144, 256>>>(Wu, 6144, whi+ogu0, wlo+ogu0, 12288, 6144, 2048*6144/8);
    k_wpack8<<<6144, 256>>>(Wd, 2048, whi+od0, wlo+od0, 2048, 0, 6144*2048/8);
    for (int i=1;i<NL_;i++){
        size_t lbi = WZ_EMB + (size_t)i*WZ_LAYER;
        size_t oqkv=lbi, oo=oqkv+WZ_QKV, ogu=oo+WZ_O, od=ogu+WZ_GU;
        k_wpack8<<<2048, 256>>>(Wq+(size_t)i*2048*2048, 2048, whi+oqkv, wlo+oqkv, 4096, 0, 2048*2048/8);
        k_wpack8<<<1024, 256>>>(Wk+(size_t)i*2048*1024, 1024, whi+oqkv, wlo+oqkv, 4096, 2048, 2048*1024/8);
        k_wpack8<<<1024, 256>>>(Wv+(size_t)i*2048*1024, 1024, whi+oqkv, wlo+oqkv, 4096, 3072, 2048*1024/8);
        k_wpack8<<<2048, 256>>>(Wo+(size_t)i*2048*2048, 2048, whi+oo, wlo+oo, 2048, 0, 2048*2048/8);
        k_wpack8<<<6144, 256>>>(Wg+(size_t)i*2048*6144, 6144, whi+ogu, wlo+ogu, 12288, 0, 2048*6144/8);
        k_wpack8<<<6144, 256>>>(Wu+(size_t)i*2048*6144, 6144, whi+ogu, wlo+ogu, 12288, 6144, 2048*6144/8);
        k_wpack8<<<6144, 256>>>(Wd+(size_t)i*6144*2048, 2048, whi+od, wlo+od, 2048, 0, 6144*2048/8);
    }

    for (int i=0;i<NL_;i++){
        size_t lbi = WZ_EMB + (size_t)i*WZ_LAYER;
        size_t oqkv=lbi, oo=oqkv+WZ_QKV, ogu=oo+WZ_O, od=ogu+WZ_GU;
        int sl = (i%2==0) ? 1 : 0;

        k_rmsnorm_split<<<MT_, 256>>>(h_, w_in_ln+(size_t)i*HID_, hnhi, hnlo);
        k_dense<0><<<dim3(16,16), 256, SM_DENSE>>>(hnhi, hnlo, 2048, whi+oqkv, wlo+oqkv, 4096, qkv_, 4096, 2048, nullptr);

        k_qrope<<<MT_*NH_, 128>>>(qkv_, w_qn+(size_t)i*HD_, qhi, qlo);
        k_krope<<<MT_*NKV_, 128>>>(qkv_, w_kn+(size_t)i*HD_, khi, klo);
        k_vsplit4<<<(MT_*1024/4)/256, 256>>>(qkv_, vhi, vlo);

        k_scores<<<dim3(8,8,32), 256, SM_SCORES>>>(qhi, qlo, khi, klo, sc_, scale, sl);
        k_softmax<<<B_*NH_*L_, 256>>>(sc_, schi, sclo, am, sl);
        k_attnv<<<dim3(1,8,32), 256, SM_ATTNV>>>(schi, sclo, vhi, vlo, ohi, olo, sl);

        k_dense<1><<<dim3(8,16), 256, SM_DENSE>>>(ohi, olo, 2048, whi+oo, wlo+oo, 2048, h_, 2048, 2048, nullptr);

        k_rmsnorm_split<<<MT_, 256>>>(h_, w_post+(size_t)i*HID_, hnhi, hnlo);
        k_dense<0><<<dim3(48,16), 256, SM_DENSE>>>(hnhi, hnlo, 2048, whi+ogu, wlo+ogu, 12288, gu_, 12288, 2048, nullptr);
        k_silu_split4<<<(MT_*INT_/4)/256, 256>>>(gu_, achi, aclo);
        k_dense<1><<<dim3(8,16), 256, SM_DENSE>>>(achi, aclo, 6144, whi+od, wlo+od, 2048, h_, 2048, 6144, nullptr);
    }

    k_rmsnorm<<<MT_, 256>>>(h_, w_final, out);
}